// round 1
// baseline (speedup 1.0000x reference)
#include <cuda_runtime.h>
#include <cuda_bf16.h>
#include <cstdint>

// Problem dims
#define HH   512
#define EE   256
#define VV   50000
#define BB   128
#define SS   200
#define H3   1536          // 3H
#define KGRU 1280          // 2H + E
#define KOUT 1792          // 3H + E

// ---------------- scratch (no allocations allowed) ----------------
__device__ float g_u[H3];            // attn_w^T v
__device__ float g_c0;               // attn_b . v
__device__ float g_togru[BB * KGRU]; // relu(concat(emb_x, context))
__device__ float g_toout[BB * KOUT]; // [h_new | context | emb_x]
__device__ float g_gi[BB * H3];
__device__ float g_gh[BB * H3];

// ---------------- f32x2 packed math helpers ----------------
__device__ __forceinline__ unsigned long long pk2(float x, float y) {
    unsigned long long r;
    asm("mov.b64 %0, {%1,%2};" : "=l"(r) : "f"(x), "f"(y));
    return r;
}
__device__ __forceinline__ float2 upk2(unsigned long long v) {
    float2 r;
    asm("mov.b64 {%0,%1}, %2;" : "=f"(r.x), "=f"(r.y) : "l"(v));
    return r;
}
__device__ __forceinline__ unsigned long long fma2(unsigned long long a,
                                                   unsigned long long b,
                                                   unsigned long long c) {
    unsigned long long d;
    asm("fma.rn.f32x2 %0, %1, %2, %3;" : "=l"(d) : "l"(a), "l"(b), "l"(c));
    return d;
}

// ---------------- kernel 1: u = attn_w^T v, c0 = attn_b.v ----------------
__global__ void prep_kernel(const float* __restrict__ attn_w,
                            const float* __restrict__ attn_b,
                            const float* __restrict__ v) {
    int j = blockIdx.x * blockDim.x + threadIdx.x;
    if (j < H3) {
        float s = 0.f;
        #pragma unroll 8
        for (int h = 0; h < HH; ++h) s += attn_w[h * H3 + j] * v[h];
        g_u[j] = s;
    } else if (j == H3) {
        float s = 0.f;
        for (int h = 0; h < HH; ++h) s += attn_b[h] * v[h];
        g_c0 = s;
    }
}

// ---------------- kernel 2: scores + softmax + context (one CTA per b) ----------------
__global__ __launch_bounds__(256)
void attn_kernel(const float* __restrict__ hidden,
                 const float* __restrict__ enc,
                 const float* __restrict__ emb,
                 const int* __restrict__ x) {
    __shared__ float s_u[2 * HH];     // u for enc part (1024)
    __shared__ float s_p[256];        // scores -> probs
    __shared__ float s_red[8];
    __shared__ float s_constb, s_max, s_sum;

    const int b = blockIdx.x;
    const int tid = threadIdx.x;
    const int lane = tid & 31, wid = tid >> 5;

    for (int j = tid; j < 2 * HH; j += 256) s_u[j] = g_u[HH + j];

    // const_b = h0[b] . u[0:512] + c0
    float p = 0.f;
    for (int j = tid; j < HH; j += 256) p += hidden[b * HH + j] * g_u[j];
    for (int o = 16; o; o >>= 1) p += __shfl_xor_sync(~0u, p, o);
    if (lane == 0) s_red[wid] = p;
    __syncthreads();
    if (tid == 0) {
        float s = g_c0;
        for (int w = 0; w < 8; ++w) s += s_red[w];
        s_constb = s;
    }
    __syncthreads();
    const float cb = s_constb;

    // scores: warp per row
    const float4* enc4 = reinterpret_cast<const float4*>(enc) + (size_t)b * SS * 256;
    const float4* u4 = reinterpret_cast<const float4*>(s_u);
    for (int s = wid; s < SS; s += 8) {
        const float4* row = enc4 + (size_t)s * 256;
        float acc = 0.f;
        #pragma unroll
        for (int t = 0; t < 8; ++t) {
            float4 e = row[lane + 32 * t];
            float4 u = u4[lane + 32 * t];
            acc += e.x * u.x + e.y * u.y + e.z * u.z + e.w * u.w;
        }
        for (int o = 16; o; o >>= 1) acc += __shfl_xor_sync(~0u, acc, o);
        if (lane == 0) s_p[s] = acc + cb;
    }
    __syncthreads();

    // softmax over 200
    float m = -1e30f;
    for (int s = tid; s < SS; s += 256) m = fmaxf(m, s_p[s]);
    for (int o = 16; o; o >>= 1) m = fmaxf(m, __shfl_xor_sync(~0u, m, o));
    if (lane == 0) s_red[wid] = m;
    __syncthreads();
    if (tid == 0) {
        float mm = -1e30f;
        for (int w = 0; w < 8; ++w) mm = fmaxf(mm, s_red[w]);
        s_max = mm;
    }
    __syncthreads();
    const float mm2 = s_max;
    float sum = 0.f;
    for (int s = tid; s < SS; s += 256) {
        float e = expf(s_p[s] - mm2);
        s_p[s] = e;
        sum += e;
    }
    for (int o = 16; o; o >>= 1) sum += __shfl_xor_sync(~0u, sum, o);
    if (lane == 0) s_red[wid] = sum;
    __syncthreads();
    if (tid == 0) {
        float t = 0.f;
        for (int w = 0; w < 8; ++w) t += s_red[w];
        s_sum = 1.f / t;
    }
    __syncthreads();
    const float inv = s_sum;

    // context: thread owns float4 lane d4 = tid (1024 dims)
    float4 acc = make_float4(0.f, 0.f, 0.f, 0.f);
    const float4* col = enc4 + tid;
    #pragma unroll 4
    for (int s = 0; s < SS; ++s) {
        float ps = s_p[s];
        float4 e = col[(size_t)s * 256];
        acc.x += ps * e.x; acc.y += ps * e.y; acc.z += ps * e.z; acc.w += ps * e.w;
    }
    acc.x *= inv; acc.y *= inv; acc.z *= inv; acc.w *= inv;

    const int d = tid * 4;
    *reinterpret_cast<float4*>(g_toout + (size_t)b * KOUT + HH + d) = acc;   // raw context
    float4 rc = make_float4(fmaxf(acc.x, 0.f), fmaxf(acc.y, 0.f),
                            fmaxf(acc.z, 0.f), fmaxf(acc.w, 0.f));
    *reinterpret_cast<float4*>(g_togru + (size_t)b * KGRU + EE + d) = rc;    // relu(context)

    // emb_x
    if (tid < EE) {
        float e = emb[(size_t)x[b] * EE + tid];
        g_toout[(size_t)b * KOUT + H3 + tid] = e;        // raw emb
        g_togru[(size_t)b * KGRU + tid] = fmaxf(e, 0.f); // relu(emb)
    }
}

// ---------------- tiled fp32 GEMM, N fixed to 128 ----------------
// C[n*ldc + m] = sum_k A[m*K+k] * Bact[n*K+k] + bias[m]
template <int BM, int TM>
__global__ __launch_bounds__(256)
void sgemm_n128(const float* __restrict__ A, const float* __restrict__ Bact,
                const float* __restrict__ bias, float* __restrict__ C,
                int M, int K, int ldc) {
    constexpr int BK = 32, BN = 128, TN = 4;
    constexpr int MT = BM / TM;
    static_assert(MT == 8 && (BN / TN) == 32, "256-thread layout");
    __shared__ float As[BK][BM + 4];
    __shared__ float Bs[BK][BN + 4];

    const int tid = threadIdx.x;
    const int lane = tid & 31;  // n-thread (0..31)
    const int tm = tid >> 5;    // m-thread (0..7)
    const int m0 = blockIdx.x * BM;

    unsigned long long acc[TM / 2][TN];
    #pragma unroll
    for (int i = 0; i < TM / 2; ++i)
        #pragma unroll
        for (int j = 0; j < TN; ++j) acc[i][j] = 0ull;

    for (int k0 = 0; k0 < K; k0 += BK) {
        #pragma unroll
        for (int r = tm; r < BM; r += 8) {
            int m = m0 + r;
            As[lane][r] = (m < M) ? A[(size_t)m * K + k0 + lane] : 0.f;
        }
        #pragma unroll
        for (int r = tm; r < BN; r += 8) {
            Bs[lane][r] = Bact[(size_t)r * K + k0 + lane];
        }
        __syncthreads();
        #pragma unroll
        for (int kk = 0; kk < BK; ++kk) {
            float4 bv = *reinterpret_cast<const float4*>(&Bs[kk][lane * 4]);
            unsigned long long bb0 = pk2(bv.x, bv.x);
            unsigned long long bb1 = pk2(bv.y, bv.y);
            unsigned long long bb2 = pk2(bv.z, bv.z);
            unsigned long long bb3 = pk2(bv.w, bv.w);
            const float2* ap = reinterpret_cast<const float2*>(&As[kk][tm * TM]);
            #pragma unroll
            for (int i = 0; i < TM / 2; ++i) {
                float2 a2 = ap[i];
                unsigned long long aa = pk2(a2.x, a2.y);
                acc[i][0] = fma2(aa, bb0, acc[i][0]);
                acc[i][1] = fma2(aa, bb1, acc[i][1]);
                acc[i][2] = fma2(aa, bb2, acc[i][2]);
                acc[i][3] = fma2(aa, bb3, acc[i][3]);
            }
        }
        __syncthreads();
    }

    #pragma unroll
    for (int i = 0; i < TM / 2; ++i) {
        int m = m0 + tm * TM + 2 * i;
        #pragma unroll
        for (int j = 0; j < TN; ++j) {
            int n = lane * 4 + j;
            float2 vv = upk2(acc[i][j]);
            if (m < M)     C[(size_t)n * ldc + m]     = vv.x + bias[m];
            if (m + 1 < M) C[(size_t)n * ldc + m + 1] = vv.y + bias[m + 1];
        }
    }
}

// ---------------- GRU gates ----------------
__global__ void gru_gates(const float* __restrict__ hidden, float* __restrict__ out_h) {
    int idx = blockIdx.x * 256 + threadIdx.x;   // 128*512
    int b = idx >> 9, h = idx & 511;
    const float* gi = g_gi + (size_t)b * H3;
    const float* gh = g_gh + (size_t)b * H3;
    float r = 1.f / (1.f + expf(-(gi[h] + gh[h])));
    float z = 1.f / (1.f + expf(-(gi[HH + h] + gh[HH + h])));
    float n = tanhf(gi[2 * HH + h] + r * gh[2 * HH + h]);
    float hp = hidden[b * HH + h];
    float hn = (1.f - z) * n + z * hp;
    g_toout[(size_t)b * KOUT + h] = hn;
    out_h[b * HH + h] = hn;
}

// ---------------- launch ----------------
extern "C" void kernel_launch(void* const* d_in, const int* in_sizes, int n_in,
                              void* d_out, int out_size) {
    const int*   x      = (const int*)d_in[0];
    const float* hidden = (const float*)d_in[1];
    const float* enc    = (const float*)d_in[2];
    const float* emb    = (const float*)d_in[3];
    const float* attn_w = (const float*)d_in[4];
    const float* attn_b = (const float*)d_in[5];
    const float* v      = (const float*)d_in[6];
    const float* w_ih   = (const float*)d_in[7];
    const float* w_hh   = (const float*)d_in[8];
    // b_ih, b_hh handled via GEMM bias args
    const float* b_ih   = (const float*)d_in[9];
    const float* b_hh   = (const float*)d_in[10];
    const float* out_w  = (const float*)d_in[11];
    const float* out_b  = (const float*)d_in[12];
    float* out = (float*)d_out;

    static float *p_togru = nullptr, *p_toout = nullptr, *p_gi = nullptr, *p_gh = nullptr;
    if (!p_togru) {
        cudaGetSymbolAddress((void**)&p_togru, g_togru);
        cudaGetSymbolAddress((void**)&p_toout, g_toout);
        cudaGetSymbolAddress((void**)&p_gi, g_gi);
        cudaGetSymbolAddress((void**)&p_gh, g_gh);
    }

    prep_kernel<<<7, 256>>>(attn_w, attn_b, v);
    attn_kernel<<<BB, 256>>>(hidden, enc, emb, x);
    sgemm_n128<16, 2><<<H3 / 16, 256>>>(w_ih, p_togru, b_ih, p_gi, H3, KGRU, H3);
    sgemm_n128<16, 2><<<H3 / 16, 256>>>(w_hh, hidden, b_hh, p_gh, H3, HH, H3);
    gru_gates<<<(BB * HH) / 256, 256>>>(hidden, out + (size_t)BB * VV);
    sgemm_n128<64, 8><<<(VV + 63) / 64, 256>>>(out_w, p_toout, out_b, out, VV, KOUT, VV);
}

// round 5
// speedup vs baseline: 1.3237x; 1.3237x over previous
#include <cuda_runtime.h>
#include <cuda_bf16.h>
#include <cstdint>

// Problem dims
#define HH   512
#define EE   256
#define VV   50000
#define BB   128
#define SS   200
#define H3   1536          // 3H
#define KGRU 1280          // 2H + E
#define KOUT 1792          // 3H + E

// ---------------- scratch ----------------
__device__ float g_u[H3];
__device__ float g_c0;
__device__ float g_togru[BB * KGRU];
__device__ float g_toout[BB * KOUT];
__device__ float g_gi[BB * H3];
__device__ float g_gh[BB * H3];

// ---------------- helpers ----------------
__device__ __forceinline__ uint32_t smem_u32(const void* p) {
    uint32_t a;
    asm("{ .reg .u64 t; cvta.to.shared.u64 t, %1; cvt.u32.u64 %0, t; }" : "=r"(a) : "l"(p));
    return a;
}
__device__ __forceinline__ uint32_t pkbf(__nv_bfloat16 a, __nv_bfloat16 b) {
    return (uint32_t)__bfloat16_as_ushort(a) | ((uint32_t)__bfloat16_as_ushort(b) << 16);
}
__device__ __forceinline__ void split2(float x, float y, uint32_t& hv, uint32_t& lv) {
    __nv_bfloat16 xh = __float2bfloat16(x);
    __nv_bfloat16 yh = __float2bfloat16(y);
    __nv_bfloat16 xl = __float2bfloat16(x - __bfloat162float(xh));
    __nv_bfloat16 yl = __float2bfloat16(y - __bfloat162float(yh));
    hv = pkbf(xh, yh);
    lv = pkbf(xl, yl);
}
__device__ __forceinline__ void split8(float4 f0, float4 f1, uint4& hv, uint4& lv) {
    split2(f0.x, f0.y, hv.x, lv.x);
    split2(f0.z, f0.w, hv.y, lv.y);
    split2(f1.x, f1.y, hv.z, lv.z);
    split2(f1.z, f1.w, hv.w, lv.w);
}
__device__ __forceinline__ void sts128(uint32_t addr, uint4 v) {
    asm volatile("st.shared.v4.b32 [%0], {%1,%2,%3,%4};"
                 :: "r"(addr), "r"(v.x), "r"(v.y), "r"(v.z), "r"(v.w) : "memory");
}
__device__ __forceinline__ void ldsm4(uint32_t (&r)[4], uint32_t addr) {
    asm volatile("ldmatrix.sync.aligned.m8n8.x4.shared.b16 {%0,%1,%2,%3}, [%4];"
                 : "=r"(r[0]), "=r"(r[1]), "=r"(r[2]), "=r"(r[3]) : "r"(addr));
}
__device__ __forceinline__ void mma16816(float (&d)[4], const uint32_t (&a)[4],
                                         uint32_t b0, uint32_t b1) {
    asm volatile(
        "mma.sync.aligned.m16n8k16.row.col.f32.bf16.bf16.f32 "
        "{%0,%1,%2,%3}, {%4,%5,%6,%7}, {%8,%9}, {%0,%1,%2,%3};"
        : "+f"(d[0]), "+f"(d[1]), "+f"(d[2]), "+f"(d[3])
        : "r"(a[0]), "r"(a[1]), "r"(a[2]), "r"(a[3]), "r"(b0), "r"(b1));
}

// ================= split-bf16 HMMA GEMM =================
// C[n*ldc + m] = sum_k A[m*K+k] * Bact[n*K+k] + bias[m],  N = 128 fixed.
// CTA tile M=128, 256 threads = 8 warps (4 M x 2 N), warp tile 32x64.
// K chunks of 64; 2-stage smem double buffer.
// smem stage (64KB): Ahi|Alo|Bhi|Blo, each 128 rows x 128B (64 bf16, swizzled).
#define STAGE_BYTES 65536
#define GEMM_SMEM   (2 * STAGE_BYTES)

__global__ __launch_bounds__(256, 1)
void mma_gemm(const float* __restrict__ A, const float* __restrict__ Bact,
              const float* __restrict__ bias, float* __restrict__ C,
              int M, int K, int nchunk, int ldc) {
    extern __shared__ char smem[];
    const uint32_t sb = smem_u32(smem);
    const int tid = threadIdx.x, wid = tid >> 5, lane = tid & 31;
    const int warpM = wid & 3, warpN = wid >> 2;

    const int m0 = blockIdx.x * 128;

    // ---- fill-side addressing ----
    const int r = tid >> 1, hf = tid & 1;       // row 0..127, k-half 0/1
    const bool avalid = (m0 + r) < M;
    const float4* arow = reinterpret_cast<const float4*>(A + (size_t)(m0 + r) * K) + hf * 8;
    const float4* brow = reinterpret_cast<const float4*>(Bact + (size_t)r * K) + hf * 8;
    uint32_t soff[4];
    #pragma unroll
    for (int j = 0; j < 4; ++j)
        soff[j] = (uint32_t)(r * 128) + (((uint32_t)(hf * 64 + j * 16)) ^ (((uint32_t)r & 7u) << 4));

    // ---- mma-side addressing ----
    const int l15 = lane & 15, lhi = lane >> 4;
    const uint32_t rowA = (uint32_t)(warpM * 32 + l15);
    const uint32_t rowB = (uint32_t)(warpN * 64 + l15);
    const uint32_t rowAoff = rowA * 128, xorA = (rowA & 7u) << 4;
    const uint32_t rowBoff = rowB * 128, xorB = (rowB & 7u) << 4;

    float acc[2][8][4];
    #pragma unroll
    for (int mt = 0; mt < 2; ++mt)
        #pragma unroll
        for (int na = 0; na < 8; ++na)
            #pragma unroll
            for (int q = 0; q < 4; ++q) acc[mt][na][q] = 0.f;

    float4 fa[8], fb[8];

    // ---- prologue: load + stage chunk 0 ----
    #pragma unroll
    for (int j = 0; j < 8; ++j) {
        fa[j] = avalid ? arow[j] : make_float4(0.f, 0.f, 0.f, 0.f);
        fb[j] = brow[j];
    }
    {
        const uint32_t base = sb;
        #pragma unroll
        for (int j = 0; j < 4; ++j) {
            uint4 hv, lv;
            split8(fa[2 * j], fa[2 * j + 1], hv, lv);
            sts128(base + soff[j], hv);
            sts128(base + 16384 + soff[j], lv);
            split8(fb[2 * j], fb[2 * j + 1], hv, lv);
            sts128(base + 32768 + soff[j], hv);
            sts128(base + 49152 + soff[j], lv);
        }
    }
    __syncthreads();

    for (int c = 0; c < nchunk; ++c) {
        const uint32_t stage = sb + (uint32_t)(c & 1) * STAGE_BYTES;
        const bool more = (c + 1) < nchunk;
        // prefetch next chunk into registers (overlaps with MMA below)
        if (more) {
            #pragma unroll
            for (int j = 0; j < 8; ++j) {
                fa[j] = avalid ? arow[(c + 1) * 16 + j] : make_float4(0.f, 0.f, 0.f, 0.f);
                fb[j] = brow[(c + 1) * 16 + j];
            }
        }
        // 3 products: (Ahi,Bhi), (Ahi,Blo), (Alo,Bhi)
        #pragma unroll
        for (int p = 0; p < 3; ++p) {
            const uint32_t aslab = stage + ((p == 2) ? 16384u : 0u);
            const uint32_t bslab = stage + 32768u + ((p == 1) ? 16384u : 0u);
            #pragma unroll
            for (int k16 = 0; k16 < 4; ++k16) {
                const uint32_t kb = (uint32_t)(k16 * 32 + lhi * 16);
                const uint32_t kA = kb ^ xorA, kB = kb ^ xorB;
                uint32_t afr[2][4], bfr[4][4];
                ldsm4(afr[0], aslab + rowAoff + kA);
                ldsm4(afr[1], aslab + rowAoff + 2048 + kA);
                #pragma unroll
                for (int nt = 0; nt < 4; ++nt)
                    ldsm4(bfr[nt], bslab + rowBoff + (uint32_t)nt * 2048 + kB);
                #pragma unroll
                for (int mt = 0; mt < 2; ++mt)
                    #pragma unroll
                    for (int na = 0; na < 8; ++na) {
                        const uint32_t* bq = bfr[na >> 1];
                        if (na & 1) mma16816(acc[mt][na], afr[mt], bq[1], bq[3]);
                        else        mma16816(acc[mt][na], afr[mt], bq[0], bq[2]);
                    }
            }
        }
        if (more) {
            const uint32_t nbase = sb + (uint32_t)((c + 1) & 1) * STAGE_BYTES;
            #pragma unroll
            for (int j = 0; j < 4; ++j) {
                uint4 hv, lv;
                split8(fa[2 * j], fa[2 * j + 1], hv, lv);
                sts128(nbase + soff[j], hv);
                sts128(nbase + 16384 + soff[j], lv);
                split8(fb[2 * j], fb[2 * j + 1], hv, lv);
                sts128(nbase + 32768 + soff[j], hv);
                sts128(nbase + 49152 + soff[j], lv);
            }
            __syncthreads();
        }
    }

    // ---- epilogue: d0:(m,n) d1:(m,n+1) d2:(m+8,n) d3:(m+8,n+1), C[n*ldc+m] ----
    const int mrow = lane >> 2, ncol = (lane & 3) * 2;
    #pragma unroll
    for (int mt = 0; mt < 2; ++mt) {
        const int mb = m0 + warpM * 32 + mt * 16 + mrow;
        const bool v0 = mb < M, v1 = (mb + 8) < M;
        const float bv0 = v0 ? bias[mb] : 0.f;
        const float bv1 = v1 ? bias[mb + 8] : 0.f;
        #pragma unroll
        for (int na = 0; na < 8; ++na) {
            const int n = warpN * 64 + na * 8 + ncol;
            float* c0 = C + (size_t)n * ldc;
            float* c1 = C + (size_t)(n + 1) * ldc;
            if (v0) { c0[mb] = acc[mt][na][0] + bv0; c1[mb] = acc[mt][na][1] + bv0; }
            if (v1) { c0[mb + 8] = acc[mt][na][2] + bv1; c1[mb + 8] = acc[mt][na][3] + bv1; }
        }
    }
}

// ---------------- kernel 1: u = attn_w^T v, c0 = attn_b.v ----------------
__global__ void prep_kernel(const float* __restrict__ attn_w,
                            const float* __restrict__ attn_b,
                            const float* __restrict__ v) {
    int j = blockIdx.x * blockDim.x + threadIdx.x;
    if (j < H3) {
        float s = 0.f;
        #pragma unroll 8
        for (int h = 0; h < HH; ++h) s += attn_w[h * H3 + j] * v[h];
        g_u[j] = s;
    } else if (j == H3) {
        float s = 0.f;
        for (int h = 0; h < HH; ++h) s += attn_b[h] * v[h];
        g_c0 = s;
    }
}

// ---------------- kernel 2: scores + softmax + context ----------------
__global__ __launch_bounds__(256)
void attn_kernel(const float* __restrict__ hidden,
                 const float* __restrict__ enc,
                 const float* __restrict__ emb,
                 const int* __restrict__ x) {
    __shared__ float s_u[2 * HH];
    __shared__ float s_p[256];
    __shared__ float s_red[8];
    __shared__ float s_constb, s_max, s_sum;

    const int b = blockIdx.x;
    const int tid = threadIdx.x;
    const int lane = tid & 31, wid = tid >> 5;

    for (int j = tid; j < 2 * HH; j += 256) s_u[j] = g_u[HH + j];

    float p = 0.f;
    for (int j = tid; j < HH; j += 256) p += hidden[b * HH + j] * g_u[j];
    for (int o = 16; o; o >>= 1) p += __shfl_xor_sync(~0u, p, o);
    if (lane == 0) s_red[wid] = p;
    __syncthreads();
    if (tid == 0) {
        float s = g_c0;
        for (int w = 0; w < 8; ++w) s += s_red[w];
        s_constb = s;
    }
    __syncthreads();
    const float cb = s_constb;

    const float4* enc4 = reinterpret_cast<const float4*>(enc) + (size_t)b * SS * 256;
    const float4* u4 = reinterpret_cast<const float4*>(s_u);
    for (int s = wid; s < SS; s += 8) {
        const float4* row = enc4 + (size_t)s * 256;
        float acc = 0.f;
        #pragma unroll
        for (int t = 0; t < 8; ++t) {
            float4 e = row[lane + 32 * t];
            float4 u = u4[lane + 32 * t];
            acc += e.x * u.x + e.y * u.y + e.z * u.z + e.w * u.w;
        }
        for (int o = 16; o; o >>= 1) acc += __shfl_xor_sync(~0u, acc, o);
        if (lane == 0) s_p[s] = acc + cb;
    }
    __syncthreads();

    float m = -1e30f;
    for (int s = tid; s < SS; s += 256) m = fmaxf(m, s_p[s]);
    for (int o = 16; o; o >>= 1) m = fmaxf(m, __shfl_xor_sync(~0u, m, o));
    if (lane == 0) s_red[wid] = m;
    __syncthreads();
    if (tid == 0) {
        float mm = -1e30f;
        for (int w = 0; w < 8; ++w) mm = fmaxf(mm, s_red[w]);
        s_max = mm;
    }
    __syncthreads();
    const float mm2 = s_max;
    float sum = 0.f;
    for (int s = tid; s < SS; s += 256) {
        float e = expf(s_p[s] - mm2);
        s_p[s] = e;
        sum += e;
    }
    for (int o = 16; o; o >>= 1) sum += __shfl_xor_sync(~0u, sum, o);
    if (lane == 0) s_red[wid] = sum;
    __syncthreads();
    if (tid == 0) {
        float t = 0.f;
        for (int w = 0; w < 8; ++w) t += s_red[w];
        s_sum = 1.f / t;
    }
    __syncthreads();
    const float inv = s_sum;

    float4 acc = make_float4(0.f, 0.f, 0.f, 0.f);
    const float4* col = enc4 + tid;
    #pragma unroll 4
    for (int s = 0; s < SS; ++s) {
        float ps = s_p[s];
        float4 e = col[(size_t)s * 256];
        acc.x += ps * e.x; acc.y += ps * e.y; acc.z += ps * e.z; acc.w += ps * e.w;
    }
    acc.x *= inv; acc.y *= inv; acc.z *= inv; acc.w *= inv;

    const int d = tid * 4;
    *reinterpret_cast<float4*>(g_toout + (size_t)b * KOUT + HH + d) = acc;
    float4 rc = make_float4(fmaxf(acc.x, 0.f), fmaxf(acc.y, 0.f),
                            fmaxf(acc.z, 0.f), fmaxf(acc.w, 0.f));
    *reinterpret_cast<float4*>(g_togru + (size_t)b * KGRU + EE + d) = rc;

    if (tid < EE) {
        float e = emb[(size_t)x[b] * EE + tid];
        g_toout[(size_t)b * KOUT + H3 + tid] = e;
        g_togru[(size_t)b * KGRU + tid] = fmaxf(e, 0.f);
    }
}

// ---------------- GRU gates ----------------
__global__ void gru_gates(const float* __restrict__ hidden, float* __restrict__ out_h) {
    int idx = blockIdx.x * 256 + threadIdx.x;
    int b = idx >> 9, h = idx & 511;
    const float* gi = g_gi + (size_t)b * H3;
    const float* gh = g_gh + (size_t)b * H3;
    float r = 1.f / (1.f + expf(-(gi[h] + gh[h])));
    float z = 1.f / (1.f + expf(-(gi[HH + h] + gh[HH + h])));
    float n = tanhf(gi[2 * HH + h] + r * gh[2 * HH + h]);
    float hp = hidden[b * HH + h];
    float hn = (1.f - z) * n + z * hp;
    g_toout[(size_t)b * KOUT + h] = hn;
    out_h[b * HH + h] = hn;
}

// ---------------- launch ----------------
extern "C" void kernel_launch(void* const* d_in, const int* in_sizes, int n_in,
                              void* d_out, int out_size) {
    const int*   x      = (const int*)d_in[0];
    const float* hidden = (const float*)d_in[1];
    const float* enc    = (const float*)d_in[2];
    const float* emb    = (const float*)d_in[3];
    const float* attn_w = (const float*)d_in[4];
    const float* attn_b = (const float*)d_in[5];
    const float* v      = (const float*)d_in[6];
    const float* w_ih   = (const float*)d_in[7];
    const float* w_hh   = (const float*)d_in[8];
    const float* b_ih   = (const float*)d_in[9];
    const float* b_hh   = (const float*)d_in[10];
    const float* out_w  = (const float*)d_in[11];
    const float* out_b  = (const float*)d_in[12];
    float* out = (float*)d_out;

    static float *p_togru = nullptr, *p_toout = nullptr, *p_gi = nullptr, *p_gh = nullptr;
    if (!p_togru) {
        cudaGetSymbolAddress((void**)&p_togru, g_togru);
        cudaGetSymbolAddress((void**)&p_toout, g_toout);
        cudaGetSymbolAddress((void**)&p_gi, g_gi);
        cudaGetSymbolAddress((void**)&p_gh, g_gh);
        cudaFuncSetAttribute(mma_gemm, cudaFuncAttributeMaxDynamicSharedMemorySize, GEMM_SMEM);
    }

    prep_kernel<<<7, 256>>>(attn_w, attn_b, v);
    attn_kernel<<<BB, 256>>>(hidden, enc, emb, x);
    mma_gemm<<<H3 / 128, 256, GEMM_SMEM>>>(w_ih, p_togru, b_ih, p_gi, H3, KGRU, KGRU / 64, H3);
    mma_gemm<<<H3 / 128, 256, GEMM_SMEM>>>(w_hh, hidden, b_hh, p_gh, H3, HH, HH / 64, H3);
    gru_gates<<<(BB * HH) / 256, 256>>>(hidden, out + (size_t)BB * VV);
    mma_gemm<<<(VV + 127) / 128, 256, GEMM_SMEM>>>(out_w, p_toout, out_b, out, VV, KOUT, KOUT / 64, VV);
}

// round 7
// speedup vs baseline: 1.6270x; 1.2291x over previous
#include <cuda_runtime.h>
#include <cuda_bf16.h>
#include <cstdint>

// Problem dims
#define HH   512
#define EE   256
#define VV   50000
#define BB   128
#define SS   200
#define H3   1536          // 3H
#define KGRU 1280          // 2H + E
#define KOUT 1792          // 3H + E

// ---------------- scratch ----------------
__device__ float g_u[H3];
__device__ float g_c0;
__device__ __align__(16) float g_togru[BB * KGRU];
__device__ __align__(16) float g_toout[BB * KOUT];
__device__ __align__(16) float g_gi[BB * H3];
__device__ __align__(16) float g_gh[BB * H3];
// pre-converted B (hi/lo), swizzled tile layout: [chunk][128 rows][128B]
__device__ uint4 g_bhi[28 * 1024];
__device__ uint4 g_blo[28 * 1024];

// ---------------- helpers ----------------
__device__ __forceinline__ uint32_t smem_u32(const void* p) {
    uint32_t a;
    asm("{ .reg .u64 t; cvta.to.shared.u64 t, %1; cvt.u32.u64 %0, t; }" : "=r"(a) : "l"(p));
    return a;
}
__device__ __forceinline__ uint32_t pkbf(__nv_bfloat16 a, __nv_bfloat16 b) {
    return (uint32_t)__bfloat16_as_ushort(a) | ((uint32_t)__bfloat16_as_ushort(b) << 16);
}
__device__ __forceinline__ void split2(float x, float y, uint32_t& hv, uint32_t& lv) {
    __nv_bfloat16 xh = __float2bfloat16(x);
    __nv_bfloat16 yh = __float2bfloat16(y);
    __nv_bfloat16 xl = __float2bfloat16(x - __bfloat162float(xh));
    __nv_bfloat16 yl = __float2bfloat16(y - __bfloat162float(yh));
    hv = pkbf(xh, yh);
    lv = pkbf(xl, yl);
}
__device__ __forceinline__ void split8(float4 f0, float4 f1, uint4& hv, uint4& lv) {
    split2(f0.x, f0.y, hv.x, lv.x);
    split2(f0.z, f0.w, hv.y, lv.y);
    split2(f1.x, f1.y, hv.z, lv.z);
    split2(f1.z, f1.w, hv.w, lv.w);
}
__device__ __forceinline__ void sts128(uint32_t addr, uint4 v) {
    asm volatile("st.shared.v4.b32 [%0], {%1,%2,%3,%4};"
                 :: "r"(addr), "r"(v.x), "r"(v.y), "r"(v.z), "r"(v.w) : "memory");
}
__device__ __forceinline__ float4 lds128f(uint32_t a) {
    float4 v;
    asm volatile("ld.shared.v4.f32 {%0,%1,%2,%3}, [%4];"
                 : "=f"(v.x), "=f"(v.y), "=f"(v.z), "=f"(v.w) : "r"(a));
    return v;
}
__device__ __forceinline__ void ldsm4(uint32_t (&r)[4], uint32_t addr) {
    asm volatile("ldmatrix.sync.aligned.m8n8.x4.shared.b16 {%0,%1,%2,%3}, [%4];"
                 : "=r"(r[0]), "=r"(r[1]), "=r"(r[2]), "=r"(r[3]) : "r"(addr));
}
__device__ __forceinline__ void mma16816(float (&d)[4], const uint32_t (&a)[4],
                                         uint32_t b0, uint32_t b1) {
    asm volatile(
        "mma.sync.aligned.m16n8k16.row.col.f32.bf16.bf16.f32 "
        "{%0,%1,%2,%3}, {%4,%5,%6,%7}, {%8,%9}, {%0,%1,%2,%3};"
        : "+f"(d[0]), "+f"(d[1]), "+f"(d[2]), "+f"(d[3])
        : "r"(a[0]), "r"(a[1]), "r"(a[2]), "r"(a[3]), "r"(b0), "r"(b1));
}
__device__ __forceinline__ void cpasync16(uint32_t dst, const void* src) {
    asm volatile("{ .reg .u64 g; cvta.to.global.u64 g, %1; "
                 "cp.async.cg.shared.global [%0], [g], 16; }"
                 :: "r"(dst), "l"(src) : "memory");
}
#define CP_COMMIT() asm volatile("cp.async.commit_group;" ::: "memory")
#define CP_WAIT1()  asm volatile("cp.async.wait_group 1;" ::: "memory")
#define CP_WAIT0()  asm volatile("cp.async.wait_group 0;" ::: "memory")

// ---------------- B pre-convert: fp32 [128][K] -> swizzled bf16 hi/lo chunk tiles ----------------
__global__ void bconv_kernel(const float* __restrict__ B, int K) {
    int idx = blockIdx.x * 256 + threadIdx.x;
    if (idx >= K * 16) return;                 // K/64 chunks * 128 rows * 8 granules
    int c = idx >> 10, r = (idx >> 3) & 127, g8 = idx & 7;
    const float4* src = reinterpret_cast<const float4*>(B + (size_t)r * K + c * 64 + g8 * 8);
    float4 f0 = src[0], f1 = src[1];
    uint4 hv, lv;
    split8(f0, f1, hv, lv);
    uint32_t off = (uint32_t)c * 16384 + (uint32_t)r * 128 +
                   (((uint32_t)g8 * 16) ^ (((uint32_t)r & 7u) << 4));
    g_bhi[off >> 4] = hv;
    g_blo[off >> 4] = lv;
}

// ================= split-bf16 HMMA GEMM (cp.async pipelined) =================
// C[n*ldc + m] = sum_k A[m*K+k] * B[n*K+k] + bias[m], N=128, B pre-converted in g_bhi/g_blo.
// Template MT: CTA M-tile (128 for logits, 32 for GRU). 256 threads, 8 warps.
template <int MT>
__global__ __launch_bounds__(256, 1)
void mma_gemm(const float* __restrict__ A, const float* __restrict__ bias,
              float* __restrict__ C, int M, int K, int nchunk, int ldc) {
    constexpr int WM = MT / 32;          // warps along M
    constexpr int WN = 8 / WM;           // warps along N
    constexpr int NW = 128 / WN;         // n-cols per warp
    constexpr int NB = NW / 16;          // b ldsm frags
    constexpr int NA = NW / 8;           // n subtiles
    constexpr uint32_t AR = MT * 256;    // raw A stage bytes
    constexpr uint32_t AT = MT * 128;    // bf16 A tile bytes
    // smem: araw[2] | ahi[2] | alo[2] | bhi[3] | blo[3]
    extern __shared__ char smem[];
    const uint32_t sb = smem_u32(smem);
    const uint32_t o_ahi = 2 * AR, o_alo = 2 * AR + 2 * AT;
    const uint32_t o_bhi = 2 * AR + 4 * AT, o_blo = o_bhi + 49152;

    const int tid = threadIdx.x, wid = tid >> 5, lane = tid & 31;
    const int warpM = wid % WM, warpN = wid / WM;
    const int m0 = blockIdx.x * MT;

    // convert/cp.async A mapping: thread t (< 2*MT) owns half-row (row, h)
    const int crow = tid & (MT - 1), ch = (tid >> (MT == 128 ? 7 : 5)) & 1;
    const bool do_a = tid < 2 * MT;
    const bool avalid = do_a && (m0 + crow) < M;
    const int srow = ((m0 + crow) < M) ? (m0 + crow) : 0;
    const uint32_t rswz = ((uint32_t)crow & 7u) << 4;

    // mma-side addressing
    const int l15 = lane & 15, lhi = lane >> 4;
    const uint32_t rowAoff = (uint32_t)(warpM * 32 + l15) * 128;
    const uint32_t xorA = (((uint32_t)(warpM * 32 + l15)) & 7u) << 4;
    const uint32_t rowBoff = (uint32_t)(warpN * NW + l15) * 128;
    const uint32_t xorB = (((uint32_t)(warpN * NW + l15)) & 7u) << 4;

    float acc[2][NA][4];
    #pragma unroll
    for (int mt = 0; mt < 2; ++mt)
        #pragma unroll
        for (int na = 0; na < NA; ++na)
            #pragma unroll
            for (int q = 0; q < 4; ++q) acc[mt][na][q] = 0.f;

    // ---- issue helpers (inlined as lambdas) ----
    auto issue_a = [&](int c) {
        if (!do_a) return;
        const uint32_t dst0 = sb + (uint32_t)(c & 1) * AR + (uint32_t)crow * 256;
        const float* src0 = A + (size_t)srow * K + c * 64;
        #pragma unroll
        for (int i = 0; i < 8; ++i) {
            uint32_t g = (uint32_t)(ch * 8 + i);
            cpasync16(dst0 + ((g << 4) ^ rswz), src0 + g * 4);
        }
    };
    auto issue_b = [&](int c, int slot) {
        const char* shi = (const char*)g_bhi + (size_t)c * 16384;
        const char* slo = (const char*)g_blo + (size_t)c * 16384;
        const uint32_t dhi = sb + o_bhi + (uint32_t)slot * 16384;
        const uint32_t dlo = sb + o_blo + (uint32_t)slot * 16384;
        #pragma unroll
        for (int i = 0; i < 4; ++i) {
            uint32_t lin = (uint32_t)(tid + i * 256) * 16;
            cpasync16(dhi + lin, shi + lin);
            cpasync16(dlo + lin, slo + lin);
        }
    };

    // ---- prologue: chunks 0 and 1 ----
    issue_a(0); issue_b(0, 0); CP_COMMIT();
    if (nchunk > 1) { issue_a(1); issue_b(1, 1); }
    CP_COMMIT();

    int bslot = 0, bslot2 = 2;
    for (int c = 0; c < nchunk; ++c) {
        CP_WAIT1();
        __syncthreads();
        const uint32_t stA = (uint32_t)(c & 1);
        // convert A raw -> bf16 tiles (own half-row)
        if (do_a) {
            const uint32_t rbase = sb + stA * AR + (uint32_t)crow * 256;
            const uint32_t hbase = sb + o_ahi + stA * AT + (uint32_t)crow * 128;
            const uint32_t lbase = sb + o_alo + stA * AT + (uint32_t)crow * 128;
            #pragma unroll
            for (int j = 0; j < 4; ++j) {
                uint32_t g0 = (uint32_t)(ch * 8 + 2 * j);
                float4 f0 = lds128f(rbase + ((g0 << 4) ^ rswz));
                float4 f1 = lds128f(rbase + (((g0 + 1) << 4) ^ rswz));
                uint4 hv, lv;
                if (avalid) split8(f0, f1, hv, lv);
                else { hv = make_uint4(0, 0, 0, 0); lv = make_uint4(0, 0, 0, 0); }
                uint32_t toff = ((uint32_t)(ch * 64 + j * 16)) ^ rswz;
                sts128(hbase + toff, hv);
                sts128(lbase + toff, lv);
            }
        }
        // issue chunk c+2
        if (c + 2 < nchunk) { issue_a(c + 2); issue_b(c + 2, bslot2); }
        CP_COMMIT();
        __syncthreads();
        // ---- MMA on tiles ----
        const uint32_t ahiB = sb + o_ahi + stA * AT;
        const uint32_t aloB = sb + o_alo + stA * AT;
        const uint32_t bhiB = sb + o_bhi + (uint32_t)bslot * 16384;
        const uint32_t bloB = sb + o_blo + (uint32_t)bslot * 16384;
        #pragma unroll
        for (int p = 0; p < 3; ++p) {
            const uint32_t aslab = (p == 2) ? aloB : ahiB;
            const uint32_t bslab = (p == 1) ? bloB : bhiB;
            #pragma unroll
            for (int k16 = 0; k16 < 4; ++k16) {
                const uint32_t kb = (uint32_t)(k16 * 32 + lhi * 16);
                const uint32_t kA = kb ^ xorA, kB = kb ^ xorB;
                uint32_t afr[2][4], bfr[NB][4];
                ldsm4(afr[0], aslab + rowAoff + kA);
                ldsm4(afr[1], aslab + rowAoff + 2048 + kA);
                #pragma unroll
                for (int nt = 0; nt < NB; ++nt)
                    ldsm4(bfr[nt], bslab + rowBoff + (uint32_t)nt * 2048 + kB);
                #pragma unroll
                for (int mt = 0; mt < 2; ++mt)
                    #pragma unroll
                    for (int na = 0; na < NA; ++na) {
                        const uint32_t* bq = bfr[na >> 1];
                        if (na & 1) mma16816(acc[mt][na], afr[mt], bq[1], bq[3]);
                        else        mma16816(acc[mt][na], afr[mt], bq[0], bq[2]);
                    }
            }
        }
        bslot = (bslot == 2) ? 0 : bslot + 1;
        bslot2 = (bslot2 == 2) ? 0 : bslot2 + 1;
    }
    CP_WAIT0();

    // ---- epilogue ----
    const int mrow = lane >> 2, ncol = (lane & 3) * 2;
    #pragma unroll
    for (int mt = 0; mt < 2; ++mt) {
        const int mb = m0 + warpM * 32 + mt * 16 + mrow;
        const bool v0 = mb < M, v1 = (mb + 8) < M;
        const float bv0 = v0 ? bias[mb] : 0.f;
        const float bv1 = v1 ? bias[mb + 8] : 0.f;
        #pragma unroll
        for (int na = 0; na < NA; ++na) {
            const int n = warpN * NW + na * 8 + ncol;
            float* c0 = C + (size_t)n * ldc;
            float* c1 = C + (size_t)(n + 1) * ldc;
            if (v0) { c0[mb] = acc[mt][na][0] + bv0; c1[mb] = acc[mt][na][1] + bv0; }
            if (v1) { c0[mb + 8] = acc[mt][na][2] + bv1; c1[mb + 8] = acc[mt][na][3] + bv1; }
        }
    }
}

// ---------------- kernel 1: u = attn_w^T v, c0 = attn_b.v ----------------
__global__ void prep_kernel(const float* __restrict__ attn_w,
                            const float* __restrict__ attn_b,
                            const float* __restrict__ v) {
    int j = blockIdx.x * blockDim.x + threadIdx.x;
    if (j < H3) {
        float s = 0.f;
        #pragma unroll 8
        for (int h = 0; h < HH; ++h) s += attn_w[h * H3 + j] * v[h];
        g_u[j] = s;
    } else if (j == H3) {
        float s = 0.f;
        for (int h = 0; h < HH; ++h) s += attn_b[h] * v[h];
        g_c0 = s;
    }
}

// ---------------- kernel 2: scores + softmax + context ----------------
__global__ __launch_bounds__(256)
void attn_kernel(const float* __restrict__ hidden,
                 const float* __restrict__ enc,
                 const float* __restrict__ emb,
                 const int* __restrict__ x) {
    __shared__ float s_u[2 * HH];
    __shared__ float s_p[256];
    __shared__ float s_red[8];
    __shared__ float s_constb, s_max, s_sum;

    const int b = blockIdx.x;
    const int tid = threadIdx.x;
    const int lane = tid & 31, wid = tid >> 5;

    for (int j = tid; j < 2 * HH; j += 256) s_u[j] = g_u[HH + j];

    float p = 0.f;
    for (int j = tid; j < HH; j += 256) p += hidden[b * HH + j] * g_u[j];
    for (int o = 16; o; o >>= 1) p += __shfl_xor_sync(~0u, p, o);
    if (lane == 0) s_red[wid] = p;
    __syncthreads();
    if (tid == 0) {
        float s = g_c0;
        for (int w = 0; w < 8; ++w) s += s_red[w];
        s_constb = s;
    }
    __syncthreads();
    const float cb = s_constb;

    const float4* enc4 = reinterpret_cast<const float4*>(enc) + (size_t)b * SS * 256;
    const float4* u4 = reinterpret_cast<const float4*>(s_u);
    for (int s = wid; s < SS; s += 8) {
        const float4* row = enc4 + (size_t)s * 256;
        float acc = 0.f;
        #pragma unroll
        for (int t = 0; t < 8; ++t) {
            float4 e = row[lane + 32 * t];
            float4 u = u4[lane + 32 * t];
            acc += e.x * u.x + e.y * u.y + e.z * u.z + e.w * u.w;
        }
        for (int o = 16; o; o >>= 1) acc += __shfl_xor_sync(~0u, acc, o);
        if (lane == 0) s_p[s] = acc + cb;
    }
    __syncthreads();

    float m = -1e30f;
    for (int s = tid; s < SS; s += 256) m = fmaxf(m, s_p[s]);
    for (int o = 16; o; o >>= 1) m = fmaxf(m, __shfl_xor_sync(~0u, m, o));
    if (lane == 0) s_red[wid] = m;
    __syncthreads();
    if (tid == 0) {
        float mm = -1e30f;
        for (int w = 0; w < 8; ++w) mm = fmaxf(mm, s_red[w]);
        s_max = mm;
    }
    __syncthreads();
    const float mm2 = s_max;
    float sum = 0.f;
    for (int s = tid; s < SS; s += 256) {
        float e = expf(s_p[s] - mm2);
        s_p[s] = e;
        sum += e;
    }
    for (int o = 16; o; o >>= 1) sum += __shfl_xor_sync(~0u, sum, o);
    if (lane == 0) s_red[wid] = sum;
    __syncthreads();
    if (tid == 0) {
        float t = 0.f;
        for (int w = 0; w < 8; ++w) t += s_red[w];
        s_sum = 1.f / t;
    }
    __syncthreads();
    const float inv = s_sum;

    float4 acc = make_float4(0.f, 0.f, 0.f, 0.f);
    const float4* col = enc4 + tid;
    #pragma unroll 4
    for (int s = 0; s < SS; ++s) {
        float ps = s_p[s];
        float4 e = col[(size_t)s * 256];
        acc.x += ps * e.x; acc.y += ps * e.y; acc.z += ps * e.z; acc.w += ps * e.w;
    }
    acc.x *= inv; acc.y *= inv; acc.z *= inv; acc.w *= inv;

    const int d = tid * 4;
    *reinterpret_cast<float4*>(g_toout + (size_t)b * KOUT + HH + d) = acc;
    float4 rc = make_float4(fmaxf(acc.x, 0.f), fmaxf(acc.y, 0.f),
                            fmaxf(acc.z, 0.f), fmaxf(acc.w, 0.f));
    *reinterpret_cast<float4*>(g_togru + (size_t)b * KGRU + EE + d) = rc;

    if (tid < EE) {
        float e = emb[(size_t)x[b] * EE + tid];
        g_toout[(size_t)b * KOUT + H3 + tid] = e;
        g_togru[(size_t)b * KGRU + tid] = fmaxf(e, 0.f);
    }
}

// ---------------- GRU gates ----------------
__global__ void gru_gates(const float* __restrict__ hidden, float* __restrict__ out_h) {
    int idx = blockIdx.x * 256 + threadIdx.x;
    int b = idx >> 9, h = idx & 511;
    const float* gi = g_gi + (size_t)b * H3;
    const float* gh = g_gh + (size_t)b * H3;
    float r = 1.f / (1.f + expf(-(gi[h] + gh[h])));
    float z = 1.f / (1.f + expf(-(gi[HH + h] + gh[HH + h])));
    float n = tanhf(gi[2 * HH + h] + r * gh[2 * HH + h]);
    float hp = hidden[b * HH + h];
    float hn = (1.f - z) * n + z * hp;
    g_toout[(size_t)b * KOUT + h] = hn;
    out_h[b * HH + h] = hn;
}

// ---------------- launch ----------------
#define SMEM_GEMM(MT) ((MT) * 1024 + 6 * 16384)

extern "C" void kernel_launch(void* const* d_in, const int* in_sizes, int n_in,
                              void* d_out, int out_size) {
    const int*   x      = (const int*)d_in[0];
    const float* hidden = (const float*)d_in[1];
    const float* enc    = (const float*)d_in[2];
    const float* emb    = (const float*)d_in[3];
    const float* attn_w = (const float*)d_in[4];
    const float* attn_b = (const float*)d_in[5];
    const float* v      = (const float*)d_in[6];
    const float* w_ih   = (const float*)d_in[7];
    const float* w_hh   = (const float*)d_in[8];
    const float* b_ih   = (const float*)d_in[9];
    const float* b_hh   = (const float*)d_in[10];
    const float* out_w  = (const float*)d_in[11];
    const float* out_b  = (const float*)d_in[12];
    float* out = (float*)d_out;

    static float *p_togru = nullptr, *p_gi = nullptr, *p_gh = nullptr;
    if (!p_togru) {
        cudaGetSymbolAddress((void**)&p_togru, g_togru);
        cudaGetSymbolAddress((void**)&p_gi, g_gi);
        cudaGetSymbolAddress((void**)&p_gh, g_gh);
        cudaFuncSetAttribute(mma_gemm<128>, cudaFuncAttributeMaxDynamicSharedMemorySize,
                             SMEM_GEMM(128));
        cudaFuncSetAttribute(mma_gemm<32>, cudaFuncAttributeMaxDynamicSharedMemorySize,
                             SMEM_GEMM(32));
    }
    static float* p_toout = nullptr;
    if (!p_toout) cudaGetSymbolAddress((void**)&p_toout, g_toout);

    prep_kernel<<<7, 256>>>(attn_w, attn_b, v);
    attn_kernel<<<BB, 256>>>(hidden, enc, emb, x);

    bconv_kernel<<<(KGRU * 16 + 255) / 256, 256>>>(p_togru, KGRU);
    mma_gemm<32><<<H3 / 32, 256, SMEM_GEMM(32)>>>(w_ih, b_ih, p_gi, H3, KGRU, KGRU / 64, H3);

    bconv_kernel<<<(HH * 16 + 255) / 256, 256>>>(hidden, HH);
    mma_gemm<32><<<H3 / 32, 256, SMEM_GEMM(32)>>>(w_hh, b_hh, p_gh, H3, HH, HH / 64, H3);

    gru_gates<<<(BB * HH) / 256, 256>>>(hidden, out + (size_t)BB * VV);

    bconv_kernel<<<(KOUT * 16 + 255) / 256, 256>>>(p_toout, KOUT);
    mma_gemm<128><<<(VV + 127) / 128, 256, SMEM_GEMM(128)>>>(out_w, out_b, out, VV, KOUT,
                                                             KOUT / 64, VV);
}

// round 8
// speedup vs baseline: 1.8994x; 1.1674x over previous
#include <cuda_runtime.h>
#include <cuda_bf16.h>
#include <cstdint>

// Problem dims
#define HH   512
#define EE   256
#define VV   50000
#define BB   128
#define SS   200
#define H3   1536          // 3H
#define KGRU 1280          // 2H + E
#define KOUT 1792          // 3H + E

// ---------------- scratch ----------------
__device__ float g_u[H3];
__device__ float g_c0;
__device__ __align__(16) float g_togru[BB * KGRU];
__device__ __align__(16) float g_toout[BB * KOUT];
__device__ __align__(16) float g_gi[BB * H3];
__device__ __align__(16) float g_gh[BB * H3];
// pre-converted B (hi/lo), swizzled tile layout: [chunk][128 rows][128B]
__device__ uint4 g_bhi[28 * 1024];
__device__ uint4 g_blo[28 * 1024];

// ---------------- helpers ----------------
__device__ __forceinline__ uint32_t smem_u32(const void* p) {
    uint32_t a;
    asm("{ .reg .u64 t; cvta.to.shared.u64 t, %1; cvt.u32.u64 %0, t; }" : "=r"(a) : "l"(p));
    return a;
}
__device__ __forceinline__ uint32_t pkbf(__nv_bfloat16 a, __nv_bfloat16 b) {
    return (uint32_t)__bfloat16_as_ushort(a) | ((uint32_t)__bfloat16_as_ushort(b) << 16);
}
__device__ __forceinline__ void split2(float x, float y, uint32_t& hv, uint32_t& lv) {
    __nv_bfloat16 xh = __float2bfloat16(x);
    __nv_bfloat16 yh = __float2bfloat16(y);
    __nv_bfloat16 xl = __float2bfloat16(x - __bfloat162float(xh));
    __nv_bfloat16 yl = __float2bfloat16(y - __bfloat162float(yh));
    hv = pkbf(xh, yh);
    lv = pkbf(xl, yl);
}
__device__ __forceinline__ void split8(float4 f0, float4 f1, uint4& hv, uint4& lv) {
    split2(f0.x, f0.y, hv.x, lv.x);
    split2(f0.z, f0.w, hv.y, lv.y);
    split2(f1.x, f1.y, hv.z, lv.z);
    split2(f1.z, f1.w, hv.w, lv.w);
}
__device__ __forceinline__ void sts128(uint32_t addr, uint4 v) {
    asm volatile("st.shared.v4.b32 [%0], {%1,%2,%3,%4};"
                 :: "r"(addr), "r"(v.x), "r"(v.y), "r"(v.z), "r"(v.w) : "memory");
}
__device__ __forceinline__ float4 lds128f(uint32_t a) {
    float4 v;
    asm volatile("ld.shared.v4.f32 {%0,%1,%2,%3}, [%4];"
                 : "=f"(v.x), "=f"(v.y), "=f"(v.z), "=f"(v.w) : "r"(a));
    return v;
}
__device__ __forceinline__ void ldsm4(uint32_t (&r)[4], uint32_t addr) {
    asm volatile("ldmatrix.sync.aligned.m8n8.x4.shared.b16 {%0,%1,%2,%3}, [%4];"
                 : "=r"(r[0]), "=r"(r[1]), "=r"(r[2]), "=r"(r[3]) : "r"(addr));
}
__device__ __forceinline__ void mma16816(float (&d)[4], const uint32_t (&a)[4],
                                         uint32_t b0, uint32_t b1) {
    asm volatile(
        "mma.sync.aligned.m16n8k16.row.col.f32.bf16.bf16.f32 "
        "{%0,%1,%2,%3}, {%4,%5,%6,%7}, {%8,%9}, {%0,%1,%2,%3};"
        : "+f"(d[0]), "+f"(d[1]), "+f"(d[2]), "+f"(d[3])
        : "r"(a[0]), "r"(a[1]), "r"(a[2]), "r"(a[3]), "r"(b0), "r"(b1));
}
__device__ __forceinline__ void cpasync16(uint32_t dst, const void* src) {
    asm volatile("{ .reg .u64 g; cvta.to.global.u64 g, %1; "
                 "cp.async.cg.shared.global [%0], [g], 16; }"
                 :: "r"(dst), "l"(src) : "memory");
}
#define CP_COMMIT() asm volatile("cp.async.commit_group;" ::: "memory")
#define CP_WAIT1()  asm volatile("cp.async.wait_group 1;" ::: "memory")
#define CP_WAIT0()  asm volatile("cp.async.wait_group 0;" ::: "memory")

// ---------------- B pre-convert: fp32 [128][K] -> swizzled bf16 hi/lo chunk tiles ----------------
__global__ void bconv_kernel(const float* __restrict__ B, int K, int boff) {
    int idx = blockIdx.x * 256 + threadIdx.x;
    if (idx >= K * 16) return;                 // K/64 chunks * 128 rows * 8 granules
    int c = idx >> 10, r = (idx >> 3) & 127, g8 = idx & 7;
    const float4* src = reinterpret_cast<const float4*>(B + (size_t)r * K + c * 64 + g8 * 8);
    float4 f0 = src[0], f1 = src[1];
    uint4 hv, lv;
    split8(f0, f1, hv, lv);
    uint32_t off = (uint32_t)(boff + c) * 16384 + (uint32_t)r * 128 +
                   (((uint32_t)g8 * 16) ^ (((uint32_t)r & 7u) << 4));
    g_bhi[off >> 4] = hv;
    g_blo[off >> 4] = lv;
}

// ================= big logits GEMM: 512 threads, 16 warps (4M x 4N) =================
// C[n*ldc + m] = sum_k A[m*K+k] * B[n*K+k] + bias[m], N=128, MT=128.
// A: LDG->regs->convert->smem tiles (conflict-free). B: cp.async from g_bhi/g_blo.
// smem: Ahi/Alo tiles 2 stages (64KB) | Bhi/Blo 2 stages (64KB) = 128KB.
#define BIG_SMEM 131072

__global__ __launch_bounds__(512, 1)
void mma_gemm_big(const float* __restrict__ A, const float* __restrict__ bias,
                  float* __restrict__ C, int M, int K, int nchunk, int ldc) {
    extern __shared__ char smem[];
    const uint32_t sb = smem_u32(smem);
    const int tid = threadIdx.x, wid = tid >> 5, lane = tid & 31;
    const int warpM = wid & 3, warpN = wid >> 2;
    const int m0 = blockIdx.x * 128;

    // A staging: thread owns (row = tid>>2, quarter q = tid&3) -> 16 floats/chunk
    const int crow = tid >> 2, cq = tid & 3;
    const bool avalid = (m0 + crow) < M;
    const int srow = avalid ? (m0 + crow) : 0;
    const uint32_t rswz = ((uint32_t)crow & 7u) << 4;
    const float4* aq = reinterpret_cast<const float4*>(A + (size_t)srow * K) + cq * 4;

    // mma-side addressing
    const int l15 = lane & 15, lhi = lane >> 4;
    const uint32_t rowAoff = (uint32_t)(warpM * 32 + l15) * 128;
    const uint32_t xorA = (((uint32_t)(warpM * 32 + l15)) & 7u) << 4;
    const uint32_t rowBoff = (uint32_t)(warpN * 32 + l15) * 128;
    const uint32_t xorB = (((uint32_t)(warpN * 32 + l15)) & 7u) << 4;

    float acc[2][4][4];
    #pragma unroll
    for (int mt = 0; mt < 2; ++mt)
        #pragma unroll
        for (int na = 0; na < 4; ++na)
            #pragma unroll
            for (int q = 0; q < 4; ++q) acc[mt][na][q] = 0.f;

    float4 rA[4];

    auto issue_b = [&](int c, int slot) {
        const char* shi = (const char*)g_bhi + (size_t)c * 16384;
        const char* slo = (const char*)g_blo + (size_t)c * 16384;
        const uint32_t dhi = sb + 65536u + (uint32_t)slot * 32768u;
        const uint32_t dlo = dhi + 16384u;
        #pragma unroll
        for (int i = 0; i < 2; ++i) {
            uint32_t lin = (uint32_t)(tid + i * 512) * 16;
            cpasync16(dhi + lin, shi + lin);
            cpasync16(dlo + lin, slo + lin);
        }
    };
    auto convert_sts = [&](int st) {
        const uint32_t hb = sb + (uint32_t)st * 32768u + (uint32_t)crow * 128;
        const uint32_t lb = hb + 16384u;
        const uint32_t o0 = ((uint32_t)(cq * 32)) ^ rswz;
        const uint32_t o1 = ((uint32_t)(cq * 32 + 16)) ^ rswz;
        uint4 hv, lv;
        if (avalid) split8(rA[0], rA[1], hv, lv);
        else { hv = make_uint4(0, 0, 0, 0); lv = make_uint4(0, 0, 0, 0); }
        sts128(hb + o0, hv);
        sts128(lb + o0, lv);
        if (avalid) split8(rA[2], rA[3], hv, lv);
        else { hv = make_uint4(0, 0, 0, 0); lv = make_uint4(0, 0, 0, 0); }
        sts128(hb + o1, hv);
        sts128(lb + o1, lv);
    };

    // ---- prologue: B(0), tiles(0), LDG(1) ----
    #pragma unroll
    for (int i = 0; i < 4; ++i) rA[i] = aq[i];
    issue_b(0, 0);
    CP_COMMIT();
    convert_sts(0);
    if (nchunk > 1) {
        #pragma unroll
        for (int i = 0; i < 4; ++i) rA[i] = aq[16 + i];
    }

    for (int c = 0; c < nchunk; ++c) {
        CP_WAIT0();
        __syncthreads();                        // tiles(c) + B(c) visible everywhere
        if (c + 1 < nchunk) { issue_b(c + 1, (c + 1) & 1); CP_COMMIT(); }

        const uint32_t stA = (uint32_t)(c & 1) * 32768u;
        const uint32_t stB = sb + 65536u + (uint32_t)(c & 1) * 32768u;
        #pragma unroll
        for (int p = 0; p < 3; ++p) {
            const uint32_t aslab = sb + stA + ((p == 2) ? 16384u : 0u);
            const uint32_t bslab = stB + ((p == 1) ? 16384u : 0u);
            #pragma unroll
            for (int k16 = 0; k16 < 4; ++k16) {
                const uint32_t kb = (uint32_t)(k16 * 32 + lhi * 16);
                const uint32_t kA = kb ^ xorA, kB = kb ^ xorB;
                uint32_t afr[2][4], bfr[2][4];
                ldsm4(afr[0], aslab + rowAoff + kA);
                ldsm4(afr[1], aslab + rowAoff + 2048 + kA);
                ldsm4(bfr[0], bslab + rowBoff + kB);
                ldsm4(bfr[1], bslab + rowBoff + 2048 + kB);
                #pragma unroll
                for (int mt = 0; mt < 2; ++mt)
                    #pragma unroll
                    for (int na = 0; na < 4; ++na) {
                        const uint32_t* bq = bfr[na >> 1];
                        if (na & 1) mma16816(acc[mt][na], afr[mt], bq[1], bq[3]);
                        else        mma16816(acc[mt][na], afr[mt], bq[0], bq[2]);
                    }
            }
        }
        if (c + 1 < nchunk) {
            convert_sts((c + 1) & 1);
            if (c + 2 < nchunk) {
                #pragma unroll
                for (int i = 0; i < 4; ++i) rA[i] = aq[(c + 2) * 16 + i];
            }
        }
    }

    // ---- epilogue ----
    const int mrow = lane >> 2, ncol = (lane & 3) * 2;
    #pragma unroll
    for (int mt = 0; mt < 2; ++mt) {
        const int mb = m0 + warpM * 32 + mt * 16 + mrow;
        const bool v0 = mb < M, v1 = (mb + 8) < M;
        const float bv0 = v0 ? bias[mb] : 0.f;
        const float bv1 = v1 ? bias[mb + 8] : 0.f;
        #pragma unroll
        for (int na = 0; na < 4; ++na) {
            const int n = warpN * 32 + na * 8 + ncol;
            float* c0 = C + (size_t)n * ldc;
            float* c1 = C + (size_t)(n + 1) * ldc;
            if (v0) { c0[mb] = acc[mt][na][0] + bv0; c1[mb] = acc[mt][na][1] + bv0; }
            if (v1) { c0[mb + 8] = acc[mt][na][2] + bv1; c1[mb + 8] = acc[mt][na][3] + bv1; }
        }
    }
}

// ================= small GEMM body (MT=32), used by fused GRU launch =================
// smem: araw[2](16KB) | ahi[2](8KB) | alo[2](8KB) | bhi[3](48KB) | blo[3](48KB) = 128KB
#define SMALL_SMEM 131072

__device__ __forceinline__
void gemm32_body(const float* __restrict__ A, const float* __restrict__ bias,
                 float* __restrict__ C, int M, int K, int nchunk, int ldc,
                 int boff, int m0, char* smem) {
    constexpr uint32_t AR = 8192, AT = 4096;
    const uint32_t sb = smem_u32(smem);
    const uint32_t o_ahi = 2 * AR, o_alo = 2 * AR + 2 * AT;
    const uint32_t o_bhi = 2 * AR + 4 * AT, o_blo = o_bhi + 49152;

    const int tid = threadIdx.x, wid = tid >> 5, lane = tid & 31;
    const int warpN = wid;  // WM=1, WN=8, NW=16

    const int crow = tid & 31, ch = (tid >> 5) & 1;
    const bool do_a = tid < 64;
    const bool avalid = do_a && (m0 + crow) < M;
    const int srow = ((m0 + crow) < M) ? (m0 + crow) : 0;
    const uint32_t rswz = ((uint32_t)crow & 7u) << 4;

    const int l15 = lane & 15, lhi = lane >> 4;
    const uint32_t rowAoff = (uint32_t)l15 * 128;
    const uint32_t xorA = (((uint32_t)l15) & 7u) << 4;
    const uint32_t rowBoff = (uint32_t)(warpN * 16 + l15) * 128;
    const uint32_t xorB = (((uint32_t)(warpN * 16 + l15)) & 7u) << 4;

    float acc[2][2][4];
    #pragma unroll
    for (int mt = 0; mt < 2; ++mt)
        #pragma unroll
        for (int na = 0; na < 2; ++na)
            #pragma unroll
            for (int q = 0; q < 4; ++q) acc[mt][na][q] = 0.f;

    auto issue_a = [&](int c) {
        if (!do_a) return;
        const uint32_t dst0 = sb + (uint32_t)(c & 1) * AR + (uint32_t)crow * 256;
        const float* src0 = A + (size_t)srow * K + c * 64;
        #pragma unroll
        for (int i = 0; i < 8; ++i) {
            uint32_t g = (uint32_t)(ch * 8 + i);
            cpasync16(dst0 + ((g << 4) ^ rswz), src0 + g * 4);
        }
    };
    auto issue_b = [&](int c, int slot) {
        const char* shi = (const char*)g_bhi + (size_t)(boff + c) * 16384;
        const char* slo = (const char*)g_blo + (size_t)(boff + c) * 16384;
        const uint32_t dhi = sb + o_bhi + (uint32_t)slot * 16384;
        const uint32_t dlo = sb + o_blo + (uint32_t)slot * 16384;
        #pragma unroll
        for (int i = 0; i < 4; ++i) {
            uint32_t lin = (uint32_t)(tid + i * 256) * 16;
            cpasync16(dhi + lin, shi + lin);
            cpasync16(dlo + lin, slo + lin);
        }
    };

    issue_a(0); issue_b(0, 0); CP_COMMIT();
    if (nchunk > 1) { issue_a(1); issue_b(1, 1); }
    CP_COMMIT();

    int bslot = 0, bslot2 = 2;
    for (int c = 0; c < nchunk; ++c) {
        CP_WAIT1();
        __syncthreads();
        const uint32_t stA = (uint32_t)(c & 1);
        if (do_a) {
            const uint32_t rbase = sb + stA * AR + (uint32_t)crow * 256;
            const uint32_t hbase = sb + o_ahi + stA * AT + (uint32_t)crow * 128;
            const uint32_t lbase = sb + o_alo + stA * AT + (uint32_t)crow * 128;
            #pragma unroll
            for (int j = 0; j < 4; ++j) {
                uint32_t g0 = (uint32_t)(ch * 8 + 2 * j);
                float4 f0 = lds128f(rbase + ((g0 << 4) ^ rswz));
                float4 f1 = lds128f(rbase + (((g0 + 1) << 4) ^ rswz));
                uint4 hv, lv;
                if (avalid) split8(f0, f1, hv, lv);
                else { hv = make_uint4(0, 0, 0, 0); lv = make_uint4(0, 0, 0, 0); }
                uint32_t toff = ((uint32_t)(ch * 64 + j * 16)) ^ rswz;
                sts128(hbase + toff, hv);
                sts128(lbase + toff, lv);
            }
        }
        if (c + 2 < nchunk) { issue_a(c + 2); issue_b(c + 2, bslot2); }
        CP_COMMIT();
        __syncthreads();
        const uint32_t ahiB = sb + o_ahi + stA * AT;
        const uint32_t aloB = sb + o_alo + stA * AT;
        const uint32_t bhiB = sb + o_bhi + (uint32_t)bslot * 16384;
        const uint32_t bloB = sb + o_blo + (uint32_t)bslot * 16384;
        #pragma unroll
        for (int p = 0; p < 3; ++p) {
            const uint32_t aslab = (p == 2) ? aloB : ahiB;
            const uint32_t bslab = (p == 1) ? bloB : bhiB;
            #pragma unroll
            for (int k16 = 0; k16 < 4; ++k16) {
                const uint32_t kb = (uint32_t)(k16 * 32 + lhi * 16);
                const uint32_t kA = kb ^ xorA, kB = kb ^ xorB;
                uint32_t afr[2][4], bfr[4];
                ldsm4(afr[0], aslab + rowAoff + kA);
                ldsm4(afr[1], aslab + rowAoff + 2048 + kA);
                ldsm4(bfr, bslab + rowBoff + kB);
                #pragma unroll
                for (int mt = 0; mt < 2; ++mt) {
                    mma16816(acc[mt][0], afr[mt], bfr[0], bfr[2]);
                    mma16816(acc[mt][1], afr[mt], bfr[1], bfr[3]);
                }
            }
        }
        bslot = (bslot == 2) ? 0 : bslot + 1;
        bslot2 = (bslot2 == 2) ? 0 : bslot2 + 1;
    }
    CP_WAIT0();

    const int mrow = lane >> 2, ncol = (lane & 3) * 2;
    #pragma unroll
    for (int mt = 0; mt < 2; ++mt) {
        const int mb = m0 + mt * 16 + mrow;
        const bool v0 = mb < M, v1 = (mb + 8) < M;
        const float bv0 = v0 ? bias[mb] : 0.f;
        const float bv1 = v1 ? bias[mb + 8] : 0.f;
        #pragma unroll
        for (int na = 0; na < 2; ++na) {
            const int n = warpN * 16 + na * 8 + ncol;
            float* c0 = C + (size_t)n * ldc;
            float* c1 = C + (size_t)(n + 1) * ldc;
            if (v0) { c0[mb] = acc[mt][na][0] + bv0; c1[mb] = acc[mt][na][1] + bv0; }
            if (v1) { c0[mb + 8] = acc[mt][na][2] + bv1; c1[mb + 8] = acc[mt][na][3] + bv1; }
        }
    }
}

__global__ __launch_bounds__(256, 1)
void gru_gemm_fused(const float* __restrict__ A1, const float* __restrict__ b1,
                    float* __restrict__ C1, int K1, int nc1,
                    const float* __restrict__ A2, const float* __restrict__ b2,
                    float* __restrict__ C2, int K2, int nc2) {
    extern __shared__ char smem[];
    if (blockIdx.x < 48)
        gemm32_body(A1, b1, C1, H3, K1, nc1, H3, 0, blockIdx.x * 32, smem);
    else
        gemm32_body(A2, b2, C2, H3, K2, nc2, H3, nc1, (blockIdx.x - 48) * 32, smem);
}

// ---------------- kernel 1: u = attn_w^T v, c0 = attn_b.v ----------------
__global__ void prep_kernel(const float* __restrict__ attn_w,
                            const float* __restrict__ attn_b,
                            const float* __restrict__ v) {
    int j = blockIdx.x * blockDim.x + threadIdx.x;
    if (j < H3) {
        float s = 0.f;
        #pragma unroll 8
        for (int h = 0; h < HH; ++h) s += attn_w[h * H3 + j] * v[h];
        g_u[j] = s;
    } else if (j == H3) {
        float s = 0.f;
        for (int h = 0; h < HH; ++h) s += attn_b[h] * v[h];
        g_c0 = s;
    }
}

// ---------------- kernel 2: scores + softmax + context ----------------
__global__ __launch_bounds__(256)
void attn_kernel(const float* __restrict__ hidden,
                 const float* __restrict__ enc,
                 const float* __restrict__ emb,
                 const int* __restrict__ x) {
    __shared__ float s_u[2 * HH];
    __shared__ float s_p[256];
    __shared__ float s_red[8];
    __shared__ float s_constb, s_max, s_sum;

    const int b = blockIdx.x;
    const int tid = threadIdx.x;
    const int lane = tid & 31, wid = tid >> 5;

    for (int j = tid; j < 2 * HH; j += 256) s_u[j] = g_u[HH + j];

    float p = 0.f;
    for (int j = tid; j < HH; j += 256) p += hidden[b * HH + j] * g_u[j];
    for (int o = 16; o; o >>= 1) p += __shfl_xor_sync(~0u, p, o);
    if (lane == 0) s_red[wid] = p;
    __syncthreads();
    if (tid == 0) {
        float s = g_c0;
        for (int w = 0; w < 8; ++w) s += s_red[w];
        s_constb = s;
    }
    __syncthreads();
    const float cb = s_constb;

    const float4* enc4 = reinterpret_cast<const float4*>(enc) + (size_t)b * SS * 256;
    const float4* u4 = reinterpret_cast<const float4*>(s_u);
    for (int s = wid; s < SS; s += 8) {
        const float4* row = enc4 + (size_t)s * 256;
        float acc = 0.f;
        #pragma unroll
        for (int t = 0; t < 8; ++t) {
            float4 e = row[lane + 32 * t];
            float4 u = u4[lane + 32 * t];
            acc += e.x * u.x + e.y * u.y + e.z * u.z + e.w * u.w;
        }
        for (int o = 16; o; o >>= 1) acc += __shfl_xor_sync(~0u, acc, o);
        if (lane == 0) s_p[s] = acc + cb;
    }
    __syncthreads();

    float m = -1e30f;
    for (int s = tid; s < SS; s += 256) m = fmaxf(m, s_p[s]);
    for (int o = 16; o; o >>= 1) m = fmaxf(m, __shfl_xor_sync(~0u, m, o));
    if (lane == 0) s_red[wid] = m;
    __syncthreads();
    if (tid == 0) {
        float mm = -1e30f;
        for (int w = 0; w < 8; ++w) mm = fmaxf(mm, s_red[w]);
        s_max = mm;
    }
    __syncthreads();
    const float mm2 = s_max;
    float sum = 0.f;
    for (int s = tid; s < SS; s += 256) {
        float e = expf(s_p[s] - mm2);
        s_p[s] = e;
        sum += e;
    }
    for (int o = 16; o; o >>= 1) sum += __shfl_xor_sync(~0u, sum, o);
    if (lane == 0) s_red[wid] = sum;
    __syncthreads();
    if (tid == 0) {
        float t = 0.f;
        for (int w = 0; w < 8; ++w) t += s_red[w];
        s_sum = 1.f / t;
    }
    __syncthreads();
    const float inv = s_sum;

    float4 acc = make_float4(0.f, 0.f, 0.f, 0.f);
    const float4* col = enc4 + tid;
    #pragma unroll 4
    for (int s = 0; s < SS; ++s) {
        float ps = s_p[s];
        float4 e = col[(size_t)s * 256];
        acc.x += ps * e.x; acc.y += ps * e.y; acc.z += ps * e.z; acc.w += ps * e.w;
    }
    acc.x *= inv; acc.y *= inv; acc.z *= inv; acc.w *= inv;

    const int d = tid * 4;
    *reinterpret_cast<float4*>(g_toout + (size_t)b * KOUT + HH + d) = acc;
    float4 rc = make_float4(fmaxf(acc.x, 0.f), fmaxf(acc.y, 0.f),
                            fmaxf(acc.z, 0.f), fmaxf(acc.w, 0.f));
    *reinterpret_cast<float4*>(g_togru + (size_t)b * KGRU + EE + d) = rc;

    if (tid < EE) {
        float e = emb[(size_t)x[b] * EE + tid];
        g_toout[(size_t)b * KOUT + H3 + tid] = e;
        g_togru[(size_t)b * KGRU + tid] = fmaxf(e, 0.f);
    }
}

// ---------------- GRU gates ----------------
__global__ void gru_gates(const float* __restrict__ hidden, float* __restrict__ out_h) {
    int idx = blockIdx.x * 256 + threadIdx.x;
    int b = idx >> 9, h = idx & 511;
    const float* gi = g_gi + (size_t)b * H3;
    const float* gh = g_gh + (size_t)b * H3;
    float r = 1.f / (1.f + expf(-(gi[h] + gh[h])));
    float z = 1.f / (1.f + expf(-(gi[HH + h] + gh[HH + h])));
    float n = tanhf(gi[2 * HH + h] + r * gh[2 * HH + h]);
    float hp = hidden[b * HH + h];
    float hn = (1.f - z) * n + z * hp;
    g_toout[(size_t)b * KOUT + h] = hn;
    out_h[b * HH + h] = hn;
}

// ---------------- launch ----------------
extern "C" void kernel_launch(void* const* d_in, const int* in_sizes, int n_in,
                              void* d_out, int out_size) {
    const int*   x      = (const int*)d_in[0];
    const float* hidden = (const float*)d_in[1];
    const float* enc    = (const float*)d_in[2];
    const float* emb    = (const float*)d_in[3];
    const float* attn_w = (const float*)d_in[4];
    const float* attn_b = (const float*)d_in[5];
    const float* v      = (const float*)d_in[6];
    const float* w_ih   = (const float*)d_in[7];
    const float* w_hh   = (const float*)d_in[8];
    const float* b_ih   = (const float*)d_in[9];
    const float* b_hh   = (const float*)d_in[10];
    const float* out_w  = (const float*)d_in[11];
    const float* out_b  = (const float*)d_in[12];
    float* out = (float*)d_out;

    static float *p_togru = nullptr, *p_gi = nullptr, *p_gh = nullptr, *p_toout = nullptr;
    if (!p_togru) {
        cudaGetSymbolAddress((void**)&p_togru, g_togru);
        cudaGetSymbolAddress((void**)&p_gi, g_gi);
        cudaGetSymbolAddress((void**)&p_gh, g_gh);
        cudaGetSymbolAddress((void**)&p_toout, g_toout);
        cudaFuncSetAttribute(mma_gemm_big, cudaFuncAttributeMaxDynamicSharedMemorySize,
                             BIG_SMEM);
        cudaFuncSetAttribute(gru_gemm_fused, cudaFuncAttributeMaxDynamicSharedMemorySize,
                             SMALL_SMEM);
    }

    prep_kernel<<<7, 256>>>(attn_w, attn_b, v);
    attn_kernel<<<BB, 256>>>(hidden, enc, emb, x);

    bconv_kernel<<<(KGRU * 16 + 255) / 256, 256>>>(p_togru, KGRU, 0);
    bconv_kernel<<<(HH * 16 + 255) / 256, 256>>>(hidden, HH, KGRU / 64);

    gru_gemm_fused<<<96, 256, SMALL_SMEM>>>(w_ih, b_ih, p_gi, KGRU, KGRU / 64,
                                            w_hh, b_hh, p_gh, HH, HH / 64);

    gru_gates<<<(BB * HH) / 256, 256>>>(hidden, out + (size_t)BB * VV);

    bconv_kernel<<<(KOUT * 16 + 255) / 256, 256>>>(p_toout, KOUT, 0);
    mma_gemm_big<<<(VV + 127) / 128, 512, BIG_SMEM>>>(out_w, out_b, out, VV, KOUT,
                                                      KOUT / 64, VV);
}

// round 9
// speedup vs baseline: 2.0357x; 1.0717x over previous
#include <cuda_runtime.h>
#include <cuda_bf16.h>
#include <cstdint>

// Problem dims
#define HH   512
#define EE   256
#define VV   50000
#define BB   128
#define SS   200
#define H3   1536          // 3H
#define KGRU 1280          // 2H + E
#define KOUT 1792          // 3H + E

// ---------------- scratch ----------------
__device__ float g_u[H3];
__device__ float g_c0;
__device__ __align__(16) float g_togru[BB * KGRU];
__device__ __align__(16) float g_toout[BB * KOUT];
__device__ __align__(16) float g_gi[BB * H3];
__device__ __align__(16) float g_gh[BB * H3];
// pre-converted B (hi/lo), swizzled tile layout: [chunk][128 rows][128B]
__device__ uint4 g_bhi[28 * 1024];
__device__ uint4 g_blo[28 * 1024];

// ---------------- helpers ----------------
__device__ __forceinline__ uint32_t smem_u32(const void* p) {
    uint32_t a;
    asm("{ .reg .u64 t; cvta.to.shared.u64 t, %1; cvt.u32.u64 %0, t; }" : "=r"(a) : "l"(p));
    return a;
}
__device__ __forceinline__ uint32_t pkbf(__nv_bfloat16 a, __nv_bfloat16 b) {
    return (uint32_t)__bfloat16_as_ushort(a) | ((uint32_t)__bfloat16_as_ushort(b) << 16);
}
__device__ __forceinline__ void split2(float x, float y, uint32_t& hv, uint32_t& lv) {
    __nv_bfloat16 xh = __float2bfloat16(x);
    __nv_bfloat16 yh = __float2bfloat16(y);
    __nv_bfloat16 xl = __float2bfloat16(x - __bfloat162float(xh));
    __nv_bfloat16 yl = __float2bfloat16(y - __bfloat162float(yh));
    hv = pkbf(xh, yh);
    lv = pkbf(xl, yl);
}
__device__ __forceinline__ void split8(float4 f0, float4 f1, uint4& hv, uint4& lv) {
    split2(f0.x, f0.y, hv.x, lv.x);
    split2(f0.z, f0.w, hv.y, lv.y);
    split2(f1.x, f1.y, hv.z, lv.z);
    split2(f1.z, f1.w, hv.w, lv.w);
}
__device__ __forceinline__ void sts128(uint32_t addr, uint4 v) {
    asm volatile("st.shared.v4.b32 [%0], {%1,%2,%3,%4};"
                 :: "r"(addr), "r"(v.x), "r"(v.y), "r"(v.z), "r"(v.w) : "memory");
}
__device__ __forceinline__ float4 lds128f(uint32_t a) {
    float4 v;
    asm volatile("ld.shared.v4.f32 {%0,%1,%2,%3}, [%4];"
                 : "=f"(v.x), "=f"(v.y), "=f"(v.z), "=f"(v.w) : "r"(a));
    return v;
}
__device__ __forceinline__ void ldsm4(uint32_t (&r)[4], uint32_t addr) {
    asm volatile("ldmatrix.sync.aligned.m8n8.x4.shared.b16 {%0,%1,%2,%3}, [%4];"
                 : "=r"(r[0]), "=r"(r[1]), "=r"(r[2]), "=r"(r[3]) : "r"(addr));
}
__device__ __forceinline__ void mma16816(float (&d)[4], const uint32_t (&a)[4],
                                         uint32_t b0, uint32_t b1) {
    asm volatile(
        "mma.sync.aligned.m16n8k16.row.col.f32.bf16.bf16.f32 "
        "{%0,%1,%2,%3}, {%4,%5,%6,%7}, {%8,%9}, {%0,%1,%2,%3};"
        : "+f"(d[0]), "+f"(d[1]), "+f"(d[2]), "+f"(d[3])
        : "r"(a[0]), "r"(a[1]), "r"(a[2]), "r"(a[3]), "r"(b0), "r"(b1));
}
__device__ __forceinline__ void cpasync16(uint32_t dst, const void* src) {
    asm volatile("{ .reg .u64 g; cvta.to.global.u64 g, %1; "
                 "cp.async.cg.shared.global [%0], [g], 16; }"
                 :: "r"(dst), "l"(src) : "memory");
}
#define CP_COMMIT() asm volatile("cp.async.commit_group;" ::: "memory")
#define CP_WAIT1()  asm volatile("cp.async.wait_group 1;" ::: "memory")
#define CP_WAIT0()  asm volatile("cp.async.wait_group 0;" ::: "memory")

// ---------------- B pre-convert: fp32 [128][K] -> swizzled bf16 hi/lo chunk tiles ----------------
__global__ void bconv_kernel(const float* __restrict__ B, int K, int boff) {
    int idx = blockIdx.x * 256 + threadIdx.x;
    if (idx >= K * 16) return;                 // K/64 chunks * 128 rows * 8 granules
    int c = idx >> 10, r = (idx >> 3) & 127, g8 = idx & 7;
    const float4* src = reinterpret_cast<const float4*>(B + (size_t)r * K + c * 64 + g8 * 8);
    float4 f0 = src[0], f1 = src[1];
    uint4 hv, lv;
    split8(f0, f1, hv, lv);
    uint32_t off = (uint32_t)(boff + c) * 16384 + (uint32_t)r * 128 +
                   (((uint32_t)g8 * 16) ^ (((uint32_t)r & 7u) << 4));
    g_bhi[off >> 4] = hv;
    g_blo[off >> 4] = lv;
}

// ================= big logits GEMM: 512 threads, 16 warps (4M x 4N) =================
// C[n*ldc + m] = sum_k A[m*K+k] * B[n*K+k] + bias[m], N=128, MT=128.
// Hi/lo fragments hoisted once per k16: 8 LDSM.x4 feed 24 HMMA.
#define BIG_SMEM 131072

__global__ __launch_bounds__(512, 1)
void mma_gemm_big(const float* __restrict__ A, const float* __restrict__ bias,
                  float* __restrict__ C, int M, int K, int nchunk, int ldc) {
    extern __shared__ char smem[];
    const uint32_t sb = smem_u32(smem);
    const int tid = threadIdx.x, wid = tid >> 5, lane = tid & 31;
    const int warpM = wid & 3, warpN = wid >> 2;
    const int m0 = blockIdx.x * 128;

    // A staging: thread owns (row = tid>>2, quarter q = tid&3) -> 16 floats/chunk
    const int crow = tid >> 2, cq = tid & 3;
    const bool avalid = (m0 + crow) < M;
    const int srow = avalid ? (m0 + crow) : 0;
    const uint32_t rswz = ((uint32_t)crow & 7u) << 4;
    const float4* aq = reinterpret_cast<const float4*>(A + (size_t)srow * K) + cq * 4;

    // mma-side addressing
    const int l15 = lane & 15, lhi = lane >> 4;
    const uint32_t rowAoff = (uint32_t)(warpM * 32 + l15) * 128;
    const uint32_t xorA = (((uint32_t)(warpM * 32 + l15)) & 7u) << 4;
    const uint32_t rowBoff = (uint32_t)(warpN * 32 + l15) * 128;
    const uint32_t xorB = (((uint32_t)(warpN * 32 + l15)) & 7u) << 4;

    float acc[2][4][4];
    #pragma unroll
    for (int mt = 0; mt < 2; ++mt)
        #pragma unroll
        for (int na = 0; na < 4; ++na)
            #pragma unroll
            for (int q = 0; q < 4; ++q) acc[mt][na][q] = 0.f;

    float4 rA[4];

    auto issue_b = [&](int c, int slot) {
        const char* shi = (const char*)g_bhi + (size_t)c * 16384;
        const char* slo = (const char*)g_blo + (size_t)c * 16384;
        const uint32_t dhi = sb + 65536u + (uint32_t)slot * 32768u;
        const uint32_t dlo = dhi + 16384u;
        #pragma unroll
        for (int i = 0; i < 2; ++i) {
            uint32_t lin = (uint32_t)(tid + i * 512) * 16;
            cpasync16(dhi + lin, shi + lin);
            cpasync16(dlo + lin, slo + lin);
        }
    };
    auto convert_sts = [&](int st) {
        const uint32_t hb = sb + (uint32_t)st * 32768u + (uint32_t)crow * 128;
        const uint32_t lb = hb + 16384u;
        const uint32_t o0 = ((uint32_t)(cq * 32)) ^ rswz;
        const uint32_t o1 = ((uint32_t)(cq * 32 + 16)) ^ rswz;
        uint4 hv, lv;
        if (avalid) split8(rA[0], rA[1], hv, lv);
        else { hv = make_uint4(0, 0, 0, 0); lv = make_uint4(0, 0, 0, 0); }
        sts128(hb + o0, hv);
        sts128(lb + o0, lv);
        if (avalid) split8(rA[2], rA[3], hv, lv);
        else { hv = make_uint4(0, 0, 0, 0); lv = make_uint4(0, 0, 0, 0); }
        sts128(hb + o1, hv);
        sts128(lb + o1, lv);
    };

    // ---- prologue: B(0), tiles(0), LDG(1) ----
    #pragma unroll
    for (int i = 0; i < 4; ++i) rA[i] = aq[i];
    issue_b(0, 0);
    CP_COMMIT();
    convert_sts(0);
    if (nchunk > 1) {
        #pragma unroll
        for (int i = 0; i < 4; ++i) rA[i] = aq[16 + i];
    }

    for (int c = 0; c < nchunk; ++c) {
        CP_WAIT0();
        __syncthreads();                        // tiles(c) + B(c) visible everywhere
        if (c + 1 < nchunk) { issue_b(c + 1, (c + 1) & 1); CP_COMMIT(); }

        const uint32_t ahiB = sb + (uint32_t)(c & 1) * 32768u;
        const uint32_t aloB = ahiB + 16384u;
        const uint32_t bhiB = sb + 65536u + (uint32_t)(c & 1) * 32768u;
        const uint32_t bloB = bhiB + 16384u;
        #pragma unroll
        for (int k16 = 0; k16 < 4; ++k16) {
            const uint32_t kb = (uint32_t)(k16 * 32 + lhi * 16);
            const uint32_t kA = kb ^ xorA, kB = kb ^ xorB;
            uint32_t ah[2][4], al[2][4], bh[2][4], bl[2][4];
            ldsm4(ah[0], ahiB + rowAoff + kA);
            ldsm4(ah[1], ahiB + rowAoff + 2048 + kA);
            ldsm4(al[0], aloB + rowAoff + kA);
            ldsm4(al[1], aloB + rowAoff + 2048 + kA);
            ldsm4(bh[0], bhiB + rowBoff + kB);
            ldsm4(bh[1], bhiB + rowBoff + 2048 + kB);
            ldsm4(bl[0], bloB + rowBoff + kB);
            ldsm4(bl[1], bloB + rowBoff + 2048 + kB);
            #pragma unroll
            for (int mt = 0; mt < 2; ++mt)
                #pragma unroll
                for (int na = 0; na < 4; ++na) {
                    const uint32_t* bq = bh[na >> 1];
                    if (na & 1) mma16816(acc[mt][na], ah[mt], bq[1], bq[3]);
                    else        mma16816(acc[mt][na], ah[mt], bq[0], bq[2]);
                }
            #pragma unroll
            for (int mt = 0; mt < 2; ++mt)
                #pragma unroll
                for (int na = 0; na < 4; ++na) {
                    const uint32_t* bq = bl[na >> 1];
                    if (na & 1) mma16816(acc[mt][na], ah[mt], bq[1], bq[3]);
                    else        mma16816(acc[mt][na], ah[mt], bq[0], bq[2]);
                }
            #pragma unroll
            for (int mt = 0; mt < 2; ++mt)
                #pragma unroll
                for (int na = 0; na < 4; ++na) {
                    const uint32_t* bq = bh[na >> 1];
                    if (na & 1) mma16816(acc[mt][na], al[mt], bq[1], bq[3]);
                    else        mma16816(acc[mt][na], al[mt], bq[0], bq[2]);
                }
        }
        if (c + 1 < nchunk) {
            convert_sts((c + 1) & 1);
            if (c + 2 < nchunk) {
                #pragma unroll
                for (int i = 0; i < 4; ++i) rA[i] = aq[(c + 2) * 16 + i];
            }
        }
    }

    // ---- epilogue ----
    const int mrow = lane >> 2, ncol = (lane & 3) * 2;
    #pragma unroll
    for (int mt = 0; mt < 2; ++mt) {
        const int mb = m0 + warpM * 32 + mt * 16 + mrow;
        const bool v0 = mb < M, v1 = (mb + 8) < M;
        const float bv0 = v0 ? bias[mb] : 0.f;
        const float bv1 = v1 ? bias[mb + 8] : 0.f;
        #pragma unroll
        for (int na = 0; na < 4; ++na) {
            const int n = warpN * 32 + na * 8 + ncol;
            float* c0 = C + (size_t)n * ldc;
            float* c1 = C + (size_t)(n + 1) * ldc;
            if (v0) { c0[mb] = acc[mt][na][0] + bv0; c1[mb] = acc[mt][na][1] + bv0; }
            if (v1) { c0[mb + 8] = acc[mt][na][2] + bv1; c1[mb + 8] = acc[mt][na][3] + bv1; }
        }
    }
}

// ================= small GEMM body (MT=32), used by fused GRU launch =================
#define SMALL_SMEM 131072

__device__ __forceinline__
void gemm32_body(const float* __restrict__ A, const float* __restrict__ bias,
                 float* __restrict__ C, int M, int K, int nchunk, int ldc,
                 int boff, int m0, char* smem) {
    constexpr uint32_t AR = 8192, AT = 4096;
    const uint32_t sb = smem_u32(smem);
    const uint32_t o_ahi = 2 * AR, o_alo = 2 * AR + 2 * AT;
    const uint32_t o_bhi = 2 * AR + 4 * AT, o_blo = o_bhi + 49152;

    const int tid = threadIdx.x, wid = tid >> 5, lane = tid & 31;
    const int warpN = wid;  // WM=1, WN=8, NW=16

    const int crow = tid & 31, ch = (tid >> 5) & 1;
    const bool do_a = tid < 64;
    const bool avalid = do_a && (m0 + crow) < M;
    const int srow = ((m0 + crow) < M) ? (m0 + crow) : 0;
    const uint32_t rswz = ((uint32_t)crow & 7u) << 4;

    const int l15 = lane & 15, lhi = lane >> 4;
    const uint32_t rowAoff = (uint32_t)l15 * 128;
    const uint32_t xorA = (((uint32_t)l15) & 7u) << 4;
    const uint32_t rowBoff = (uint32_t)(warpN * 16 + l15) * 128;
    const uint32_t xorB = (((uint32_t)(warpN * 16 + l15)) & 7u) << 4;

    float acc[2][2][4];
    #pragma unroll
    for (int mt = 0; mt < 2; ++mt)
        #pragma unroll
        for (int na = 0; na < 2; ++na)
            #pragma unroll
            for (int q = 0; q < 4; ++q) acc[mt][na][q] = 0.f;

    auto issue_a = [&](int c) {
        if (!do_a) return;
        const uint32_t dst0 = sb + (uint32_t)(c & 1) * AR + (uint32_t)crow * 256;
        const float* src0 = A + (size_t)srow * K + c * 64;
        #pragma unroll
        for (int i = 0; i < 8; ++i) {
            uint32_t g = (uint32_t)(ch * 8 + i);
            cpasync16(dst0 + ((g << 4) ^ rswz), src0 + g * 4);
        }
    };
    auto issue_b = [&](int c, int slot) {
        const char* shi = (const char*)g_bhi + (size_t)(boff + c) * 16384;
        const char* slo = (const char*)g_blo + (size_t)(boff + c) * 16384;
        const uint32_t dhi = sb + o_bhi + (uint32_t)slot * 16384;
        const uint32_t dlo = sb + o_blo + (uint32_t)slot * 16384;
        #pragma unroll
        for (int i = 0; i < 4; ++i) {
            uint32_t lin = (uint32_t)(tid + i * 256) * 16;
            cpasync16(dhi + lin, shi + lin);
            cpasync16(dlo + lin, slo + lin);
        }
    };

    issue_a(0); issue_b(0, 0); CP_COMMIT();
    if (nchunk > 1) { issue_a(1); issue_b(1, 1); }
    CP_COMMIT();

    int bslot = 0, bslot2 = 2;
    for (int c = 0; c < nchunk; ++c) {
        CP_WAIT1();
        __syncthreads();
        const uint32_t stA = (uint32_t)(c & 1);
        if (do_a) {
            const uint32_t rbase = sb + stA * AR + (uint32_t)crow * 256;
            const uint32_t hbase = sb + o_ahi + stA * AT + (uint32_t)crow * 128;
            const uint32_t lbase = sb + o_alo + stA * AT + (uint32_t)crow * 128;
            #pragma unroll
            for (int j = 0; j < 4; ++j) {
                uint32_t g0 = (uint32_t)(ch * 8 + 2 * j);
                float4 f0 = lds128f(rbase + ((g0 << 4) ^ rswz));
                float4 f1 = lds128f(rbase + (((g0 + 1) << 4) ^ rswz));
                uint4 hv, lv;
                if (avalid) split8(f0, f1, hv, lv);
                else { hv = make_uint4(0, 0, 0, 0); lv = make_uint4(0, 0, 0, 0); }
                uint32_t toff = ((uint32_t)(ch * 64 + j * 16)) ^ rswz;
                sts128(hbase + toff, hv);
                sts128(lbase + toff, lv);
            }
        }
        if (c + 2 < nchunk) { issue_a(c + 2); issue_b(c + 2, bslot2); }
        CP_COMMIT();
        __syncthreads();
        const uint32_t ahiB = sb + o_ahi + stA * AT;
        const uint32_t aloB = sb + o_alo + stA * AT;
        const uint32_t bhiB = sb + o_bhi + (uint32_t)bslot * 16384;
        const uint32_t bloB = sb + o_blo + (uint32_t)bslot * 16384;
        #pragma unroll
        for (int k16 = 0; k16 < 4; ++k16) {
            const uint32_t kb = (uint32_t)(k16 * 32 + lhi * 16);
            const uint32_t kA = kb ^ xorA, kB = kb ^ xorB;
            uint32_t ah[2][4], al[2][4], bh[4], bl[4];
            ldsm4(ah[0], ahiB + rowAoff + kA);
            ldsm4(ah[1], ahiB + rowAoff + 2048 + kA);
            ldsm4(al[0], aloB + rowAoff + kA);
            ldsm4(al[1], aloB + rowAoff + 2048 + kA);
            ldsm4(bh, bhiB + rowBoff + kB);
            ldsm4(bl, bloB + rowBoff + kB);
            #pragma unroll
            for (int mt = 0; mt < 2; ++mt) {
                mma16816(acc[mt][0], ah[mt], bh[0], bh[2]);
                mma16816(acc[mt][1], ah[mt], bh[1], bh[3]);
            }
            #pragma unroll
            for (int mt = 0; mt < 2; ++mt) {
                mma16816(acc[mt][0], ah[mt], bl[0], bl[2]);
                mma16816(acc[mt][1], ah[mt], bl[1], bl[3]);
            }
            #pragma unroll
            for (int mt = 0; mt < 2; ++mt) {
                mma16816(acc[mt][0], al[mt], bh[0], bh[2]);
                mma16816(acc[mt][1], al[mt], bh[1], bh[3]);
            }
        }
        bslot = (bslot == 2) ? 0 : bslot + 1;
        bslot2 = (bslot2 == 2) ? 0 : bslot2 + 1;
    }
    CP_WAIT0();

    const int mrow = lane >> 2, ncol = (lane & 3) * 2;
    #pragma unroll
    for (int mt = 0; mt < 2; ++mt) {
        const int mb = m0 + mt * 16 + mrow;
        const bool v0 = mb < M, v1 = (mb + 8) < M;
        const float bv0 = v0 ? bias[mb] : 0.f;
        const float bv1 = v1 ? bias[mb + 8] : 0.f;
        #pragma unroll
        for (int na = 0; na < 2; ++na) {
            const int n = warpN * 16 + na * 8 + ncol;
            float* c0 = C + (size_t)n * ldc;
            float* c1 = C + (size_t)(n + 1) * ldc;
            if (v0) { c0[mb] = acc[mt][na][0] + bv0; c1[mb] = acc[mt][na][1] + bv0; }
            if (v1) { c0[mb + 8] = acc[mt][na][2] + bv1; c1[mb + 8] = acc[mt][na][3] + bv1; }
        }
    }
}

__global__ __launch_bounds__(256, 1)
void gru_gemm_fused(const float* __restrict__ A1, const float* __restrict__ b1,
                    float* __restrict__ C1, int K1, int nc1,
                    const float* __restrict__ A2, const float* __restrict__ b2,
                    float* __restrict__ C2, int K2, int nc2) {
    extern __shared__ char smem[];
    if (blockIdx.x < 48)
        gemm32_body(A1, b1, C1, H3, K1, nc1, H3, 0, blockIdx.x * 32, smem);
    else
        gemm32_body(A2, b2, C2, H3, K2, nc2, H3, nc1, (blockIdx.x - 48) * 32, smem);
}

// ---------------- kernel 1: u = attn_w^T v, c0 = attn_b.v ----------------
__global__ void prep_kernel(const float* __restrict__ attn_w,
                            const float* __restrict__ attn_b,
                            const float* __restrict__ v) {
    int j = blockIdx.x * blockDim.x + threadIdx.x;
    if (j < H3) {
        float s = 0.f;
        #pragma unroll 8
        for (int h = 0; h < HH; ++h) s += attn_w[h * H3 + j] * v[h];
        g_u[j] = s;
    } else if (j == H3) {
        float s = 0.f;
        for (int h = 0; h < HH; ++h) s += attn_b[h] * v[h];
        g_c0 = s;
    }
}

// ---------------- kernel 2: scores + softmax + context (512 threads) ----------------
__global__ __launch_bounds__(512)
void attn_kernel(const float* __restrict__ hidden,
                 const float* __restrict__ enc,
                 const float* __restrict__ emb,
                 const int* __restrict__ x) {
    __shared__ float s_u[2 * HH];
    __shared__ float s_p[256];
    __shared__ float s_red[16];
    __shared__ float s_constb, s_max, s_sum;

    const int b = blockIdx.x;
    const int tid = threadIdx.x;
    const int lane = tid & 31, wid = tid >> 5;

    for (int j = tid; j < 2 * HH; j += 512) s_u[j] = g_u[HH + j];

    // const_b = h0[b].u[0:512] + c0  (512 threads, one element each)
    float p = hidden[b * HH + tid % HH] * g_u[tid % HH];
    if (tid >= HH) p = 0.f;
    for (int o = 16; o; o >>= 1) p += __shfl_xor_sync(~0u, p, o);
    if (lane == 0) s_red[wid] = p;
    __syncthreads();
    if (tid == 0) {
        float s = g_c0;
        for (int w = 0; w < 16; ++w) s += s_red[w];
        s_constb = s;
    }
    __syncthreads();
    const float cb = s_constb;

    // scores: warp per row, 16 warps
    const float4* enc4 = reinterpret_cast<const float4*>(enc) + (size_t)b * SS * 256;
    const float4* u4 = reinterpret_cast<const float4*>(s_u);
    for (int s = wid; s < SS; s += 16) {
        const float4* row = enc4 + (size_t)s * 256;
        float acc = 0.f;
        #pragma unroll
        for (int t = 0; t < 8; ++t) {
            float4 e = row[lane + 32 * t];
            float4 u = u4[lane + 32 * t];
            acc += e.x * u.x + e.y * u.y + e.z * u.z + e.w * u.w;
        }
        for (int o = 16; o; o >>= 1) acc += __shfl_xor_sync(~0u, acc, o);
        if (lane == 0) s_p[s] = acc + cb;
    }
    __syncthreads();

    float m = -1e30f;
    for (int s = tid; s < SS; s += 512) m = fmaxf(m, s_p[s]);
    for (int o = 16; o; o >>= 1) m = fmaxf(m, __shfl_xor_sync(~0u, m, o));
    if (lane == 0) s_red[wid] = m;
    __syncthreads();
    if (tid == 0) {
        float mm = -1e30f;
        for (int w = 0; w < 16; ++w) mm = fmaxf(mm, s_red[w]);
        s_max = mm;
    }
    __syncthreads();
    const float mm2 = s_max;
    float sum = 0.f;
    for (int s = tid; s < SS; s += 512) {
        float e = expf(s_p[s] - mm2);
        s_p[s] = e;
        sum += e;
    }
    for (int o = 16; o; o >>= 1) sum += __shfl_xor_sync(~0u, sum, o);
    if (lane == 0) s_red[wid] = sum;
    __syncthreads();
    if (tid == 0) {
        float t = 0.f;
        for (int w = 0; w < 16; ++w) t += s_red[w];
        s_sum = 1.f / t;
    }
    __syncthreads();
    const float inv = s_sum;

    // context: thread owns float2 lane (1024 dims / 512 threads)
    float2 acc = make_float2(0.f, 0.f);
    const float2* col = reinterpret_cast<const float2*>(enc) + (size_t)b * SS * 512 + tid;
    #pragma unroll 4
    for (int s = 0; s < SS; ++s) {
        float ps = s_p[s];
        float2 e = col[(size_t)s * 512];
        acc.x += ps * e.x; acc.y += ps * e.y;
    }
    acc.x *= inv; acc.y *= inv;

    const int d = tid * 2;
    *reinterpret_cast<float2*>(g_toout + (size_t)b * KOUT + HH + d) = acc;
    float2 rc = make_float2(fmaxf(acc.x, 0.f), fmaxf(acc.y, 0.f));
    *reinterpret_cast<float2*>(g_togru + (size_t)b * KGRU + EE + d) = rc;

    if (tid < EE) {
        float e = emb[(size_t)x[b] * EE + tid];
        g_toout[(size_t)b * KOUT + H3 + tid] = e;
        g_togru[(size_t)b * KGRU + tid] = fmaxf(e, 0.f);
    }
}

// ---------------- GRU gates ----------------
__global__ void gru_gates(const float* __restrict__ hidden, float* __restrict__ out_h) {
    int idx = blockIdx.x * 256 + threadIdx.x;
    int b = idx >> 9, h = idx & 511;
    const float* gi = g_gi + (size_t)b * H3;
    const float* gh = g_gh + (size_t)b * H3;
    float r = 1.f / (1.f + expf(-(gi[h] + gh[h])));
    float z = 1.f / (1.f + expf(-(gi[HH + h] + gh[HH + h])));
    float n = tanhf(gi[2 * HH + h] + r * gh[2 * HH + h]);
    float hp = hidden[b * HH + h];
    float hn = (1.f - z) * n + z * hp;
    g_toout[(size_t)b * KOUT + h] = hn;
    out_h[b * HH + h] = hn;
}

// ---------------- launch ----------------
extern "C" void kernel_launch(void* const* d_in, const int* in_sizes, int n_in,
                              void* d_out, int out_size) {
    const int*   x      = (const int*)d_in[0];
    const float* hidden = (const float*)d_in[1];
    const float* enc    = (const float*)d_in[2];
    const float* emb    = (const float*)d_in[3];
    const float* attn_w = (const float*)d_in[4];
    const float* attn_b = (const float*)d_in[5];
    const float* v      = (const float*)d_in[6];
    const float* w_ih   = (const float*)d_in[7];
    const float* w_hh   = (const float*)d_in[8];
    const float* b_ih   = (const float*)d_in[9];
    const float* b_hh   = (const float*)d_in[10];
    const float* out_w  = (const float*)d_in[11];
    const float* out_b  = (const float*)d_in[12];
    float* out = (float*)d_out;

    static float *p_togru = nullptr, *p_gi = nullptr, *p_gh = nullptr, *p_toout = nullptr;
    if (!p_togru) {
        cudaGetSymbolAddress((void**)&p_togru, g_togru);
        cudaGetSymbolAddress((void**)&p_gi, g_gi);
        cudaGetSymbolAddress((void**)&p_gh, g_gh);
        cudaGetSymbolAddress((void**)&p_toout, g_toout);
        cudaFuncSetAttribute(mma_gemm_big, cudaFuncAttributeMaxDynamicSharedMemorySize,
                             BIG_SMEM);
        cudaFuncSetAttribute(gru_gemm_fused, cudaFuncAttributeMaxDynamicSharedMemorySize,
                             SMALL_SMEM);
    }

    prep_kernel<<<7, 256>>>(attn_w, attn_b, v);
    attn_kernel<<<BB, 512>>>(hidden, enc, emb, x);

    bconv_kernel<<<(KGRU * 16 + 255) / 256, 256>>>(p_togru, KGRU, 0);
    bconv_kernel<<<(HH * 16 + 255) / 256, 256>>>(hidden, HH, KGRU / 64);

    gru_gemm_fused<<<96, 256, SMALL_SMEM>>>(w_ih, b_ih, p_gi, KGRU, KGRU / 64,
                                            w_hh, b_hh, p_gh, HH, HH / 64);

    gru_gates<<<(BB * HH) / 256, 256>>>(hidden, out + (size_t)BB * VV);

    bconv_kernel<<<(KOUT * 16 + 255) / 256, 256>>>(p_toout, KOUT, 0);
    mma_gemm_big<<<(VV + 127) / 128, 512, BIG_SMEM>>>(out_w, out_b, out, VV, KOUT,
                                                      KOUT / 64, VV);
}

// round 10
// speedup vs baseline: 2.1106x; 1.0368x over previous
#include <cuda_runtime.h>
#include <cuda_bf16.h>
#include <cstdint>

// Problem dims
#define HH   512
#define EE   256
#define VV   50000
#define BB   128
#define SS   200
#define H3   1536          // 3H
#define KGRU 1280          // 2H + E
#define KOUT 1792          // 3H + E

// ---------------- scratch ----------------
__device__ float g_u[H3];
__device__ float g_c0;
__device__ __align__(16) float g_togru[BB * KGRU];
__device__ __align__(16) float g_toout[BB * KOUT];   // [unused 0:512 | context | emb]
__device__ __align__(16) float g_gi[BB * H3];
__device__ __align__(16) float g_gh[BB * H3];
// pre-converted B (hi/lo), swizzled tile layout: [chunk][128 rows][128B]
__device__ uint4 g_bhi[28 * 1024];
__device__ uint4 g_blo[28 * 1024];

// ---------------- helpers ----------------
__device__ __forceinline__ uint32_t smem_u32(const void* p) {
    uint32_t a;
    asm("{ .reg .u64 t; cvta.to.shared.u64 t, %1; cvt.u32.u64 %0, t; }" : "=r"(a) : "l"(p));
    return a;
}
// fast split: hv = {bf16(x) lo, bf16(y) hi}, lv = residuals, identical rounding to
// __float2bfloat16 (rn). 6 instrs per 2 elems.
__device__ __forceinline__ void split2(float x, float y, uint32_t& hv, uint32_t& lv) {
    uint32_t h;
    asm("cvt.rn.bf16x2.f32 %0, %1, %2;" : "=r"(h) : "f"(y), "f"(x));
    float hx = __uint_as_float(h << 16);
    float hy = __uint_as_float(h & 0xFFFF0000u);
    float lx = x - hx, ly = y - hy;
    uint32_t l;
    asm("cvt.rn.bf16x2.f32 %0, %1, %2;" : "=r"(l) : "f"(ly), "f"(lx));
    hv = h; lv = l;
}
__device__ __forceinline__ void split8(float4 f0, float4 f1, uint4& hv, uint4& lv) {
    split2(f0.x, f0.y, hv.x, lv.x);
    split2(f0.z, f0.w, hv.y, lv.y);
    split2(f1.x, f1.y, hv.z, lv.z);
    split2(f1.z, f1.w, hv.w, lv.w);
}
__device__ __forceinline__ void sts128(uint32_t addr, uint4 v) {
    asm volatile("st.shared.v4.b32 [%0], {%1,%2,%3,%4};"
                 :: "r"(addr), "r"(v.x), "r"(v.y), "r"(v.z), "r"(v.w) : "memory");
}
__device__ __forceinline__ float4 lds128f(uint32_t a) {
    float4 v;
    asm volatile("ld.shared.v4.f32 {%0,%1,%2,%3}, [%4];"
                 : "=f"(v.x), "=f"(v.y), "=f"(v.z), "=f"(v.w) : "r"(a));
    return v;
}
__device__ __forceinline__ void ldsm4(uint32_t (&r)[4], uint32_t addr) {
    asm volatile("ldmatrix.sync.aligned.m8n8.x4.shared.b16 {%0,%1,%2,%3}, [%4];"
                 : "=r"(r[0]), "=r"(r[1]), "=r"(r[2]), "=r"(r[3]) : "r"(addr));
}
__device__ __forceinline__ void mma16816(float (&d)[4], const uint32_t (&a)[4],
                                         uint32_t b0, uint32_t b1) {
    asm volatile(
        "mma.sync.aligned.m16n8k16.row.col.f32.bf16.bf16.f32 "
        "{%0,%1,%2,%3}, {%4,%5,%6,%7}, {%8,%9}, {%0,%1,%2,%3};"
        : "+f"(d[0]), "+f"(d[1]), "+f"(d[2]), "+f"(d[3])
        : "r"(a[0]), "r"(a[1]), "r"(a[2]), "r"(a[3]), "r"(b0), "r"(b1));
}
__device__ __forceinline__ void cpasync16(uint32_t dst, const void* src) {
    asm volatile("{ .reg .u64 g; cvta.to.global.u64 g, %1; "
                 "cp.async.cg.shared.global [%0], [g], 16; }"
                 :: "r"(dst), "l"(src) : "memory");
}
#define CP_COMMIT() asm volatile("cp.async.commit_group;" ::: "memory")
#define CP_WAIT1()  asm volatile("cp.async.wait_group 1;" ::: "memory")
#define CP_WAIT0()  asm volatile("cp.async.wait_group 0;" ::: "memory")

// ---------------- B convert core: 8 floats -> swizzled hi/lo granule ----------------
__device__ __forceinline__ void bconv_store(int chunk, int r, int g8, float4 f0, float4 f1) {
    uint4 hv, lv;
    split8(f0, f1, hv, lv);
    uint32_t off = (uint32_t)chunk * 16384 + (uint32_t)r * 128 +
                   (((uint32_t)g8 * 16) ^ (((uint32_t)r & 7u) << 4));
    g_bhi[off >> 4] = hv;
    g_blo[off >> 4] = lv;
}

// merged GRU B convert: togru (20 chunks, boff 0) + hidden (8 chunks, boff 20)
__global__ void bconv_gru(const float* __restrict__ togru, const float* __restrict__ hidden) {
    int idx = blockIdx.x * 256 + threadIdx.x;
    if (idx < KGRU * 16) {
        int c = idx >> 10, r = (idx >> 3) & 127, g8 = idx & 7;
        const float4* src = reinterpret_cast<const float4*>(togru + (size_t)r * KGRU + c * 64 + g8 * 8);
        bconv_store(c, r, g8, src[0], src[1]);
    } else {
        idx -= KGRU * 16;
        if (idx >= HH * 16) return;
        int c = idx >> 10, r = (idx >> 3) & 127, g8 = idx & 7;
        const float4* src = reinterpret_cast<const float4*>(hidden + (size_t)r * HH + c * 64 + g8 * 8);
        bconv_store(KGRU / 64 + c, r, g8, src[0], src[1]);
    }
}

// fused GRU gates + logits-B convert: chunks c<8 compute h_new from gi/gh directly
// (also writing out_h); chunks c>=8 convert toout (context|emb) as before.
__global__ void bconv_out_gates(const float* __restrict__ hidden, float* __restrict__ out_h) {
    int idx = blockIdx.x * 256 + threadIdx.x;
    if (idx >= KOUT * 16) return;
    int c = idx >> 10, r = (idx >> 3) & 127, g8 = idx & 7;
    int k0 = c * 64 + g8 * 8;
    float4 f0, f1;
    if (c < 8) {
        float v[8];
        const float* gi = g_gi + (size_t)r * H3 + k0;
        const float* gh = g_gh + (size_t)r * H3 + k0;
        const float* hp = hidden + (size_t)r * HH + k0;
        #pragma unroll
        for (int i = 0; i < 8; ++i) {
            float rr = 1.f / (1.f + expf(-(gi[i] + gh[i])));
            float zz = 1.f / (1.f + expf(-(gi[HH + i] + gh[HH + i])));
            float nn = tanhf(gi[2 * HH + i] + rr * gh[2 * HH + i]);
            v[i] = (1.f - zz) * nn + zz * hp[i];
        }
        f0 = make_float4(v[0], v[1], v[2], v[3]);
        f1 = make_float4(v[4], v[5], v[6], v[7]);
        *reinterpret_cast<float4*>(out_h + (size_t)r * HH + k0) = f0;
        *reinterpret_cast<float4*>(out_h + (size_t)r * HH + k0 + 4) = f1;
    } else {
        const float4* src = reinterpret_cast<const float4*>(g_toout + (size_t)r * KOUT + k0);
        f0 = src[0];
        f1 = src[1];
    }
    bconv_store(c, r, g8, f0, f1);
}

// ================= big logits GEMM: 512 threads, 16 warps (4M x 4N) =================
#define BIG_SMEM 131072

__global__ __launch_bounds__(512, 1)
void mma_gemm_big(const float* __restrict__ A, const float* __restrict__ bias,
                  float* __restrict__ C, int M, int K, int nchunk, int ldc) {
    extern __shared__ char smem[];
    const uint32_t sb = smem_u32(smem);
    const int tid = threadIdx.x, wid = tid >> 5, lane = tid & 31;
    const int warpM = wid & 3, warpN = wid >> 2;
    const int m0 = blockIdx.x * 128;

    const int crow = tid >> 2, cq = tid & 3;
    const bool avalid = (m0 + crow) < M;
    const int srow = avalid ? (m0 + crow) : 0;
    const uint32_t rswz = ((uint32_t)crow & 7u) << 4;
    const float4* aq = reinterpret_cast<const float4*>(A + (size_t)srow * K) + cq * 4;

    const int l15 = lane & 15, lhi = lane >> 4;
    const uint32_t rowAoff = (uint32_t)(warpM * 32 + l15) * 128;
    const uint32_t xorA = (((uint32_t)(warpM * 32 + l15)) & 7u) << 4;
    const uint32_t rowBoff = (uint32_t)(warpN * 32 + l15) * 128;
    const uint32_t xorB = (((uint32_t)(warpN * 32 + l15)) & 7u) << 4;

    float acc[2][4][4];
    #pragma unroll
    for (int mt = 0; mt < 2; ++mt)
        #pragma unroll
        for (int na = 0; na < 4; ++na)
            #pragma unroll
            for (int q = 0; q < 4; ++q) acc[mt][na][q] = 0.f;

    float4 rA[4];

    auto issue_b = [&](int c, int slot) {
        const char* shi = (const char*)g_bhi + (size_t)c * 16384;
        const char* slo = (const char*)g_blo + (size_t)c * 16384;
        const uint32_t dhi = sb + 65536u + (uint32_t)slot * 32768u;
        const uint32_t dlo = dhi + 16384u;
        #pragma unroll
        for (int i = 0; i < 2; ++i) {
            uint32_t lin = (uint32_t)(tid + i * 512) * 16;
            cpasync16(dhi + lin, shi + lin);
            cpasync16(dlo + lin, slo + lin);
        }
    };
    auto convert_sts = [&](int st) {
        const uint32_t hb = sb + (uint32_t)st * 32768u + (uint32_t)crow * 128;
        const uint32_t lb = hb + 16384u;
        const uint32_t o0 = ((uint32_t)(cq * 32)) ^ rswz;
        const uint32_t o1 = ((uint32_t)(cq * 32 + 16)) ^ rswz;
        uint4 hv, lv;
        if (avalid) split8(rA[0], rA[1], hv, lv);
        else { hv = make_uint4(0, 0, 0, 0); lv = make_uint4(0, 0, 0, 0); }
        sts128(hb + o0, hv);
        sts128(lb + o0, lv);
        if (avalid) split8(rA[2], rA[3], hv, lv);
        else { hv = make_uint4(0, 0, 0, 0); lv = make_uint4(0, 0, 0, 0); }
        sts128(hb + o1, hv);
        sts128(lb + o1, lv);
    };

    #pragma unroll
    for (int i = 0; i < 4; ++i) rA[i] = aq[i];
    issue_b(0, 0);
    CP_COMMIT();
    convert_sts(0);
    if (nchunk > 1) {
        #pragma unroll
        for (int i = 0; i < 4; ++i) rA[i] = aq[16 + i];
    }

    for (int c = 0; c < nchunk; ++c) {
        CP_WAIT0();
        __syncthreads();
        if (c + 1 < nchunk) { issue_b(c + 1, (c + 1) & 1); CP_COMMIT(); }

        const uint32_t ahiB = sb + (uint32_t)(c & 1) * 32768u;
        const uint32_t aloB = ahiB + 16384u;
        const uint32_t bhiB = sb + 65536u + (uint32_t)(c & 1) * 32768u;
        const uint32_t bloB = bhiB + 16384u;
        #pragma unroll
        for (int k16 = 0; k16 < 4; ++k16) {
            const uint32_t kb = (uint32_t)(k16 * 32 + lhi * 16);
            const uint32_t kA = kb ^ xorA, kB = kb ^ xorB;
            uint32_t ah[2][4], al[2][4], bh[2][4], bl[2][4];
            ldsm4(ah[0], ahiB + rowAoff + kA);
            ldsm4(ah[1], ahiB + rowAoff + 2048 + kA);
            ldsm4(al[0], aloB + rowAoff + kA);
            ldsm4(al[1], aloB + rowAoff + 2048 + kA);
            ldsm4(bh[0], bhiB + rowBoff + kB);
            ldsm4(bh[1], bhiB + rowBoff + 2048 + kB);
            ldsm4(bl[0], bloB + rowBoff + kB);
            ldsm4(bl[1], bloB + rowBoff + 2048 + kB);
            #pragma unroll
            for (int mt = 0; mt < 2; ++mt)
                #pragma unroll
                for (int na = 0; na < 4; ++na) {
                    const uint32_t* bq = bh[na >> 1];
                    if (na & 1) mma16816(acc[mt][na], ah[mt], bq[1], bq[3]);
                    else        mma16816(acc[mt][na], ah[mt], bq[0], bq[2]);
                }
            #pragma unroll
            for (int mt = 0; mt < 2; ++mt)
                #pragma unroll
                for (int na = 0; na < 4; ++na) {
                    const uint32_t* bq = bl[na >> 1];
                    if (na & 1) mma16816(acc[mt][na], ah[mt], bq[1], bq[3]);
                    else        mma16816(acc[mt][na], ah[mt], bq[0], bq[2]);
                }
            #pragma unroll
            for (int mt = 0; mt < 2; ++mt)
                #pragma unroll
                for (int na = 0; na < 4; ++na) {
                    const uint32_t* bq = bh[na >> 1];
                    if (na & 1) mma16816(acc[mt][na], al[mt], bq[1], bq[3]);
                    else        mma16816(acc[mt][na], al[mt], bq[0], bq[2]);
                }
        }
        if (c + 1 < nchunk) {
            convert_sts((c + 1) & 1);
            if (c + 2 < nchunk) {
                #pragma unroll
                for (int i = 0; i < 4; ++i) rA[i] = aq[(c + 2) * 16 + i];
            }
        }
    }

    const int mrow = lane >> 2, ncol = (lane & 3) * 2;
    #pragma unroll
    for (int mt = 0; mt < 2; ++mt) {
        const int mb = m0 + warpM * 32 + mt * 16 + mrow;
        const bool v0 = mb < M, v1 = (mb + 8) < M;
        const float bv0 = v0 ? bias[mb] : 0.f;
        const float bv1 = v1 ? bias[mb + 8] : 0.f;
        #pragma unroll
        for (int na = 0; na < 4; ++na) {
            const int n = warpN * 32 + na * 8 + ncol;
            float* c0 = C + (size_t)n * ldc;
            float* c1 = C + (size_t)(n + 1) * ldc;
            if (v0) { c0[mb] = acc[mt][na][0] + bv0; c1[mb] = acc[mt][na][1] + bv0; }
            if (v1) { c0[mb + 8] = acc[mt][na][2] + bv1; c1[mb + 8] = acc[mt][na][3] + bv1; }
        }
    }
}

// ================= small GEMM body (MT=32), used by fused GRU launch =================
#define SMALL_SMEM 131072

__device__ __forceinline__
void gemm32_body(const float* __restrict__ A, const float* __restrict__ bias,
                 float* __restrict__ C, int M, int K, int nchunk, int ldc,
                 int boff, int m0, char* smem) {
    constexpr uint32_t AR = 8192, AT = 4096;
    const uint32_t sb = smem_u32(smem);
    const uint32_t o_ahi = 2 * AR, o_alo = 2 * AR + 2 * AT;
    const uint32_t o_bhi = 2 * AR + 4 * AT, o_blo = o_bhi + 49152;

    const int tid = threadIdx.x, wid = tid >> 5, lane = tid & 31;
    const int warpN = wid;

    const int crow = tid & 31, ch = (tid >> 5) & 1;
    const bool do_a = tid < 64;
    const bool avalid = do_a && (m0 + crow) < M;
    const int srow = ((m0 + crow) < M) ? (m0 + crow) : 0;
    const uint32_t rswz = ((uint32_t)crow & 7u) << 4;

    const int l15 = lane & 15, lhi = lane >> 4;
    const uint32_t rowAoff = (uint32_t)l15 * 128;
    const uint32_t xorA = (((uint32_t)l15) & 7u) << 4;
    const uint32_t rowBoff = (uint32_t)(warpN * 16 + l15) * 128;
    const uint32_t xorB = (((uint32_t)(warpN * 16 + l15)) & 7u) << 4;

    float acc[2][2][4];
    #pragma unroll
    for (int mt = 0; mt < 2; ++mt)
        #pragma unroll
        for (int na = 0; na < 2; ++na)
            #pragma unroll
            for (int q = 0; q < 4; ++q) acc[mt][na][q] = 0.f;

    auto issue_a = [&](int c) {
        if (!do_a) return;
        const uint32_t dst0 = sb + (uint32_t)(c & 1) * AR + (uint32_t)crow * 256;
        const float* src0 = A + (size_t)srow * K + c * 64;
        #pragma unroll
        for (int i = 0; i < 8; ++i) {
            uint32_t g = (uint32_t)(ch * 8 + i);
            cpasync16(dst0 + ((g << 4) ^ rswz), src0 + g * 4);
        }
    };
    auto issue_b = [&](int c, int slot) {
        const char* shi = (const char*)g_bhi + (size_t)(boff + c) * 16384;
        const char* slo = (const char*)g_blo + (size_t)(boff + c) * 16384;
        const uint32_t dhi = sb + o_bhi + (uint32_t)slot * 16384;
        const uint32_t dlo = sb + o_blo + (uint32_t)slot * 16384;
        #pragma unroll
        for (int i = 0; i < 4; ++i) {
            uint32_t lin = (uint32_t)(tid + i * 256) * 16;
            cpasync16(dhi + lin, shi + lin);
            cpasync16(dlo + lin, slo + lin);
        }
    };

    issue_a(0); issue_b(0, 0); CP_COMMIT();
    if (nchunk > 1) { issue_a(1); issue_b(1, 1); }
    CP_COMMIT();

    int bslot = 0, bslot2 = 2;
    for (int c = 0; c < nchunk; ++c) {
        CP_WAIT1();
        __syncthreads();
        const uint32_t stA = (uint32_t)(c & 1);
        if (do_a) {
            const uint32_t rbase = sb + stA * AR + (uint32_t)crow * 256;
            const uint32_t hbase = sb + o_ahi + stA * AT + (uint32_t)crow * 128;
            const uint32_t lbase = sb + o_alo + stA * AT + (uint32_t)crow * 128;
            #pragma unroll
            for (int j = 0; j < 4; ++j) {
                uint32_t g0 = (uint32_t)(ch * 8 + 2 * j);
                float4 f0 = lds128f(rbase + ((g0 << 4) ^ rswz));
                float4 f1 = lds128f(rbase + (((g0 + 1) << 4) ^ rswz));
                uint4 hv, lv;
                if (avalid) split8(f0, f1, hv, lv);
                else { hv = make_uint4(0, 0, 0, 0); lv = make_uint4(0, 0, 0, 0); }
                uint32_t toff = ((uint32_t)(ch * 64 + j * 16)) ^ rswz;
                sts128(hbase + toff, hv);
                sts128(lbase + toff, lv);
            }
        }
        if (c + 2 < nchunk) { issue_a(c + 2); issue_b(c + 2, bslot2); }
        CP_COMMIT();
        __syncthreads();
        const uint32_t ahiB = sb + o_ahi + stA * AT;
        const uint32_t aloB = sb + o_alo + stA * AT;
        const uint32_t bhiB = sb + o_bhi + (uint32_t)bslot * 16384;
        const uint32_t bloB = sb + o_blo + (uint32_t)bslot * 16384;
        #pragma unroll
        for (int k16 = 0; k16 < 4; ++k16) {
            const uint32_t kb = (uint32_t)(k16 * 32 + lhi * 16);
            const uint32_t kA = kb ^ xorA, kB = kb ^ xorB;
            uint32_t ah[2][4], al[2][4], bh[4], bl[4];
            ldsm4(ah[0], ahiB + rowAoff + kA);
            ldsm4(ah[1], ahiB + rowAoff + 2048 + kA);
            ldsm4(al[0], aloB + rowAoff + kA);
            ldsm4(al[1], aloB + rowAoff + 2048 + kA);
            ldsm4(bh, bhiB + rowBoff + kB);
            ldsm4(bl, bloB + rowBoff + kB);
            #pragma unroll
            for (int mt = 0; mt < 2; ++mt) {
                mma16816(acc[mt][0], ah[mt], bh[0], bh[2]);
                mma16816(acc[mt][1], ah[mt], bh[1], bh[3]);
            }
            #pragma unroll
            for (int mt = 0; mt < 2; ++mt) {
                mma16816(acc[mt][0], ah[mt], bl[0], bl[2]);
                mma16816(acc[mt][1], ah[mt], bl[1], bl[3]);
            }
            #pragma unroll
            for (int mt = 0; mt < 2; ++mt) {
                mma16816(acc[mt][0], al[mt], bh[0], bh[2]);
                mma16816(acc[mt][1], al[mt], bh[1], bh[3]);
            }
        }
        bslot = (bslot == 2) ? 0 : bslot + 1;
        bslot2 = (bslot2 == 2) ? 0 : bslot2 + 1;
    }
    CP_WAIT0();

    const int mrow = lane >> 2, ncol = (lane & 3) * 2;
    #pragma unroll
    for (int mt = 0; mt < 2; ++mt) {
        const int mb = m0 + mt * 16 + mrow;
        const bool v0 = mb < M, v1 = (mb + 8) < M;
        const float bv0 = v0 ? bias[mb] : 0.f;
        const float bv1 = v1 ? bias[mb + 8] : 0.f;
        #pragma unroll
        for (int na = 0; na < 2; ++na) {
            const int n = warpN * 16 + na * 8 + ncol;
            float* c0 = C + (size_t)n * ldc;
            float* c1 = C + (size_t)(n + 1) * ldc;
            if (v0) { c0[mb] = acc[mt][na][0] + bv0; c1[mb] = acc[mt][na][1] + bv0; }
            if (v1) { c0[mb + 8] = acc[mt][na][2] + bv1; c1[mb + 8] = acc[mt][na][3] + bv1; }
        }
    }
}

__global__ __launch_bounds__(256, 1)
void gru_gemm_fused(const float* __restrict__ A1, const float* __restrict__ b1,
                    float* __restrict__ C1, int K1, int nc1,
                    const float* __restrict__ A2, const float* __restrict__ b2,
                    float* __restrict__ C2, int K2, int nc2) {
    extern __shared__ char smem[];
    if (blockIdx.x < 48)
        gemm32_body(A1, b1, C1, H3, K1, nc1, H3, 0, blockIdx.x * 32, smem);
    else
        gemm32_body(A2, b2, C2, H3, K2, nc2, H3, nc1, (blockIdx.x - 48) * 32, smem);
}

// ---------------- kernel 1: u = attn_w^T v, c0 = attn_b.v ----------------
__global__ void prep_kernel(const float* __restrict__ attn_w,
                            const float* __restrict__ attn_b,
                            const float* __restrict__ v) {
    int j = blockIdx.x * blockDim.x + threadIdx.x;
    if (j < H3) {
        float s = 0.f;
        #pragma unroll 8
        for (int h = 0; h < HH; ++h) s += attn_w[h * H3 + j] * v[h];
        g_u[j] = s;
    } else if (j == H3) {
        float s = 0.f;
        for (int h = 0; h < HH; ++h) s += attn_b[h] * v[h];
        g_c0 = s;
    }
}

// ---------------- kernel 2: scores + softmax + context (512 threads) ----------------
__global__ __launch_bounds__(512)
void attn_kernel(const float* __restrict__ hidden,
                 const float* __restrict__ enc,
                 const float* __restrict__ emb,
                 const int* __restrict__ x) {
    __shared__ float s_u[2 * HH];
    __shared__ float s_p[256];
    __shared__ float s_red[16];
    __shared__ float s_constb, s_max, s_sum;

    const int b = blockIdx.x;
    const int tid = threadIdx.x;
    const int lane = tid & 31, wid = tid >> 5;

    for (int j = tid; j < 2 * HH; j += 512) s_u[j] = g_u[HH + j];

    float p = hidden[b * HH + tid % HH] * g_u[tid % HH];
    if (tid >= HH) p = 0.f;
    for (int o = 16; o; o >>= 1) p += __shfl_xor_sync(~0u, p, o);
    if (lane == 0) s_red[wid] = p;
    __syncthreads();
    if (tid == 0) {
        float s = g_c0;
        for (int w = 0; w < 16; ++w) s += s_red[w];
        s_constb = s;
    }
    __syncthreads();
    const float cb = s_constb;

    const float4* enc4 = reinterpret_cast<const float4*>(enc) + (size_t)b * SS * 256;
    const float4* u4 = reinterpret_cast<const float4*>(s_u);
    for (int s = wid; s < SS; s += 16) {
        const float4* row = enc4 + (size_t)s * 256;
        float acc = 0.f;
        #pragma unroll
        for (int t = 0; t < 8; ++t) {
            float4 e = row[lane + 32 * t];
            float4 u = u4[lane + 32 * t];
            acc += e.x * u.x + e.y * u.y + e.z * u.z + e.w * u.w;
        }
        for (int o = 16; o; o >>= 1) acc += __shfl_xor_sync(~0u, acc, o);
        if (lane == 0) s_p[s] = acc + cb;
    }
    __syncthreads();

    float m = -1e30f;
    for (int s = tid; s < SS; s += 512) m = fmaxf(m, s_p[s]);
    for (int o = 16; o; o >>= 1) m = fmaxf(m, __shfl_xor_sync(~0u, m, o));
    if (lane == 0) s_red[wid] = m;
    __syncthreads();
    if (tid == 0) {
        float mm = -1e30f;
        for (int w = 0; w < 16; ++w) mm = fmaxf(mm, s_red[w]);
        s_max = mm;
    }
    __syncthreads();
    const float mm2 = s_max;
    float sum = 0.f;
    for (int s = tid; s < SS; s += 512) {
        float e = expf(s_p[s] - mm2);
        s_p[s] = e;
        sum += e;
    }
    for (int o = 16; o; o >>= 1) sum += __shfl_xor_sync(~0u, sum, o);
    if (lane == 0) s_red[wid] = sum;
    __syncthreads();
    if (tid == 0) {
        float t = 0.f;
        for (int w = 0; w < 16; ++w) t += s_red[w];
        s_sum = 1.f / t;
    }
    __syncthreads();
    const float inv = s_sum;

    float2 acc = make_float2(0.f, 0.f);
    const float2* col = reinterpret_cast<const float2*>(enc) + (size_t)b * SS * 512 + tid;
    #pragma unroll 4
    for (int s = 0; s < SS; ++s) {
        float ps = s_p[s];
        float2 e = col[(size_t)s * 512];
        acc.x += ps * e.x; acc.y += ps * e.y;
    }
    acc.x *= inv; acc.y *= inv;

    const int d = tid * 2;
    *reinterpret_cast<float2*>(g_toout + (size_t)b * KOUT + HH + d) = acc;
    float2 rc = make_float2(fmaxf(acc.x, 0.f), fmaxf(acc.y, 0.f));
    *reinterpret_cast<float2*>(g_togru + (size_t)b * KGRU + EE + d) = rc;

    if (tid < EE) {
        float e = emb[(size_t)x[b] * EE + tid];
        g_toout[(size_t)b * KOUT + H3 + tid] = e;
        g_togru[(size_t)b * KGRU + tid] = fmaxf(e, 0.f);
    }
}

// ---------------- launch (6 launches; ncu -s 5 captures mma_gemm_big) ----------------
extern "C" void kernel_launch(void* const* d_in, const int* in_sizes, int n_in,
                              void* d_out, int out_size) {
    const int*   x      = (const int*)d_in[0];
    const float* hidden = (const float*)d_in[1];
    const float* enc    = (const float*)d_in[2];
    const float* emb    = (const float*)d_in[3];
    const float* attn_w = (const float*)d_in[4];
    const float* attn_b = (const float*)d_in[5];
    const float* v      = (const float*)d_in[6];
    const float* w_ih   = (const float*)d_in[7];
    const float* w_hh   = (const float*)d_in[8];
    const float* b_ih   = (const float*)d_in[9];
    const float* b_hh   = (const float*)d_in[10];
    const float* out_w  = (const float*)d_in[11];
    const float* out_b  = (const float*)d_in[12];
    float* out = (float*)d_out;

    static float *p_togru = nullptr, *p_gi = nullptr, *p_gh = nullptr;
    if (!p_togru) {
        cudaGetSymbolAddress((void**)&p_togru, g_togru);
        cudaGetSymbolAddress((void**)&p_gi, g_gi);
        cudaGetSymbolAddress((void**)&p_gh, g_gh);
        cudaFuncSetAttribute(mma_gemm_big, cudaFuncAttributeMaxDynamicSharedMemorySize,
                             BIG_SMEM);
        cudaFuncSetAttribute(gru_gemm_fused, cudaFuncAttributeMaxDynamicSharedMemorySize,
                             SMALL_SMEM);
    }

    prep_kernel<<<7, 256>>>(attn_w, attn_b, v);                       // 1
    attn_kernel<<<BB, 512>>>(hidden, enc, emb, x);                    // 2
    bconv_gru<<<(KGRU * 16 + HH * 16 + 255) / 256, 256>>>(p_togru, hidden);  // 3
    gru_gemm_fused<<<96, 256, SMALL_SMEM>>>(w_ih, b_ih, p_gi, KGRU, KGRU / 64,
                                            w_hh, b_hh, p_gh, HH, HH / 64);  // 4
    bconv_out_gates<<<(KOUT * 16 + 255) / 256, 256>>>(hidden, out + (size_t)BB * VV);  // 5
    mma_gemm_big<<<(VV + 127) / 128, 512, BIG_SMEM>>>(out_w, out_b, out, VV, KOUT,
                                                      KOUT / 64, VV);  // 6
}

// round 12
// speedup vs baseline: 2.6590x; 1.2598x over previous
#include <cuda_runtime.h>
#include <cuda_bf16.h>
#include <cstdint>

// Problem dims
#define HH   512
#define EE   256
#define VV   50000
#define BB   128
#define SS   200
#define H3   1536          // 3H
#define KGRU 1280          // 2H + E
#define KOUT 1792          // 3H + E

// ---------------- scratch ----------------
__device__ float g_u[H3];
__device__ float g_c0;
__device__ int   g_cnt;                              // prep-slice release counter
__device__ __align__(16) float g_togru[BB * KGRU];
__device__ __align__(16) float g_toout[BB * KOUT];   // [unused 0:512 | context | emb]
__device__ __align__(16) float g_gi[BB * H3];
__device__ __align__(16) float g_gh[BB * H3];
// pre-converted B (hi/lo), swizzled tile layout: [chunk][128 rows][128B]
__device__ uint4 g_bhi[28 * 1024];
__device__ uint4 g_blo[28 * 1024];

// ---------------- helpers ----------------
__device__ __forceinline__ uint32_t smem_u32(const void* p) {
    uint32_t a;
    asm("{ .reg .u64 t; cvta.to.shared.u64 t, %1; cvt.u32.u64 %0, t; }" : "=r"(a) : "l"(p));
    return a;
}
__device__ __forceinline__ void split2(float x, float y, uint32_t& hv, uint32_t& lv) {
    uint32_t h;
    asm("cvt.rn.bf16x2.f32 %0, %1, %2;" : "=r"(h) : "f"(y), "f"(x));
    float hx = __uint_as_float(h << 16);
    float hy = __uint_as_float(h & 0xFFFF0000u);
    float lx = x - hx, ly = y - hy;
    uint32_t l;
    asm("cvt.rn.bf16x2.f32 %0, %1, %2;" : "=r"(l) : "f"(ly), "f"(lx));
    hv = h; lv = l;
}
__device__ __forceinline__ void split8(float4 f0, float4 f1, uint4& hv, uint4& lv) {
    split2(f0.x, f0.y, hv.x, lv.x);
    split2(f0.z, f0.w, hv.y, lv.y);
    split2(f1.x, f1.y, hv.z, lv.z);
    split2(f1.z, f1.w, hv.w, lv.w);
}
__device__ __forceinline__ void sts128(uint32_t addr, uint4 v) {
    asm volatile("st.shared.v4.b32 [%0], {%1,%2,%3,%4};"
                 :: "r"(addr), "r"(v.x), "r"(v.y), "r"(v.z), "r"(v.w) : "memory");
}
__device__ __forceinline__ float4 lds128f(uint32_t a) {
    float4 v;
    asm volatile("ld.shared.v4.f32 {%0,%1,%2,%3}, [%4];"
                 : "=f"(v.x), "=f"(v.y), "=f"(v.z), "=f"(v.w) : "r"(a));
    return v;
}
__device__ __forceinline__ void ldsm4(uint32_t (&r)[4], uint32_t addr) {
    asm volatile("ldmatrix.sync.aligned.m8n8.x4.shared.b16 {%0,%1,%2,%3}, [%4];"
                 : "=r"(r[0]), "=r"(r[1]), "=r"(r[2]), "=r"(r[3]) : "r"(addr));
}
__device__ __forceinline__ void mma16816(float (&d)[4], const uint32_t (&a)[4],
                                         uint32_t b0, uint32_t b1) {
    asm volatile(
        "mma.sync.aligned.m16n8k16.row.col.f32.bf16.bf16.f32 "
        "{%0,%1,%2,%3}, {%4,%5,%6,%7}, {%8,%9}, {%0,%1,%2,%3};"
        : "+f"(d[0]), "+f"(d[1]), "+f"(d[2]), "+f"(d[3])
        : "r"(a[0]), "r"(a[1]), "r"(a[2]), "r"(a[3]), "r"(b0), "r"(b1));
}
__device__ __forceinline__ void cpasync16(uint32_t dst, const void* src) {
    asm volatile("{ .reg .u64 g; cvta.to.global.u64 g, %1; "
                 "cp.async.cg.shared.global [%0], [g], 16; }"
                 :: "r"(dst), "l"(src) : "memory");
}
#define CP_COMMIT() asm volatile("cp.async.commit_group;" ::: "memory")
#define CP_WAIT1()  asm volatile("cp.async.wait_group 1;" ::: "memory")
#define CP_WAIT0()  asm volatile("cp.async.wait_group 0;" ::: "memory")

// ---------------- B convert core: 8 floats -> swizzled hi/lo granule ----------------
__device__ __forceinline__ void bconv_store(int chunk, int r, int g8, float4 f0, float4 f1) {
    uint4 hv, lv;
    split8(f0, f1, hv, lv);
    uint32_t off = (uint32_t)chunk * 16384 + (uint32_t)r * 128 +
                   (((uint32_t)g8 * 16) ^ (((uint32_t)r & 7u) << 4));
    g_bhi[off >> 4] = hv;
    g_blo[off >> 4] = lv;
}

// ---------------- launch 1: prep(sliced) + attention + GRU-B convert ----------------
__global__ __launch_bounds__(512)
void attn_fused(const float* __restrict__ hidden,
                const float* __restrict__ enc,
                const float* __restrict__ emb,
                const int* __restrict__ x,
                const float* __restrict__ attn_w,
                const float* __restrict__ attn_b,
                const float* __restrict__ v) {
    __shared__ float s_u[2 * HH];
    __shared__ float s_p[256];
    __shared__ float s_red[16];
    __shared__ float s_part[4][128];
    __shared__ float s_constb, s_max, s_sum;

    const int b = blockIdx.x;
    const int tid = threadIdx.x;
    const int lane = tid & 31, wid = tid >> 5;

    // ---- phase 0: CTAs 0..11 compute u slice [b*128, b*128+128) ----
    if (b < 12) {
        const int j = tid & 127, hq = tid >> 7;     // 4 h-quarters
        const int jj = b * 128 + j;
        float s = 0.f;
        #pragma unroll 8
        for (int h = hq * 128; h < hq * 128 + 128; ++h)
            s += attn_w[(size_t)h * H3 + jj] * v[h];
        s_part[hq][j] = s;
        float pc = 0.f;
        if (b == 0) pc = attn_b[tid] * v[tid];      // c0 partial (CTA 0 only)
        for (int o = 16; o; o >>= 1) pc += __shfl_xor_sync(~0u, pc, o);
        if (lane == 0) s_red[wid] = pc;
        __syncthreads();
        if (tid < 128)
            g_u[b * 128 + tid] = s_part[0][tid] + s_part[1][tid] +
                                 s_part[2][tid] + s_part[3][tid];
        if (b == 0 && tid == 0) {
            float s0 = 0.f;
            for (int w = 0; w < 16; ++w) s0 += s_red[w];
            g_c0 = s0;
        }
        __threadfence();
        __syncthreads();
        if (tid == 0) atomicAdd(&g_cnt, 1);
    }
    // ---- all CTAs wait for the 12 slices (all co-resident: grid 128 < 148 SMs) ----
    if (tid == 0) {
        while (atomicAdd(&g_cnt, 0) < 12) __nanosleep(32);
    }
    __syncthreads();
    __threadfence();

    for (int j = tid; j < 2 * HH; j += 512) s_u[j] = g_u[HH + j];

    float p = hidden[b * HH + (tid & (HH - 1))] * g_u[tid & (HH - 1)];
    if (tid >= HH) p = 0.f;
    for (int o = 16; o; o >>= 1) p += __shfl_xor_sync(~0u, p, o);
    if (lane == 0) s_red[wid] = p;
    __syncthreads();
    if (tid == 0) {
        float s = g_c0;
        for (int w = 0; w < 16; ++w) s += s_red[w];
        s_constb = s;
    }
    __syncthreads();
    const float cb = s_constb;

    const float4* enc4 = reinterpret_cast<const float4*>(enc) + (size_t)b * SS * 256;
    const float4* u4 = reinterpret_cast<const float4*>(s_u);
    for (int s = wid; s < SS; s += 16) {
        const float4* row = enc4 + (size_t)s * 256;
        float acc = 0.f;
        #pragma unroll
        for (int t = 0; t < 8; ++t) {
            float4 e = row[lane + 32 * t];
            float4 u = u4[lane + 32 * t];
            acc += e.x * u.x + e.y * u.y + e.z * u.z + e.w * u.w;
        }
        for (int o = 16; o; o >>= 1) acc += __shfl_xor_sync(~0u, acc, o);
        if (lane == 0) s_p[s] = acc + cb;
    }
    __syncthreads();

    float m = -1e30f;
    for (int s = tid; s < SS; s += 512) m = fmaxf(m, s_p[s]);
    for (int o = 16; o; o >>= 1) m = fmaxf(m, __shfl_xor_sync(~0u, m, o));
    if (lane == 0) s_red[wid] = m;
    __syncthreads();
    if (tid == 0) {
        float mm = -1e30f;
        for (int w = 0; w < 16; ++w) mm = fmaxf(mm, s_red[w]);
        s_max = mm;
    }
    __syncthreads();
    const float mm2 = s_max;
    float sum = 0.f;
    for (int s = tid; s < SS; s += 512) {
        float e = expf(s_p[s] - mm2);
        s_p[s] = e;
        sum += e;
    }
    for (int o = 16; o; o >>= 1) sum += __shfl_xor_sync(~0u, sum, o);
    if (lane == 0) s_red[wid] = sum;
    __syncthreads();
    if (tid == 0) {
        float t = 0.f;
        for (int w = 0; w < 16; ++w) t += s_red[w];
        s_sum = 1.f / t;
    }
    __syncthreads();
    const float inv = s_sum;

    float2 acc = make_float2(0.f, 0.f);
    const float2* col = reinterpret_cast<const float2*>(enc) + (size_t)b * SS * 512 + tid;
    #pragma unroll 4
    for (int s = 0; s < SS; ++s) {
        float ps = s_p[s];
        float2 e = col[(size_t)s * 512];
        acc.x += ps * e.x; acc.y += ps * e.y;
    }
    acc.x *= inv; acc.y *= inv;

    const int d = tid * 2;
    *reinterpret_cast<float2*>(g_toout + (size_t)b * KOUT + HH + d) = acc;
    float2 rc = make_float2(fmaxf(acc.x, 0.f), fmaxf(acc.y, 0.f));
    *reinterpret_cast<float2*>(g_togru + (size_t)b * KGRU + EE + d) = rc;

    if (tid < EE) {
        float e = emb[(size_t)x[b] * EE + tid];
        g_toout[(size_t)b * KOUT + H3 + tid] = e;
        g_togru[(size_t)b * KGRU + tid] = fmaxf(e, 0.f);
    }
    __syncthreads();   // togru row b visible CTA-wide

    // ---- epilogue: convert GRU B row b (togru: chunks 0..19, hidden: 20..27) ----
    if (tid < 224) {
        const int c = tid >> 3, g8 = tid & 7;
        float4 f0, f1;
        if (c < 20) {
            const float4* src = reinterpret_cast<const float4*>(
                g_togru + (size_t)b * KGRU + c * 64 + g8 * 8);
            f0 = src[0]; f1 = src[1];
            bconv_store(c, b, g8, f0, f1);
        } else {
            const float4* src = reinterpret_cast<const float4*>(
                hidden + (size_t)b * HH + (c - 20) * 64 + g8 * 8);
            f0 = src[0]; f1 = src[1];
            bconv_store(c, b, g8, f0, f1);
        }
    }
}

// ================= small GEMM body (MT=32), fused GRU launch (launch 2) =================
#define SMALL_SMEM 131072

__device__ __forceinline__
void gemm32_body(const float* __restrict__ A, const float* __restrict__ bias,
                 float* __restrict__ C, int M, int K, int nchunk, int ldc,
                 int boff, int m0, char* smem) {
    constexpr uint32_t AR = 8192, AT = 4096;
    const uint32_t sb = smem_u32(smem);
    const uint32_t o_ahi = 2 * AR, o_alo = 2 * AR + 2 * AT;
    const uint32_t o_bhi = 2 * AR + 4 * AT, o_blo = o_bhi + 49152;

    const int tid = threadIdx.x, wid = tid >> 5, lane = tid & 31;
    const int warpN = wid;

    const int crow = tid & 31, ch = (tid >> 5) & 1;
    const bool do_a = tid < 64;
    const bool avalid = do_a && (m0 + crow) < M;
    const int srow = ((m0 + crow) < M) ? (m0 + crow) : 0;
    const uint32_t rswz = ((uint32_t)crow & 7u) << 4;

    const int l15 = lane & 15, lhi = lane >> 4;
    const uint32_t rowAoff = (uint32_t)l15 * 128;
    const uint32_t xorA = (((uint32_t)l15) & 7u) << 4;
    const uint32_t rowBoff = (uint32_t)(warpN * 16 + l15) * 128;
    const uint32_t xorB = (((uint32_t)(warpN * 16 + l15)) & 7u) << 4;

    float acc[2][2][4];
    #pragma unroll
    for (int mt = 0; mt < 2; ++mt)
        #pragma unroll
        for (int na = 0; na < 2; ++na)
            #pragma unroll
            for (int q = 0; q < 4; ++q) acc[mt][na][q] = 0.f;

    auto issue_a = [&](int c) {
        if (!do_a) return;
        const uint32_t dst0 = sb + (uint32_t)(c & 1) * AR + (uint32_t)crow * 256;
        const float* src0 = A + (size_t)srow * K + c * 64;
        #pragma unroll
        for (int i = 0; i < 8; ++i) {
            uint32_t g = (uint32_t)(ch * 8 + i);
            cpasync16(dst0 + ((g << 4) ^ rswz), src0 + g * 4);
        }
    };
    auto issue_b = [&](int c, int slot) {
        const char* shi = (const char*)g_bhi + (size_t)(boff + c) * 16384;
        const char* slo = (const char*)g_blo + (size_t)(boff + c) * 16384;
        const uint32_t dhi = sb + o_bhi + (uint32_t)slot * 16384;
        const uint32_t dlo = sb + o_blo + (uint32_t)slot * 16384;
        #pragma unroll
        for (int i = 0; i < 4; ++i) {
            uint32_t lin = (uint32_t)(tid + i * 256) * 16;
            cpasync16(dhi + lin, shi + lin);
            cpasync16(dlo + lin, slo + lin);
        }
    };

    issue_a(0); issue_b(0, 0); CP_COMMIT();
    if (nchunk > 1) { issue_a(1); issue_b(1, 1); }
    CP_COMMIT();

    int bslot = 0, bslot2 = 2;
    for (int c = 0; c < nchunk; ++c) {
        CP_WAIT1();
        __syncthreads();
        const uint32_t stA = (uint32_t)(c & 1);
        if (do_a) {
            const uint32_t rbase = sb + stA * AR + (uint32_t)crow * 256;
            const uint32_t hbase = sb + o_ahi + stA * AT + (uint32_t)crow * 128;
            const uint32_t lbase = sb + o_alo + stA * AT + (uint32_t)crow * 128;
            #pragma unroll
            for (int j = 0; j < 4; ++j) {
                uint32_t g0 = (uint32_t)(ch * 8 + 2 * j);
                float4 f0 = lds128f(rbase + ((g0 << 4) ^ rswz));
                float4 f1 = lds128f(rbase + (((g0 + 1) << 4) ^ rswz));
                uint4 hv, lv;
                if (avalid) split8(f0, f1, hv, lv);
                else { hv = make_uint4(0, 0, 0, 0); lv = make_uint4(0, 0, 0, 0); }
                uint32_t toff = ((uint32_t)(ch * 64 + j * 16)) ^ rswz;
                sts128(hbase + toff, hv);
                sts128(lbase + toff, lv);
            }
        }
        if (c + 2 < nchunk) { issue_a(c + 2); issue_b(c + 2, bslot2); }
        CP_COMMIT();
        __syncthreads();
        const uint32_t ahiB = sb + o_ahi + stA * AT;
        const uint32_t aloB = sb + o_alo + stA * AT;
        const uint32_t bhiB = sb + o_bhi + (uint32_t)bslot * 16384;
        const uint32_t bloB = sb + o_blo + (uint32_t)bslot * 16384;
        #pragma unroll
        for (int k16 = 0; k16 < 4; ++k16) {
            const uint32_t kb = (uint32_t)(k16 * 32 + lhi * 16);
            const uint32_t kA = kb ^ xorA, kB = kb ^ xorB;
            uint32_t ah[2][4], al[2][4], bh[4], bl[4];
            ldsm4(ah[0], ahiB + rowAoff + kA);
            ldsm4(ah[1], ahiB + rowAoff + 2048 + kA);
            ldsm4(al[0], aloB + rowAoff + kA);
            ldsm4(al[1], aloB + rowAoff + 2048 + kA);
            ldsm4(bh, bhiB + rowBoff + kB);
            ldsm4(bl, bloB + rowBoff + kB);
            #pragma unroll
            for (int mt = 0; mt < 2; ++mt) {
                mma16816(acc[mt][0], ah[mt], bh[0], bh[2]);
                mma16816(acc[mt][1], ah[mt], bh[1], bh[3]);
            }
            #pragma unroll
            for (int mt = 0; mt < 2; ++mt) {
                mma16816(acc[mt][0], ah[mt], bl[0], bl[2]);
                mma16816(acc[mt][1], ah[mt], bl[1], bl[3]);
            }
            #pragma unroll
            for (int mt = 0; mt < 2; ++mt) {
                mma16816(acc[mt][0], al[mt], bh[0], bh[2]);
                mma16816(acc[mt][1], al[mt], bh[1], bh[3]);
            }
        }
        bslot = (bslot == 2) ? 0 : bslot + 1;
        bslot2 = (bslot2 == 2) ? 0 : bslot2 + 1;
    }
    CP_WAIT0();

    const int mrow = lane >> 2, ncol = (lane & 3) * 2;
    #pragma unroll
    for (int mt = 0; mt < 2; ++mt) {
        const int mb = m0 + mt * 16 + mrow;
        const bool v0 = mb < M, v1 = (mb + 8) < M;
        const float bv0 = v0 ? bias[mb] : 0.f;
        const float bv1 = v1 ? bias[mb + 8] : 0.f;
        #pragma unroll
        for (int na = 0; na < 2; ++na) {
            const int n = warpN * 16 + na * 8 + ncol;
            float* c0 = C + (size_t)n * ldc;
            float* c1 = C + (size_t)(n + 1) * ldc;
            if (v0) { c0[mb] = acc[mt][na][0] + bv0; c1[mb] = acc[mt][na][1] + bv0; }
            if (v1) { c0[mb + 8] = acc[mt][na][2] + bv1; c1[mb + 8] = acc[mt][na][3] + bv1; }
        }
    }
}

__global__ __launch_bounds__(256, 1)
void gru_gemm_fused(const float* __restrict__ A1, const float* __restrict__ b1,
                    float* __restrict__ C1, int K1, int nc1,
                    const float* __restrict__ A2, const float* __restrict__ b2,
                    float* __restrict__ C2, int K2, int nc2) {
    extern __shared__ char smem[];
    if (blockIdx.x < 48)
        gemm32_body(A1, b1, C1, H3, K1, nc1, H3, 0, blockIdx.x * 32, smem);
    else
        gemm32_body(A2, b2, C2, H3, K2, nc2, H3, nc1, (blockIdx.x - 48) * 32, smem);
}

// ---------------- launch 3: GRU gates + logits-B convert ----------------
__global__ void bconv_out_gates(const float* __restrict__ hidden, float* __restrict__ out_h) {
    int idx = blockIdx.x * 256 + threadIdx.x;
    if (idx >= KOUT * 16) return;
    int c = idx >> 10, r = (idx >> 3) & 127, g8 = idx & 7;
    int k0 = c * 64 + g8 * 8;
    float4 f0, f1;
    if (c < 8) {
        float v[8];
        const float* gi = g_gi + (size_t)r * H3 + k0;
        const float* gh = g_gh + (size_t)r * H3 + k0;
        const float* hp = hidden + (size_t)r * HH + k0;
        #pragma unroll
        for (int i = 0; i < 8; ++i) {
            float rr = 1.f / (1.f + expf(-(gi[i] + gh[i])));
            float zz = 1.f / (1.f + expf(-(gi[HH + i] + gh[HH + i])));
            float nn = tanhf(gi[2 * HH + i] + rr * gh[2 * HH + i]);
            v[i] = (1.f - zz) * nn + zz * hp[i];
        }
        f0 = make_float4(v[0], v[1], v[2], v[3]);
        f1 = make_float4(v[4], v[5], v[6], v[7]);
        *reinterpret_cast<float4*>(out_h + (size_t)r * HH + k0) = f0;
        *reinterpret_cast<float4*>(out_h + (size_t)r * HH + k0 + 4) = f1;
    } else {
        const float4* src = reinterpret_cast<const float4*>(g_toout + (size_t)r * KOUT + k0);
        f0 = src[0];
        f1 = src[1];
    }
    bconv_store(c, r, g8, f0, f1);
}

// ============ launch 4: big logits GEMM (MT=64, 256 thr, 2 CTAs/SM) ============
#define BIG_SMEM 98304

__global__ __launch_bounds__(256, 2)
void mma_gemm_big(const float* __restrict__ A, const float* __restrict__ bias,
                  float* __restrict__ C, int M, int K, int nchunk, int ldc) {
    extern __shared__ char smem[];
    const uint32_t sb = smem_u32(smem);
    const int tid = threadIdx.x, wid = tid >> 5, lane = tid & 31;
    const int warpM = wid & 1, warpN = wid >> 1;
    const int m0 = blockIdx.x * 64;

    // A staging: thread owns (row = tid>>2, quarter q = tid&3) -> 16 floats/chunk
    const int crow = tid >> 2, cq = tid & 3;
    const bool avalid = (m0 + crow) < M;
    const int srow = avalid ? (m0 + crow) : 0;
    const uint32_t rswz = ((uint32_t)crow & 7u) << 4;
    const float4* aq = reinterpret_cast<const float4*>(A + (size_t)srow * K) + cq * 4;

    const int l15 = lane & 15, lhi = lane >> 4;
    const uint32_t rowAoff = (uint32_t)(warpM * 32 + l15) * 128;
    const uint32_t xorA = (((uint32_t)(warpM * 32 + l15)) & 7u) << 4;
    const uint32_t rowBoff = (uint32_t)(warpN * 32 + l15) * 128;
    const uint32_t xorB = (((uint32_t)(warpN * 32 + l15)) & 7u) << 4;

    float acc[2][4][4];
    #pragma unroll
    for (int mt = 0; mt < 2; ++mt)
        #pragma unroll
        for (int na = 0; na < 4; ++na)
            #pragma unroll
            for (int q = 0; q < 4; ++q) acc[mt][na][q] = 0.f;

    float4 rA[4];

    // smem: ahi[2]@0 (8KB ea), alo[2]@16K, B stages @32K: [bhi 16K | blo 16K] x2
    auto issue_b = [&](int c, int slot) {
        const char* shi = (const char*)g_bhi + (size_t)c * 16384;
        const char* slo = (const char*)g_blo + (size_t)c * 16384;
        const uint32_t dhi = sb + 32768u + (uint32_t)slot * 32768u;
        const uint32_t dlo = dhi + 16384u;
        #pragma unroll
        for (int i = 0; i < 4; ++i) {
            uint32_t lin = (uint32_t)(tid + i * 256) * 16;
            cpasync16(dhi + lin, shi + lin);
            cpasync16(dlo + lin, slo + lin);
        }
    };
    auto convert_sts = [&](int st) {
        const uint32_t hb = sb + (uint32_t)st * 8192u + (uint32_t)crow * 128;
        const uint32_t lb = hb + 16384u;
        const uint32_t o0 = ((uint32_t)(cq * 32)) ^ rswz;
        const uint32_t o1 = ((uint32_t)(cq * 32 + 16)) ^ rswz;
        uint4 hv, lv;
        if (avalid) split8(rA[0], rA[1], hv, lv);
        else { hv = make_uint4(0, 0, 0, 0); lv = make_uint4(0, 0, 0, 0); }
        sts128(hb + o0, hv);
        sts128(lb + o0, lv);
        if (avalid) split8(rA[2], rA[3], hv, lv);
        else { hv = make_uint4(0, 0, 0, 0); lv = make_uint4(0, 0, 0, 0); }
        sts128(hb + o1, hv);
        sts128(lb + o1, lv);
    };

    #pragma unroll
    for (int i = 0; i < 4; ++i) rA[i] = aq[i];
    issue_b(0, 0);
    CP_COMMIT();
    convert_sts(0);
    if (nchunk > 1) {
        #pragma unroll
        for (int i = 0; i < 4; ++i) rA[i] = aq[16 + i];
    }

    for (int c = 0; c < nchunk; ++c) {
        CP_WAIT0();
        __syncthreads();
        if (c + 1 < nchunk) { issue_b(c + 1, (c + 1) & 1); CP_COMMIT(); }

        const uint32_t ahiB = sb + (uint32_t)(c & 1) * 8192u;
        const uint32_t aloB = ahiB + 16384u;
        const uint32_t bhiB = sb + 32768u + (uint32_t)(c & 1) * 32768u;
        const uint32_t bloB = bhiB + 16384u;
        #pragma unroll
        for (int k16 = 0; k16 < 4; ++k16) {
            const uint32_t kb = (uint32_t)(k16 * 32 + lhi * 16);
            const uint32_t kA = kb ^ xorA, kB = kb ^ xorB;
            uint32_t ah[2][4], al[2][4], bh[2][4], bl[2][4];
            ldsm4(ah[0], ahiB + rowAoff + kA);
            ldsm4(ah[1], ahiB + rowAoff + 2048 + kA);
            ldsm4(al[0], aloB + rowAoff + kA);
            ldsm4(al[1], aloB + rowAoff + 2048 + kA);
            ldsm4(bh[0], bhiB + rowBoff + kB);
            ldsm4(bh[1], bhiB + rowBoff + 2048 + kB);
            ldsm4(bl[0], bloB + rowBoff + kB);
            ldsm4(bl[1], bloB + rowBoff + 2048 + kB);
            #pragma unroll
            for (int mt = 0; mt < 2; ++mt)
                #pragma unroll
                for (int na = 0; na < 4; ++na) {
                    const uint32_t* bq = bh[na >> 1];
                    if (na & 1) mma16816(acc[mt][na], ah[mt], bq[1], bq[3]);
                    else        mma16816(acc[mt][na], ah[mt], bq[0], bq[2]);
                }
            #pragma unroll
            for (int mt = 0; mt < 2; ++mt)
                #pragma unroll
                for (int na = 0; na < 4; ++na) {
                    const uint32_t* bq = bl[na >> 1];
                    if (na & 1) mma16816(acc[mt][na], ah[mt], bq[1], bq[3]);
                    else        mma16816(acc[mt][na], ah[mt], bq[0], bq[2]);
                }
            #pragma unroll
            for (int mt = 0; mt < 2; ++mt)
                #pragma unroll
                for (int na = 0; na < 4; ++na) {
                    const uint32_t* bq = bh[na >> 1];
                    if (na & 1) mma16816(acc[mt][na], al[mt], bq[1], bq[3]);
                    else        mma16816(acc[mt][na], al[mt], bq[0], bq[2]);
                }
        }
        if (c + 1 < nchunk) {
            convert_sts((c + 1) & 1);
            if (c + 2 < nchunk) {
                #pragma unroll
                for (int i = 0; i < 4; ++i) rA[i] = aq[(c + 2) * 16 + i];
            }
        }
    }

    const int mrow = lane >> 2, ncol = (lane & 3) * 2;
    #pragma unroll
    for (int mt = 0; mt < 2; ++mt) {
        const int mb = m0 + warpM * 32 + mt * 16 + mrow;
        const bool v0 = mb < M, v1 = (mb + 8) < M;
        const float bv0 = v0 ? bias[mb] : 0.f;
        const float bv1 = v1 ? bias[mb + 8] : 0.f;
        #pragma unroll
        for (int na = 0; na < 4; ++na) {
            const int n = warpN * 32 + na * 8 + ncol;
            float* c0 = C + (size_t)n * ldc;
            float* c1 = C + (size_t)(n + 1) * ldc;
            if (v0) { c0[mb] = acc[mt][na][0] + bv0; c1[mb] = acc[mt][na][1] + bv0; }
            if (v1) { c0[mb + 8] = acc[mt][na][2] + bv1; c1[mb + 8] = acc[mt][na][3] + bv1; }
        }
    }
}

// ---------------- launch (4 launches; ncu -s 5 (+2 harness) captures #4 = big) ----------------
extern "C" void kernel_launch(void* const* d_in, const int* in_sizes, int n_in,
                              void* d_out, int out_size) {
    const int*   x      = (const int*)d_in[0];
    const float* hidden = (const float*)d_in[1];
    const float* enc    = (const float*)d_in[2];
    const float* emb    = (const float*)d_in[3];
    const float* attn_w = (const float*)d_in[4];
    const float* attn_b = (const float*)d_in[5];
    const float* v      = (const float*)d_in[6];
    const float* w_ih   = (const float*)d_in[7];
    const float* w_hh   = (const float*)d_in[8];
    const float* b_ih   = (const float*)d_in[9];
    const float* b_hh   = (const float*)d_in[10];
    const float* out_w  = (const float*)d_in[11];
    const float* out_b  = (const float*)d_in[12];
    float* out = (float*)d_out;

    static float *p_gi = nullptr, *p_gh = nullptr;
    if (!p_gi) {
        cudaGetSymbolAddress((void**)&p_gi, g_gi);
        cudaGetSymbolAddress((void**)&p_gh, g_gh);
        cudaFuncSetAttribute(mma_gemm_big, cudaFuncAttributeMaxDynamicSharedMemorySize,
                             BIG_SMEM);
        cudaFuncSetAttribute(gru_gemm_fused, cudaFuncAttributeMaxDynamicSharedMemorySize,
                             SMALL_SMEM);
    }

    attn_fused<<<BB, 512>>>(hidden, enc, emb, x, attn_w, attn_b, v);           // 1
    gru_gemm_fused<<<96, 256, SMALL_SMEM>>>(w_ih, b_ih, p_gi, KGRU, KGRU / 64,
                                            w_hh, b_hh, p_gh, HH, HH / 64);    // 2
    bconv_out_gates<<<(KOUT * 16 + 255) / 256, 256>>>(hidden, out + (size_t)BB * VV);  // 3
    mma_gemm_big<<<(VV + 63) / 64, 256, BIG_SMEM>>>(out_w, out_b, out, VV, KOUT,
                                                    KOUT / 64, VV);            // 4
}

// round 13
// speedup vs baseline: 3.2970x; 1.2399x over previous
#include <cuda_runtime.h>
#include <cuda_fp16.h>
#include <cstdint>

// Problem dims
#define HH   512
#define EE   256
#define VV   50000
#define BB   128
#define SS   200
#define H3   1536          // 3H
#define KGRU 1280          // 2H + E
#define KOUT 1792          // 3H + E

// ---------------- scratch ----------------
__device__ float g_u[H3];
__device__ float g_c0;
__device__ int   g_cnt;                              // prep-slice release counter
__device__ __align__(16) float g_togru[BB * KGRU];
__device__ __align__(16) float g_toout[BB * KOUT];   // [unused 0:512 | context | emb]
__device__ __align__(16) float g_gi[BB * H3];
__device__ __align__(16) float g_gh[BB * H3];
// pre-converted B (single fp16), swizzled tile layout: [chunk][128 rows][128B]
__device__ uint4 g_bh[28 * 1024];

// ---------------- helpers ----------------
__device__ __forceinline__ uint32_t smem_u32(const void* p) {
    uint32_t a;
    asm("{ .reg .u64 t; cvta.to.shared.u64 t, %1; cvt.u32.u64 %0, t; }" : "=r"(a) : "l"(p));
    return a;
}
__device__ __forceinline__ uint32_t f16pair(float x, float y) {   // {lo=x, hi=y}
    uint32_t h;
    asm("cvt.rn.f16x2.f32 %0, %1, %2;" : "=r"(h) : "f"(y), "f"(x));
    return h;
}
// fp16 hi/lo split: hv = fp16(x),fp16(y); lv = fp16 residuals (A to ~2^-22)
__device__ __forceinline__ void split2(float x, float y, uint32_t& hv, uint32_t& lv) {
    uint32_t h = f16pair(x, y);
    __half2 hh = *reinterpret_cast<const __half2*>(&h);
    float2 hf = __half22float2(hh);
    lv = f16pair(x - hf.x, y - hf.y);
    hv = h;
}
__device__ __forceinline__ void split8(float4 f0, float4 f1, uint4& hv, uint4& lv) {
    split2(f0.x, f0.y, hv.x, lv.x);
    split2(f0.z, f0.w, hv.y, lv.y);
    split2(f1.x, f1.y, hv.z, lv.z);
    split2(f1.z, f1.w, hv.w, lv.w);
}
__device__ __forceinline__ uint4 pack8h(float4 f0, float4 f1) {
    uint4 hv;
    hv.x = f16pair(f0.x, f0.y);
    hv.y = f16pair(f0.z, f0.w);
    hv.z = f16pair(f1.x, f1.y);
    hv.w = f16pair(f1.z, f1.w);
    return hv;
}
__device__ __forceinline__ void sts128(uint32_t addr, uint4 v) {
    asm volatile("st.shared.v4.b32 [%0], {%1,%2,%3,%4};"
                 :: "r"(addr), "r"(v.x), "r"(v.y), "r"(v.z), "r"(v.w) : "memory");
}
__device__ __forceinline__ float4 lds128f(uint32_t a) {
    float4 v;
    asm volatile("ld.shared.v4.f32 {%0,%1,%2,%3}, [%4];"
                 : "=f"(v.x), "=f"(v.y), "=f"(v.z), "=f"(v.w) : "r"(a));
    return v;
}
__device__ __forceinline__ void ldsm4(uint32_t (&r)[4], uint32_t addr) {
    asm volatile("ldmatrix.sync.aligned.m8n8.x4.shared.b16 {%0,%1,%2,%3}, [%4];"
                 : "=r"(r[0]), "=r"(r[1]), "=r"(r[2]), "=r"(r[3]) : "r"(addr));
}
__device__ __forceinline__ void mma16816(float (&d)[4], const uint32_t (&a)[4],
                                         uint32_t b0, uint32_t b1) {
    asm volatile(
        "mma.sync.aligned.m16n8k16.row.col.f32.f16.f16.f32 "
        "{%0,%1,%2,%3}, {%4,%5,%6,%7}, {%8,%9}, {%0,%1,%2,%3};"
        : "+f"(d[0]), "+f"(d[1]), "+f"(d[2]), "+f"(d[3])
        : "r"(a[0]), "r"(a[1]), "r"(a[2]), "r"(a[3]), "r"(b0), "r"(b1));
}
__device__ __forceinline__ void cpasync16(uint32_t dst, const void* src) {
    asm volatile("{ .reg .u64 g; cvta.to.global.u64 g, %1; "
                 "cp.async.cg.shared.global [%0], [g], 16; }"
                 :: "r"(dst), "l"(src) : "memory");
}
#define CP_COMMIT() asm volatile("cp.async.commit_group;" ::: "memory")
#define CP_WAIT1()  asm volatile("cp.async.wait_group 1;" ::: "memory")
#define CP_WAIT0()  asm volatile("cp.async.wait_group 0;" ::: "memory")

// ---------------- B convert core: 8 floats -> swizzled fp16 granule (16B) ----------------
__device__ __forceinline__ void bconv_store(int chunk, int r, int g8, float4 f0, float4 f1) {
    uint32_t off = (uint32_t)chunk * 16384 + (uint32_t)r * 128 +
                   (((uint32_t)g8 * 16) ^ (((uint32_t)r & 7u) << 4));
    g_bh[off >> 4] = pack8h(f0, f1);
}

// ---------------- launch 1: prep(sliced) + attention + GRU-B convert ----------------
__global__ __launch_bounds__(512)
void attn_fused(const float* __restrict__ hidden,
                const float* __restrict__ enc,
                const float* __restrict__ emb,
                const int* __restrict__ x,
                const float* __restrict__ attn_w,
                const float* __restrict__ attn_b,
                const float* __restrict__ v) {
    __shared__ float s_u[2 * HH];
    __shared__ float s_p[256];
    __shared__ float s_red[16];
    __shared__ float s_part[4][128];
    __shared__ float s_constb, s_max, s_sum;

    const int b = blockIdx.x;
    const int tid = threadIdx.x;
    const int lane = tid & 31, wid = tid >> 5;

    // ---- phase 0: CTAs 0..11 compute u slice [b*128, b*128+128) ----
    if (b < 12) {
        const int j = tid & 127, hq = tid >> 7;
        const int jj = b * 128 + j;
        float s = 0.f;
        #pragma unroll 8
        for (int h = hq * 128; h < hq * 128 + 128; ++h)
            s += attn_w[(size_t)h * H3 + jj] * v[h];
        s_part[hq][j] = s;
        float pc = 0.f;
        if (b == 0) pc = attn_b[tid] * v[tid];
        for (int o = 16; o; o >>= 1) pc += __shfl_xor_sync(~0u, pc, o);
        if (lane == 0) s_red[wid] = pc;
        __syncthreads();
        if (tid < 128)
            g_u[b * 128 + tid] = s_part[0][tid] + s_part[1][tid] +
                                 s_part[2][tid] + s_part[3][tid];
        if (b == 0 && tid == 0) {
            float s0 = 0.f;
            for (int w = 0; w < 16; ++w) s0 += s_red[w];
            g_c0 = s0;
        }
        __threadfence();
        __syncthreads();
        if (tid == 0) atomicAdd(&g_cnt, 1);
    }
    if (tid == 0) {
        while (atomicAdd(&g_cnt, 0) < 12) __nanosleep(32);
    }
    __syncthreads();
    __threadfence();

    for (int j = tid; j < 2 * HH; j += 512) s_u[j] = g_u[HH + j];

    float p = hidden[b * HH + (tid & (HH - 1))] * g_u[tid & (HH - 1)];
    if (tid >= HH) p = 0.f;
    for (int o = 16; o; o >>= 1) p += __shfl_xor_sync(~0u, p, o);
    if (lane == 0) s_red[wid] = p;
    __syncthreads();
    if (tid == 0) {
        float s = g_c0;
        for (int w = 0; w < 16; ++w) s += s_red[w];
        s_constb = s;
    }
    __syncthreads();
    const float cb = s_constb;

    const float4* enc4 = reinterpret_cast<const float4*>(enc) + (size_t)b * SS * 256;
    const float4* u4 = reinterpret_cast<const float4*>(s_u);
    for (int s = wid; s < SS; s += 16) {
        const float4* row = enc4 + (size_t)s * 256;
        float acc = 0.f;
        #pragma unroll
        for (int t = 0; t < 8; ++t) {
            float4 e = row[lane + 32 * t];
            float4 u = u4[lane + 32 * t];
            acc += e.x * u.x + e.y * u.y + e.z * u.z + e.w * u.w;
        }
        for (int o = 16; o; o >>= 1) acc += __shfl_xor_sync(~0u, acc, o);
        if (lane == 0) s_p[s] = acc + cb;
    }
    __syncthreads();

    float m = -1e30f;
    for (int s = tid; s < SS; s += 512) m = fmaxf(m, s_p[s]);
    for (int o = 16; o; o >>= 1) m = fmaxf(m, __shfl_xor_sync(~0u, m, o));
    if (lane == 0) s_red[wid] = m;
    __syncthreads();
    if (tid == 0) {
        float mm = -1e30f;
        for (int w = 0; w < 16; ++w) mm = fmaxf(mm, s_red[w]);
        s_max = mm;
    }
    __syncthreads();
    const float mm2 = s_max;
    float sum = 0.f;
    for (int s = tid; s < SS; s += 512) {
        float e = expf(s_p[s] - mm2);
        s_p[s] = e;
        sum += e;
    }
    for (int o = 16; o; o >>= 1) sum += __shfl_xor_sync(~0u, sum, o);
    if (lane == 0) s_red[wid] = sum;
    __syncthreads();
    if (tid == 0) {
        float t = 0.f;
        for (int w = 0; w < 16; ++w) t += s_red[w];
        s_sum = 1.f / t;
    }
    __syncthreads();
    const float inv = s_sum;

    float2 acc = make_float2(0.f, 0.f);
    const float2* col = reinterpret_cast<const float2*>(enc) + (size_t)b * SS * 512 + tid;
    #pragma unroll 4
    for (int s = 0; s < SS; ++s) {
        float ps = s_p[s];
        float2 e = col[(size_t)s * 512];
        acc.x += ps * e.x; acc.y += ps * e.y;
    }
    acc.x *= inv; acc.y *= inv;

    const int d = tid * 2;
    *reinterpret_cast<float2*>(g_toout + (size_t)b * KOUT + HH + d) = acc;
    float2 rc = make_float2(fmaxf(acc.x, 0.f), fmaxf(acc.y, 0.f));
    *reinterpret_cast<float2*>(g_togru + (size_t)b * KGRU + EE + d) = rc;

    if (tid < EE) {
        float e = emb[(size_t)x[b] * EE + tid];
        g_toout[(size_t)b * KOUT + H3 + tid] = e;
        g_togru[(size_t)b * KGRU + tid] = fmaxf(e, 0.f);
    }
    __syncthreads();

    // ---- epilogue: convert GRU B row b (togru: chunks 0..19, hidden: 20..27) ----
    if (tid < 224) {
        const int c = tid >> 3, g8 = tid & 7;
        if (c < 20) {
            const float4* src = reinterpret_cast<const float4*>(
                g_togru + (size_t)b * KGRU + c * 64 + g8 * 8);
            bconv_store(c, b, g8, src[0], src[1]);
        } else {
            const float4* src = reinterpret_cast<const float4*>(
                hidden + (size_t)b * HH + (c - 20) * 64 + g8 * 8);
            bconv_store(c, b, g8, src[0], src[1]);
        }
    }
}

// ================= small GEMM body (MT=32), fused GRU launch (launch 2) =================
// smem: araw[2](16K) | ahi[2](8K) | alo[2](8K) | b[3](48K) = 80KB
#define SMALL_SMEM 81920

__device__ __forceinline__
void gemm32_body(const float* __restrict__ A, const float* __restrict__ bias,
                 float* __restrict__ C, int M, int K, int nchunk, int ldc,
                 int boff, int m0, char* smem) {
    constexpr uint32_t AR = 8192, AT = 4096;
    const uint32_t sb = smem_u32(smem);
    const uint32_t o_ahi = 2 * AR;           // 16384
    const uint32_t o_alo = 2 * AR + 2 * AT;  // 24576
    const uint32_t o_b   = 2 * AR + 4 * AT;  // 32768

    const int tid = threadIdx.x, wid = tid >> 5, lane = tid & 31;
    const int warpN = wid;

    const int crow = tid & 31, ch = (tid >> 5) & 1;
    const bool do_a = tid < 64;
    const bool avalid = do_a && (m0 + crow) < M;
    const int srow = ((m0 + crow) < M) ? (m0 + crow) : 0;
    const uint32_t rswz = ((uint32_t)crow & 7u) << 4;

    const int l15 = lane & 15, lhi = lane >> 4;
    const uint32_t rowAoff = (uint32_t)l15 * 128;
    const uint32_t xorA = (((uint32_t)l15) & 7u) << 4;
    const uint32_t rowBoff = (uint32_t)(warpN * 16 + l15) * 128;
    const uint32_t xorB = (((uint32_t)(warpN * 16 + l15)) & 7u) << 4;

    float acc[2][2][4];
    #pragma unroll
    for (int mt = 0; mt < 2; ++mt)
        #pragma unroll
        for (int na = 0; na < 2; ++na)
            #pragma unroll
            for (int q = 0; q < 4; ++q) acc[mt][na][q] = 0.f;

    auto issue_a = [&](int c) {
        if (!do_a) return;
        const uint32_t dst0 = sb + (uint32_t)(c & 1) * AR + (uint32_t)crow * 256;
        const float* src0 = A + (size_t)srow * K + c * 64;
        #pragma unroll
        for (int i = 0; i < 8; ++i) {
            uint32_t g = (uint32_t)(ch * 8 + i);
            cpasync16(dst0 + ((g << 4) ^ rswz), src0 + g * 4);
        }
    };
    auto issue_b = [&](int c, int slot) {
        const char* sh = (const char*)g_bh + (size_t)(boff + c) * 16384;
        const uint32_t dh = sb + o_b + (uint32_t)slot * 16384;
        #pragma unroll
        for (int i = 0; i < 4; ++i) {
            uint32_t lin = (uint32_t)(tid + i * 256) * 16;
            cpasync16(dh + lin, sh + lin);
        }
    };

    issue_a(0); issue_b(0, 0); CP_COMMIT();
    if (nchunk > 1) { issue_a(1); issue_b(1, 1); }
    CP_COMMIT();

    int bslot = 0, bslot2 = 2;
    for (int c = 0; c < nchunk; ++c) {
        CP_WAIT1();
        __syncthreads();
        const uint32_t stA = (uint32_t)(c & 1);
        if (do_a) {
            const uint32_t rbase = sb + stA * AR + (uint32_t)crow * 256;
            const uint32_t hbase = sb + o_ahi + stA * AT + (uint32_t)crow * 128;
            const uint32_t lbase = sb + o_alo + stA * AT + (uint32_t)crow * 128;
            #pragma unroll
            for (int j = 0; j < 4; ++j) {
                uint32_t g0 = (uint32_t)(ch * 8 + 2 * j);
                float4 f0 = lds128f(rbase + ((g0 << 4) ^ rswz));
                float4 f1 = lds128f(rbase + (((g0 + 1) << 4) ^ rswz));
                uint4 hv, lv;
                if (avalid) split8(f0, f1, hv, lv);
                else { hv = make_uint4(0, 0, 0, 0); lv = make_uint4(0, 0, 0, 0); }
                uint32_t toff = ((uint32_t)(ch * 64 + j * 16)) ^ rswz;
                sts128(hbase + toff, hv);
                sts128(lbase + toff, lv);
            }
        }
        if (c + 2 < nchunk) { issue_a(c + 2); issue_b(c + 2, bslot2); }
        CP_COMMIT();
        __syncthreads();
        const uint32_t ahiB = sb + o_ahi + stA * AT;
        const uint32_t aloB = sb + o_alo + stA * AT;
        const uint32_t bB = sb + o_b + (uint32_t)bslot * 16384;
        #pragma unroll
        for (int k16 = 0; k16 < 4; ++k16) {
            const uint32_t kb = (uint32_t)(k16 * 32 + lhi * 16);
            const uint32_t kA = kb ^ xorA, kB = kb ^ xorB;
            uint32_t ah[2][4], al[2][4], bf[4];
            ldsm4(ah[0], ahiB + rowAoff + kA);
            ldsm4(ah[1], ahiB + rowAoff + 2048 + kA);
            ldsm4(al[0], aloB + rowAoff + kA);
            ldsm4(al[1], aloB + rowAoff + 2048 + kA);
            ldsm4(bf, bB + rowBoff + kB);
            #pragma unroll
            for (int mt = 0; mt < 2; ++mt) {
                mma16816(acc[mt][0], ah[mt], bf[0], bf[2]);
                mma16816(acc[mt][1], ah[mt], bf[1], bf[3]);
            }
            #pragma unroll
            for (int mt = 0; mt < 2; ++mt) {
                mma16816(acc[mt][0], al[mt], bf[0], bf[2]);
                mma16816(acc[mt][1], al[mt], bf[1], bf[3]);
            }
        }
        bslot = (bslot == 2) ? 0 : bslot + 1;
        bslot2 = (bslot2 == 2) ? 0 : bslot2 + 1;
    }
    CP_WAIT0();

    const int mrow = lane >> 2, ncol = (lane & 3) * 2;
    #pragma unroll
    for (int mt = 0; mt < 2; ++mt) {
        const int mb = m0 + mt * 16 + mrow;
        const bool v0 = mb < M, v1 = (mb + 8) < M;
        const float bv0 = v0 ? bias[mb] : 0.f;
        const float bv1 = v1 ? bias[mb + 8] : 0.f;
        #pragma unroll
        for (int na = 0; na < 2; ++na) {
            const int n = warpN * 16 + na * 8 + ncol;
            float* c0 = C + (size_t)n * ldc;
            float* c1 = C + (size_t)(n + 1) * ldc;
            if (v0) { c0[mb] = acc[mt][na][0] + bv0; c1[mb] = acc[mt][na][1] + bv0; }
            if (v1) { c0[mb + 8] = acc[mt][na][2] + bv1; c1[mb + 8] = acc[mt][na][3] + bv1; }
        }
    }
}

__global__ __launch_bounds__(256, 1)
void gru_gemm_fused(const float* __restrict__ A1, const float* __restrict__ b1,
                    float* __restrict__ C1, int K1, int nc1,
                    const float* __restrict__ A2, const float* __restrict__ b2,
                    float* __restrict__ C2, int K2, int nc2) {
    extern __shared__ char smem[];
    if (blockIdx.x < 48)
        gemm32_body(A1, b1, C1, H3, K1, nc1, H3, 0, blockIdx.x * 32, smem);
    else
        gemm32_body(A2, b2, C2, H3, K2, nc2, H3, nc1, (blockIdx.x - 48) * 32, smem);
}

// ---------------- launch 3: GRU gates + logits-B convert ----------------
__global__ void bconv_out_gates(const float* __restrict__ hidden, float* __restrict__ out_h) {
    int idx = blockIdx.x * 256 + threadIdx.x;
    if (idx >= KOUT * 16) return;
    int c = idx >> 10, r = (idx >> 3) & 127, g8 = idx & 7;
    int k0 = c * 64 + g8 * 8;
    float4 f0, f1;
    if (c < 8) {
        float v[8];
        const float* gi = g_gi + (size_t)r * H3 + k0;
        const float* gh = g_gh + (size_t)r * H3 + k0;
        const float* hp = hidden + (size_t)r * HH + k0;
        #pragma unroll
        for (int i = 0; i < 8; ++i) {
            float rr = 1.f / (1.f + expf(-(gi[i] + gh[i])));
            float zz = 1.f / (1.f + expf(-(gi[HH + i] + gh[HH + i])));
            float nn = tanhf(gi[2 * HH + i] + rr * gh[2 * HH + i]);
            v[i] = (1.f - zz) * nn + zz * hp[i];
        }
        f0 = make_float4(v[0], v[1], v[2], v[3]);
        f1 = make_float4(v[4], v[5], v[6], v[7]);
        *reinterpret_cast<float4*>(out_h + (size_t)r * HH + k0) = f0;
        *reinterpret_cast<float4*>(out_h + (size_t)r * HH + k0 + 4) = f1;
    } else {
        const float4* src = reinterpret_cast<const float4*>(g_toout + (size_t)r * KOUT + k0);
        f0 = src[0];
        f1 = src[1];
    }
    bconv_store(c, r, g8, f0, f1);
}

// ============ launch 4: big logits GEMM (MT=64, 256 thr, 2 CTAs/SM) ============
// smem: ahi[2]@0 (8K ea) | alo[2]@16K (8K ea) | b[2]@32K (16K ea) = 64KB
#define BIG_SMEM 65536

__global__ __launch_bounds__(256, 2)
void mma_gemm_big(const float* __restrict__ A, const float* __restrict__ bias,
                  float* __restrict__ C, int M, int K, int nchunk, int ldc) {
    extern __shared__ char smem[];
    const uint32_t sb = smem_u32(smem);
    const int tid = threadIdx.x, wid = tid >> 5, lane = tid & 31;
    const int warpM = wid & 1, warpN = wid >> 1;
    const int m0 = blockIdx.x * 64;

    const int crow = tid >> 2, cq = tid & 3;
    const bool avalid = (m0 + crow) < M;
    const int srow = avalid ? (m0 + crow) : 0;
    const uint32_t rswz = ((uint32_t)crow & 7u) << 4;
    const float4* aq = reinterpret_cast<const float4*>(A + (size_t)srow * K) + cq * 4;

    const int l15 = lane & 15, lhi = lane >> 4;
    const uint32_t rowAoff = (uint32_t)(warpM * 32 + l15) * 128;
    const uint32_t xorA = (((uint32_t)(warpM * 32 + l15)) & 7u) << 4;
    const uint32_t rowBoff = (uint32_t)(warpN * 32 + l15) * 128;
    const uint32_t xorB = (((uint32_t)(warpN * 32 + l15)) & 7u) << 4;

    float acc[2][4][4];
    #pragma unroll
    for (int mt = 0; mt < 2; ++mt)
        #pragma unroll
        for (int na = 0; na < 4; ++na)
            #pragma unroll
            for (int q = 0; q < 4; ++q) acc[mt][na][q] = 0.f;

    float4 rA[4];

    auto issue_b = [&](int c, int slot) {
        const char* sh = (const char*)g_bh + (size_t)c * 16384;
        const uint32_t dh = sb + 32768u + (uint32_t)slot * 16384u;
        #pragma unroll
        for (int i = 0; i < 4; ++i) {
            uint32_t lin = (uint32_t)(tid + i * 256) * 16;
            cpasync16(dh + lin, sh + lin);
        }
    };
    auto convert_sts = [&](int st) {
        const uint32_t hb = sb + (uint32_t)st * 8192u + (uint32_t)crow * 128;
        const uint32_t lb = hb + 16384u;
        const uint32_t o0 = ((uint32_t)(cq * 32)) ^ rswz;
        const uint32_t o1 = ((uint32_t)(cq * 32 + 16)) ^ rswz;
        uint4 hv, lv;
        if (avalid) split8(rA[0], rA[1], hv, lv);
        else { hv = make_uint4(0, 0, 0, 0); lv = make_uint4(0, 0, 0, 0); }
        sts128(hb + o0, hv);
        sts128(lb + o0, lv);
        if (avalid) split8(rA[2], rA[3], hv, lv);
        else { hv = make_uint4(0, 0, 0, 0); lv = make_uint4(0, 0, 0, 0); }
        sts128(hb + o1, hv);
        sts128(lb + o1, lv);
    };

    #pragma unroll
    for (int i = 0; i < 4; ++i) rA[i] = aq[i];
    issue_b(0, 0);
    CP_COMMIT();
    convert_sts(0);
    if (nchunk > 1) {
        #pragma unroll
        for (int i = 0; i < 4; ++i) rA[i] = aq[16 + i];
    }

    for (int c = 0; c < nchunk; ++c) {
        CP_WAIT0();
        __syncthreads();
        if (c + 1 < nchunk) { issue_b(c + 1, (c + 1) & 1); CP_COMMIT(); }

        const uint32_t ahiB = sb + (uint32_t)(c & 1) * 8192u;
        const uint32_t aloB = ahiB + 16384u;
        const uint32_t bB = sb + 32768u + (uint32_t)(c & 1) * 16384u;
        #pragma unroll
        for (int k16 = 0; k16 < 4; ++k16) {
            const uint32_t kb = (uint32_t)(k16 * 32 + lhi * 16);
            const uint32_t kA = kb ^ xorA, kB = kb ^ xorB;
            uint32_t ah[2][4], al[2][4], bf[2][4];
            ldsm4(ah[0], ahiB + rowAoff + kA);
            ldsm4(ah[1], ahiB + rowAoff + 2048 + kA);
            ldsm4(al[0], aloB + rowAoff + kA);
            ldsm4(al[1], aloB + rowAoff + 2048 + kA);
            ldsm4(bf[0], bB + rowBoff + kB);
            ldsm4(bf[1], bB + rowBoff + 2048 + kB);
            #pragma unroll
            for (int mt = 0; mt < 2; ++mt)
                #pragma unroll
                for (int na = 0; na < 4; ++na) {
                    const uint32_t* bq = bf[na >> 1];
                    if (na & 1) mma16816(acc[mt][na], ah[mt], bq[1], bq[3]);
                    else        mma16816(acc[mt][na], ah[mt], bq[0], bq[2]);
                }
            #pragma unroll
            for (int mt = 0; mt < 2; ++mt)
                #pragma unroll
                for (int na = 0; na < 4; ++na) {
                    const uint32_t* bq = bf[na >> 1];
                    if (na & 1) mma16816(acc[mt][na], al[mt], bq[1], bq[3]);
                    else        mma16816(acc[mt][na], al[mt], bq[0], bq[2]);
                }
        }
        if (c + 1 < nchunk) {
            convert_sts((c + 1) & 1);
            if (c + 2 < nchunk) {
                #pragma unroll
                for (int i = 0; i < 4; ++i) rA[i] = aq[(c + 2) * 16 + i];
            }
        }
    }

    const int mrow = lane >> 2, ncol = (lane & 3) * 2;
    #pragma unroll
    for (int mt = 0; mt < 2; ++mt) {
        const int mb = m0 + warpM * 32 + mt * 16 + mrow;
        const bool v0 = mb < M, v1 = (mb + 8) < M;
        const float bv0 = v0 ? bias[mb] : 0.f;
        const float bv1 = v1 ? bias[mb + 8] : 0.f;
        #pragma unroll
        for (int na = 0; na < 4; ++na) {
            const int n = warpN * 32 + na * 8 + ncol;
            float* c0 = C + (size_t)n * ldc;
            float* c1 = C + (size_t)(n + 1) * ldc;
            if (v0) { c0[mb] = acc[mt][na][0] + bv0; c1[mb] = acc[mt][na][1] + bv0; }
            if (v1) { c0[mb + 8] = acc[mt][na][2] + bv1; c1[mb + 8] = acc[mt][na][3] + bv1; }
        }
    }
}

// ---------------- launch (4 launches; ncu -s 5 (+2 harness) captures #4 = big) ----------------
extern "C" void kernel_launch(void* const* d_in, const int* in_sizes, int n_in,
                              void* d_out, int out_size) {
    const int*   x      = (const int*)d_in[0];
    const float* hidden = (const float*)d_in[1];
    const float* enc    = (const float*)d_in[2];
    const float* emb    = (const float*)d_in[3];
    const float* attn_w = (const float*)d_in[4];
    const float* attn_b = (const float*)d_in[5];
    const float* v      = (const float*)d_in[6];
    const float* w_ih   = (const float*)d_in[7];
    const float* w_hh   = (const float*)d_in[8];
    const float* b_ih   = (const float*)d_in[9];
    const float* b_hh   = (const float*)d_in[10];
    const float* out_w  = (const float*)d_in[11];
    const float* out_b  = (const float*)d_in[12];
    float* out = (float*)d_out;

    static float *p_gi = nullptr, *p_gh = nullptr;
    if (!p_gi) {
        cudaGetSymbolAddress((void**)&p_gi, g_gi);
        cudaGetSymbolAddress((void**)&p_gh, g_gh);
        cudaFuncSetAttribute(mma_gemm_big, cudaFuncAttributeMaxDynamicSharedMemorySize,
                             BIG_SMEM);
        cudaFuncSetAttribute(gru_gemm_fused, cudaFuncAttributeMaxDynamicSharedMemorySize,
                             SMALL_SMEM);
    }

    attn_fused<<<BB, 512>>>(hidden, enc, emb, x, attn_w, attn_b, v);           // 1
    gru_gemm_fused<<<96, 256, SMALL_SMEM>>>(w_ih, b_ih, p_gi, KGRU, KGRU / 64,
                                            w_hh, b_hh, p_gh, HH, HH / 64);    // 2
    bconv_out_gates<<<(KOUT * 16 + 255) / 256, 256>>>(hidden, out + (size_t)BB * VV);  // 3
    mma_gemm_big<<<(VV + 63) / 64, 256, BIG_SMEM>>>(out_w, out_b, out, VV, KOUT,
                                                    KOUT / 64, VV);            // 4
}

// round 14
// speedup vs baseline: 4.3518x; 1.3199x over previous
#include <cuda_runtime.h>
#include <cuda_fp16.h>
#include <cstdint>

// Problem dims
#define HH   512
#define EE   256
#define VV   50000
#define BB   128
#define SS   200
#define H3   1536          // 3H
#define KGRU 1280          // 2H + E
#define KOUT 1792          // 3H + E

// ---------------- scratch ----------------
__device__ float g_u[H3];
__device__ float g_c0;
__device__ int   g_cnt;                              // prep-slice release counter
__device__ __align__(16) float g_togru[BB * KGRU];
__device__ __align__(16) float g_toout[BB * KOUT];   // [unused 0:512 | context | emb]
__device__ __align__(16) float g_gi[BB * H3];
__device__ __align__(16) float g_gh[BB * H3];
// pre-converted B (single fp16), swizzled tile layout: [chunk][128 rows][128B]
__device__ uint4 g_bh[28 * 1024];

// ---------------- helpers ----------------
__device__ __forceinline__ uint32_t smem_u32(const void* p) {
    uint32_t a;
    asm("{ .reg .u64 t; cvta.to.shared.u64 t, %1; cvt.u32.u64 %0, t; }" : "=r"(a) : "l"(p));
    return a;
}
__device__ __forceinline__ uint32_t f16pair(float x, float y) {   // {lo=x, hi=y}
    uint32_t h;
    asm("cvt.rn.f16x2.f32 %0, %1, %2;" : "=r"(h) : "f"(y), "f"(x));
    return h;
}
// fp16 hi/lo split (GRU path only)
__device__ __forceinline__ void split2(float x, float y, uint32_t& hv, uint32_t& lv) {
    uint32_t h = f16pair(x, y);
    __half2 hh = *reinterpret_cast<const __half2*>(&h);
    float2 hf = __half22float2(hh);
    lv = f16pair(x - hf.x, y - hf.y);
    hv = h;
}
__device__ __forceinline__ void split8(float4 f0, float4 f1, uint4& hv, uint4& lv) {
    split2(f0.x, f0.y, hv.x, lv.x);
    split2(f0.z, f0.w, hv.y, lv.y);
    split2(f1.x, f1.y, hv.z, lv.z);
    split2(f1.z, f1.w, hv.w, lv.w);
}
__device__ __forceinline__ uint4 pack8h(float4 f0, float4 f1) {
    uint4 hv;
    hv.x = f16pair(f0.x, f0.y);
    hv.y = f16pair(f0.z, f0.w);
    hv.z = f16pair(f1.x, f1.y);
    hv.w = f16pair(f1.z, f1.w);
    return hv;
}
__device__ __forceinline__ void sts128(uint32_t addr, uint4 v) {
    asm volatile("st.shared.v4.b32 [%0], {%1,%2,%3,%4};"
                 :: "r"(addr), "r"(v.x), "r"(v.y), "r"(v.z), "r"(v.w) : "memory");
}
__device__ __forceinline__ float4 lds128f(uint32_t a) {
    float4 v;
    asm volatile("ld.shared.v4.f32 {%0,%1,%2,%3}, [%4];"
                 : "=f"(v.x), "=f"(v.y), "=f"(v.z), "=f"(v.w) : "r"(a));
    return v;
}
__device__ __forceinline__ void ldsm4(uint32_t (&r)[4], uint32_t addr) {
    asm volatile("ldmatrix.sync.aligned.m8n8.x4.shared.b16 {%0,%1,%2,%3}, [%4];"
                 : "=r"(r[0]), "=r"(r[1]), "=r"(r[2]), "=r"(r[3]) : "r"(addr));
}
__device__ __forceinline__ void mma16816(float (&d)[4], const uint32_t (&a)[4],
                                         uint32_t b0, uint32_t b1) {
    asm volatile(
        "mma.sync.aligned.m16n8k16.row.col.f32.f16.f16.f32 "
        "{%0,%1,%2,%3}, {%4,%5,%6,%7}, {%8,%9}, {%0,%1,%2,%3};"
        : "+f"(d[0]), "+f"(d[1]), "+f"(d[2]), "+f"(d[3])
        : "r"(a[0]), "r"(a[1]), "r"(a[2]), "r"(a[3]), "r"(b0), "r"(b1));
}
__device__ __forceinline__ void cpasync16(uint32_t dst, const void* src) {
    asm volatile("{ .reg .u64 g; cvta.to.global.u64 g, %1; "
                 "cp.async.cg.shared.global [%0], [g], 16; }"
                 :: "r"(dst), "l"(src) : "memory");
}
#define CP_COMMIT() asm volatile("cp.async.commit_group;" ::: "memory")
#define CP_WAIT1()  asm volatile("cp.async.wait_group 1;" ::: "memory")
#define CP_WAIT0()  asm volatile("cp.async.wait_group 0;" ::: "memory")

// ---------------- B convert core: 8 floats -> swizzled fp16 granule (16B) ----------------
__device__ __forceinline__ void bconv_store(int chunk, int r, int g8, float4 f0, float4 f1) {
    uint32_t off = (uint32_t)chunk * 16384 + (uint32_t)r * 128 +
                   (((uint32_t)g8 * 16) ^ (((uint32_t)r & 7u) << 4));
    g_bh[off >> 4] = pack8h(f0, f1);
}

// ---------------- launch 1: prep(sliced) + attention + GRU-B convert ----------------
__global__ __launch_bounds__(512)
void attn_fused(const float* __restrict__ hidden,
                const float* __restrict__ enc,
                const float* __restrict__ emb,
                const int* __restrict__ x,
                const float* __restrict__ attn_w,
                const float* __restrict__ attn_b,
                const float* __restrict__ v) {
    __shared__ float s_u[2 * HH];
    __shared__ float s_p[256];
    __shared__ float s_red[16];
    __shared__ float s_part[4][128];
    __shared__ float s_constb, s_max, s_sum;

    const int b = blockIdx.x;
    const int tid = threadIdx.x;
    const int lane = tid & 31, wid = tid >> 5;

    // ---- phase 0: CTAs 0..11 compute u slice [b*128, b*128+128) ----
    if (b < 12) {
        const int j = tid & 127, hq = tid >> 7;
        const int jj = b * 128 + j;
        float s = 0.f;
        #pragma unroll 8
        for (int h = hq * 128; h < hq * 128 + 128; ++h)
            s += attn_w[(size_t)h * H3 + jj] * v[h];
        s_part[hq][j] = s;
        float pc = 0.f;
        if (b == 0) pc = attn_b[tid] * v[tid];
        for (int o = 16; o; o >>= 1) pc += __shfl_xor_sync(~0u, pc, o);
        if (lane == 0) s_red[wid] = pc;
        __syncthreads();
        if (tid < 128)
            g_u[b * 128 + tid] = s_part[0][tid] + s_part[1][tid] +
                                 s_part[2][tid] + s_part[3][tid];
        if (b == 0 && tid == 0) {
            float s0 = 0.f;
            for (int w = 0; w < 16; ++w) s0 += s_red[w];
            g_c0 = s0;
        }
        __threadfence();
        __syncthreads();
        if (tid == 0) atomicAdd(&g_cnt, 1);
    }
    if (tid == 0) {
        while (atomicAdd(&g_cnt, 0) < 12) __nanosleep(32);
    }
    __syncthreads();
    __threadfence();

    for (int j = tid; j < 2 * HH; j += 512) s_u[j] = g_u[HH + j];

    float p = hidden[b * HH + (tid & (HH - 1))] * g_u[tid & (HH - 1)];
    if (tid >= HH) p = 0.f;
    for (int o = 16; o; o >>= 1) p += __shfl_xor_sync(~0u, p, o);
    if (lane == 0) s_red[wid] = p;
    __syncthreads();
    if (tid == 0) {
        float s = g_c0;
        for (int w = 0; w < 16; ++w) s += s_red[w];
        s_constb = s;
    }
    __syncthreads();
    const float cb = s_constb;

    const float4* enc4 = reinterpret_cast<const float4*>(enc) + (size_t)b * SS * 256;
    const float4* u4 = reinterpret_cast<const float4*>(s_u);
    for (int s = wid; s < SS; s += 16) {
        const float4* row = enc4 + (size_t)s * 256;
        float acc = 0.f;
        #pragma unroll
        for (int t = 0; t < 8; ++t) {
            float4 e = row[lane + 32 * t];
            float4 u = u4[lane + 32 * t];
            acc += e.x * u.x + e.y * u.y + e.z * u.z + e.w * u.w;
        }
        for (int o = 16; o; o >>= 1) acc += __shfl_xor_sync(~0u, acc, o);
        if (lane == 0) s_p[s] = acc + cb;
    }
    __syncthreads();

    float m = -1e30f;
    for (int s = tid; s < SS; s += 512) m = fmaxf(m, s_p[s]);
    for (int o = 16; o; o >>= 1) m = fmaxf(m, __shfl_xor_sync(~0u, m, o));
    if (lane == 0) s_red[wid] = m;
    __syncthreads();
    if (tid == 0) {
        float mm = -1e30f;
        for (int w = 0; w < 16; ++w) mm = fmaxf(mm, s_red[w]);
        s_max = mm;
    }
    __syncthreads();
    const float mm2 = s_max;
    float sum = 0.f;
    for (int s = tid; s < SS; s += 512) {
        float e = expf(s_p[s] - mm2);
        s_p[s] = e;
        sum += e;
    }
    for (int o = 16; o; o >>= 1) sum += __shfl_xor_sync(~0u, sum, o);
    if (lane == 0) s_red[wid] = sum;
    __syncthreads();
    if (tid == 0) {
        float t = 0.f;
        for (int w = 0; w < 16; ++w) t += s_red[w];
        s_sum = 1.f / t;
    }
    __syncthreads();
    const float inv = s_sum;

    float2 acc = make_float2(0.f, 0.f);
    const float2* col = reinterpret_cast<const float2*>(enc) + (size_t)b * SS * 512 + tid;
    #pragma unroll 4
    for (int s = 0; s < SS; ++s) {
        float ps = s_p[s];
        float2 e = col[(size_t)s * 512];
        acc.x += ps * e.x; acc.y += ps * e.y;
    }
    acc.x *= inv; acc.y *= inv;

    const int d = tid * 2;
    *reinterpret_cast<float2*>(g_toout + (size_t)b * KOUT + HH + d) = acc;
    float2 rc = make_float2(fmaxf(acc.x, 0.f), fmaxf(acc.y, 0.f));
    *reinterpret_cast<float2*>(g_togru + (size_t)b * KGRU + EE + d) = rc;

    if (tid < EE) {
        float e = emb[(size_t)x[b] * EE + tid];
        g_toout[(size_t)b * KOUT + H3 + tid] = e;
        g_togru[(size_t)b * KGRU + tid] = fmaxf(e, 0.f);
    }
    __syncthreads();

    // ---- epilogue: convert GRU B row b (togru: chunks 0..19, hidden: 20..27) ----
    if (tid < 224) {
        const int c = tid >> 3, g8 = tid & 7;
        if (c < 20) {
            const float4* src = reinterpret_cast<const float4*>(
                g_togru + (size_t)b * KGRU + c * 64 + g8 * 8);
            bconv_store(c, b, g8, src[0], src[1]);
        } else {
            const float4* src = reinterpret_cast<const float4*>(
                hidden + (size_t)b * HH + (c - 20) * 64 + g8 * 8);
            bconv_store(c, b, g8, src[0], src[1]);
        }
    }
}

// ================= small GEMM body (MT=32), fused GRU launch (launch 2) =================
// A keeps hi/lo split (h_new accuracy); smem: araw[2](16K)|ahi[2](8K)|alo[2](8K)|b[3](48K)
#define SMALL_SMEM 81920

__device__ __forceinline__
void gemm32_body(const float* __restrict__ A, const float* __restrict__ bias,
                 float* __restrict__ C, int M, int K, int nchunk, int ldc,
                 int boff, int m0, char* smem) {
    constexpr uint32_t AR = 8192, AT = 4096;
    const uint32_t sb = smem_u32(smem);
    const uint32_t o_ahi = 2 * AR;           // 16384
    const uint32_t o_alo = 2 * AR + 2 * AT;  // 24576
    const uint32_t o_b   = 2 * AR + 4 * AT;  // 32768

    const int tid = threadIdx.x, wid = tid >> 5, lane = tid & 31;
    const int warpN = wid;

    const int crow = tid & 31, ch = (tid >> 5) & 1;
    const bool do_a = tid < 64;
    const bool avalid = do_a && (m0 + crow) < M;
    const int srow = ((m0 + crow) < M) ? (m0 + crow) : 0;
    const uint32_t rswz = ((uint32_t)crow & 7u) << 4;

    const int l15 = lane & 15, lhi = lane >> 4;
    const uint32_t rowAoff = (uint32_t)l15 * 128;
    const uint32_t xorA = (((uint32_t)l15) & 7u) << 4;
    const uint32_t rowBoff = (uint32_t)(warpN * 16 + l15) * 128;
    const uint32_t xorB = (((uint32_t)(warpN * 16 + l15)) & 7u) << 4;

    float acc[2][2][4];
    #pragma unroll
    for (int mt = 0; mt < 2; ++mt)
        #pragma unroll
        for (int na = 0; na < 2; ++na)
            #pragma unroll
            for (int q = 0; q < 4; ++q) acc[mt][na][q] = 0.f;

    auto issue_a = [&](int c) {
        if (!do_a) return;
        const uint32_t dst0 = sb + (uint32_t)(c & 1) * AR + (uint32_t)crow * 256;
        const float* src0 = A + (size_t)srow * K + c * 64;
        #pragma unroll
        for (int i = 0; i < 8; ++i) {
            uint32_t g = (uint32_t)(ch * 8 + i);
            cpasync16(dst0 + ((g << 4) ^ rswz), src0 + g * 4);
        }
    };
    auto issue_b = [&](int c, int slot) {
        const char* sh = (const char*)g_bh + (size_t)(boff + c) * 16384;
        const uint32_t dh = sb + o_b + (uint32_t)slot * 16384;
        #pragma unroll
        for (int i = 0; i < 4; ++i) {
            uint32_t lin = (uint32_t)(tid + i * 256) * 16;
            cpasync16(dh + lin, sh + lin);
        }
    };

    issue_a(0); issue_b(0, 0); CP_COMMIT();
    if (nchunk > 1) { issue_a(1); issue_b(1, 1); }
    CP_COMMIT();

    int bslot = 0, bslot2 = 2;
    for (int c = 0; c < nchunk; ++c) {
        CP_WAIT1();
        __syncthreads();
        const uint32_t stA = (uint32_t)(c & 1);
        if (do_a) {
            const uint32_t rbase = sb + stA * AR + (uint32_t)crow * 256;
            const uint32_t hbase = sb + o_ahi + stA * AT + (uint32_t)crow * 128;
            const uint32_t lbase = sb + o_alo + stA * AT + (uint32_t)crow * 128;
            #pragma unroll
            for (int j = 0; j < 4; ++j) {
                uint32_t g0 = (uint32_t)(ch * 8 + 2 * j);
                float4 f0 = lds128f(rbase + ((g0 << 4) ^ rswz));
                float4 f1 = lds128f(rbase + (((g0 + 1) << 4) ^ rswz));
                uint4 hv, lv;
                if (avalid) split8(f0, f1, hv, lv);
                else { hv = make_uint4(0, 0, 0, 0); lv = make_uint4(0, 0, 0, 0); }
                uint32_t toff = ((uint32_t)(ch * 64 + j * 16)) ^ rswz;
                sts128(hbase + toff, hv);
                sts128(lbase + toff, lv);
            }
        }
        if (c + 2 < nchunk) { issue_a(c + 2); issue_b(c + 2, bslot2); }
        CP_COMMIT();
        __syncthreads();
        const uint32_t ahiB = sb + o_ahi + stA * AT;
        const uint32_t aloB = sb + o_alo + stA * AT;
        const uint32_t bB = sb + o_b + (uint32_t)bslot * 16384;
        #pragma unroll
        for (int k16 = 0; k16 < 4; ++k16) {
            const uint32_t kb = (uint32_t)(k16 * 32 + lhi * 16);
            const uint32_t kA = kb ^ xorA, kB = kb ^ xorB;
            uint32_t ah[2][4], al[2][4], bf[4];
            ldsm4(ah[0], ahiB + rowAoff + kA);
            ldsm4(ah[1], ahiB + rowAoff + 2048 + kA);
            ldsm4(al[0], aloB + rowAoff + kA);
            ldsm4(al[1], aloB + rowAoff + 2048 + kA);
            ldsm4(bf, bB + rowBoff + kB);
            #pragma unroll
            for (int mt = 0; mt < 2; ++mt) {
                mma16816(acc[mt][0], ah[mt], bf[0], bf[2]);
                mma16816(acc[mt][1], ah[mt], bf[1], bf[3]);
            }
            #pragma unroll
            for (int mt = 0; mt < 2; ++mt) {
                mma16816(acc[mt][0], al[mt], bf[0], bf[2]);
                mma16816(acc[mt][1], al[mt], bf[1], bf[3]);
            }
        }
        bslot = (bslot == 2) ? 0 : bslot + 1;
        bslot2 = (bslot2 == 2) ? 0 : bslot2 + 1;
    }
    CP_WAIT0();

    const int mrow = lane >> 2, ncol = (lane & 3) * 2;
    #pragma unroll
    for (int mt = 0; mt < 2; ++mt) {
        const int mb = m0 + mt * 16 + mrow;
        const bool v0 = mb < M, v1 = (mb + 8) < M;
        const float bv0 = v0 ? bias[mb] : 0.f;
        const float bv1 = v1 ? bias[mb + 8] : 0.f;
        #pragma unroll
        for (int na = 0; na < 2; ++na) {
            const int n = warpN * 16 + na * 8 + ncol;
            float* c0 = C + (size_t)n * ldc;
            float* c1 = C + (size_t)(n + 1) * ldc;
            if (v0) { c0[mb] = acc[mt][na][0] + bv0; c1[mb] = acc[mt][na][1] + bv0; }
            if (v1) { c0[mb + 8] = acc[mt][na][2] + bv1; c1[mb + 8] = acc[mt][na][3] + bv1; }
        }
    }
}

__global__ __launch_bounds__(256, 1)
void gru_gemm_fused(const float* __restrict__ A1, const float* __restrict__ b1,
                    float* __restrict__ C1, int K1, int nc1,
                    const float* __restrict__ A2, const float* __restrict__ b2,
                    float* __restrict__ C2, int K2, int nc2) {
    extern __shared__ char smem[];
    if (blockIdx.x < 48)
        gemm32_body(A1, b1, C1, H3, K1, nc1, H3, 0, blockIdx.x * 32, smem);
    else
        gemm32_body(A2, b2, C2, H3, K2, nc2, H3, nc1, (blockIdx.x - 48) * 32, smem);
}

// ---------------- launch 3: GRU gates + logits-B convert ----------------
__global__ void bconv_out_gates(const float* __restrict__ hidden, float* __restrict__ out_h) {
    int idx = blockIdx.x * 256 + threadIdx.x;
    if (idx >= KOUT * 16) return;
    int c = idx >> 10, r = (idx >> 3) & 127, g8 = idx & 7;
    int k0 = c * 64 + g8 * 8;
    float4 f0, f1;
    if (c < 8) {
        float v[8];
        const float* gi = g_gi + (size_t)r * H3 + k0;
        const float* gh = g_gh + (size_t)r * H3 + k0;
        const float* hp = hidden + (size_t)r * HH + k0;
        #pragma unroll
        for (int i = 0; i < 8; ++i) {
            float rr = 1.f / (1.f + expf(-(gi[i] + gh[i])));
            float zz = 1.f / (1.f + expf(-(gi[HH + i] + gh[HH + i])));
            float nn = tanhf(gi[2 * HH + i] + rr * gh[2 * HH + i]);
            v[i] = (1.f - zz) * nn + zz * hp[i];
        }
        f0 = make_float4(v[0], v[1], v[2], v[3]);
        f1 = make_float4(v[4], v[5], v[6], v[7]);
        *reinterpret_cast<float4*>(out_h + (size_t)r * HH + k0) = f0;
        *reinterpret_cast<float4*>(out_h + (size_t)r * HH + k0 + 4) = f1;
    } else {
        const float4* src = reinterpret_cast<const float4*>(g_toout + (size_t)r * KOUT + k0);
        f0 = src[0];
        f1 = src[1];
    }
    bconv_store(c, r, g8, f0, f1);
}

// ============ launch 4: big logits GEMM (MT=64, 256 thr, 3 CTAs/SM, single fp16) ============
// smem: a[2]@0 (8K ea = 16K) | b[2]@16K (16K ea = 32K) = 48KB
#define BIG_SMEM 49152

__global__ __launch_bounds__(256, 3)
void mma_gemm_big(const float* __restrict__ A, const float* __restrict__ bias,
                  float* __restrict__ C, int M, int K, int nchunk, int ldc) {
    extern __shared__ char smem[];
    const uint32_t sb = smem_u32(smem);
    const int tid = threadIdx.x, wid = tid >> 5, lane = tid & 31;
    const int warpM = wid & 1, warpN = wid >> 1;
    const int m0 = blockIdx.x * 64;

    const int crow = tid >> 2, cq = tid & 3;
    const bool avalid = (m0 + crow) < M;
    const int srow = avalid ? (m0 + crow) : 0;
    const uint32_t rswz = ((uint32_t)crow & 7u) << 4;
    const float4* aq = reinterpret_cast<const float4*>(A + (size_t)srow * K) + cq * 4;

    const int l15 = lane & 15, lhi = lane >> 4;
    const uint32_t rowAoff = (uint32_t)(warpM * 32 + l15) * 128;
    const uint32_t xorA = (((uint32_t)(warpM * 32 + l15)) & 7u) << 4;
    const uint32_t rowBoff = (uint32_t)(warpN * 32 + l15) * 128;
    const uint32_t xorB = (((uint32_t)(warpN * 32 + l15)) & 7u) << 4;

    float acc[2][4][4];
    #pragma unroll
    for (int mt = 0; mt < 2; ++mt)
        #pragma unroll
        for (int na = 0; na < 4; ++na)
            #pragma unroll
            for (int q = 0; q < 4; ++q) acc[mt][na][q] = 0.f;

    float4 rA[4];

    auto issue_b = [&](int c, int slot) {
        const char* sh = (const char*)g_bh + (size_t)c * 16384;
        const uint32_t dh = sb + 16384u + (uint32_t)slot * 16384u;
        #pragma unroll
        for (int i = 0; i < 4; ++i) {
            uint32_t lin = (uint32_t)(tid + i * 256) * 16;
            cpasync16(dh + lin, sh + lin);
        }
    };
    auto convert_sts = [&](int st) {
        const uint32_t hb = sb + (uint32_t)st * 8192u + (uint32_t)crow * 128;
        const uint32_t o0 = ((uint32_t)(cq * 32)) ^ rswz;
        const uint32_t o1 = ((uint32_t)(cq * 32 + 16)) ^ rswz;
        uint4 hv;
        if (avalid) hv = pack8h(rA[0], rA[1]);
        else hv = make_uint4(0, 0, 0, 0);
        sts128(hb + o0, hv);
        if (avalid) hv = pack8h(rA[2], rA[3]);
        else hv = make_uint4(0, 0, 0, 0);
        sts128(hb + o1, hv);
    };

    #pragma unroll
    for (int i = 0; i < 4; ++i) rA[i] = aq[i];
    issue_b(0, 0);
    CP_COMMIT();
    convert_sts(0);
    if (nchunk > 1) {
        #pragma unroll
        for (int i = 0; i < 4; ++i) rA[i] = aq[16 + i];
    }

    for (int c = 0; c < nchunk; ++c) {
        CP_WAIT0();
        __syncthreads();
        if (c + 1 < nchunk) { issue_b(c + 1, (c + 1) & 1); CP_COMMIT(); }

        const uint32_t aB = sb + (uint32_t)(c & 1) * 8192u;
        const uint32_t bB = sb + 16384u + (uint32_t)(c & 1) * 16384u;
        #pragma unroll
        for (int k16 = 0; k16 < 4; ++k16) {
            const uint32_t kb = (uint32_t)(k16 * 32 + lhi * 16);
            const uint32_t kA = kb ^ xorA, kB = kb ^ xorB;
            uint32_t ah[2][4], bf[2][4];
            ldsm4(ah[0], aB + rowAoff + kA);
            ldsm4(ah[1], aB + rowAoff + 2048 + kA);
            ldsm4(bf[0], bB + rowBoff + kB);
            ldsm4(bf[1], bB + rowBoff + 2048 + kB);
            #pragma unroll
            for (int mt = 0; mt < 2; ++mt)
                #pragma unroll
                for (int na = 0; na < 4; ++na) {
                    const uint32_t* bq = bf[na >> 1];
                    if (na & 1) mma16816(acc[mt][na], ah[mt], bq[1], bq[3]);
                    else        mma16816(acc[mt][na], ah[mt], bq[0], bq[2]);
                }
        }
        if (c + 1 < nchunk) {
            convert_sts((c + 1) & 1);
            if (c + 2 < nchunk) {
                #pragma unroll
                for (int i = 0; i < 4; ++i) rA[i] = aq[(c + 2) * 16 + i];
            }
        }
    }

    const int mrow = lane >> 2, ncol = (lane & 3) * 2;
    #pragma unroll
    for (int mt = 0; mt < 2; ++mt) {
        const int mb = m0 + warpM * 32 + mt * 16 + mrow;
        const bool v0 = mb < M, v1 = (mb + 8) < M;
        const float bv0 = v0 ? bias[mb] : 0.f;
        const float bv1 = v1 ? bias[mb + 8] : 0.f;
        #pragma unroll
        for (int na = 0; na < 4; ++na) {
            const int n = warpN * 32 + na * 8 + ncol;
            float* c0 = C + (size_t)n * ldc;
            float* c1 = C + (size_t)(n + 1) * ldc;
            if (v0) { c0[mb] = acc[mt][na][0] + bv0; c1[mb] = acc[mt][na][1] + bv0; }
            if (v1) { c0[mb + 8] = acc[mt][na][2] + bv1; c1[mb + 8] = acc[mt][na][3] + bv1; }
        }
    }
}

// ---------------- launch (4 launches; ncu -s 5 (+2 harness) captures #4 = big) ----------------
extern "C" void kernel_launch(void* const* d_in, const int* in_sizes, int n_in,
                              void* d_out, int out_size) {
    const int*   x      = (const int*)d_in[0];
    const float* hidden = (const float*)d_in[1];
    const float* enc    = (const float*)d_in[2];
    const float* emb    = (const float*)d_in[3];
    const float* attn_w = (const float*)d_in[4];
    const float* attn_b = (const float*)d_in[5];
    const float* v      = (const float*)d_in[6];
    const float* w_ih   = (const float*)d_in[7];
    const float* w_hh   = (const float*)d_in[8];
    const float* b_ih   = (const float*)d_in[9];
    const float* b_hh   = (const float*)d_in[10];
    const float* out_w  = (const float*)d_in[11];
    const float* out_b  = (const float*)d_in[12];
    float* out = (float*)d_out;

    static float *p_gi = nullptr, *p_gh = nullptr;
    if (!p_gi) {
        cudaGetSymbolAddress((void**)&p_gi, g_gi);
        cudaGetSymbolAddress((void**)&p_gh, g_gh);
        cudaFuncSetAttribute(mma_gemm_big, cudaFuncAttributeMaxDynamicSharedMemorySize,
                             BIG_SMEM);
        cudaFuncSetAttribute(gru_gemm_fused, cudaFuncAttributeMaxDynamicSharedMemorySize,
                             SMALL_SMEM);
    }

    attn_fused<<<BB, 512>>>(hidden, enc, emb, x, attn_w, attn_b, v);           // 1
    gru_gemm_fused<<<96, 256, SMALL_SMEM>>>(w_ih, b_ih, p_gi, KGRU, KGRU / 64,
                                            w_hh, b_hh, p_gh, HH, HH / 64);    // 2
    bconv_out_gates<<<(KOUT * 16 + 255) / 256, 256>>>(hidden, out + (size_t)BB * VV);  // 3
    mma_gemm_big<<<(VV + 63) / 64, 256, BIG_SMEM>>>(out_w, out_b, out, VV, KOUT,
                                                    KOUT / 64, VV);            // 4
}